// round 5
// baseline (speedup 1.0000x reference)
#include <cuda_runtime.h>
#include <cuda_bf16.h>
#include <math.h>

#define NN 4096
#define ALPHA 0.2f

__device__ __forceinline__ float lrelu(float v){ return v >= 0.f ? v : ALPHA * v; }

// ---------------- scratch arenas (device globals; no allocation) -------------
#define OFF_P0    0L          // fp32 P0: 8*512 = 4096
#define OFF_P1    4096L       // fp32 P1: 8*256 = 2048
#define OFF_OWH   8192L       // 4096*64
#define OFF_HO0   270336L     // 4096*64
#define OFF_WHC   532480L     // 4096
#define OFF_HOUT  536576L     // 4096
#define OFF_S1    540672L     // 4*4096
#define OFF_S2    557056L     // 4*4096
#define OFF_M     573440L     // 16
#define OFF_DV    573456L     // 4096
#define OFF_WHB   577552L     // bf16 4*4096*256 -> 2097152 floats
#define OFF_HINB  2674704L    // bf16 4096*512   -> 1048576 floats
#define OFF_H1B   3723280L    // bf16 4*4096*256 -> 2097152 floats
#define OFF_HCATB 5820432L    // bf16 4096*1024  -> 2097152 floats
#define OFF_W0B   7917584L    // bf16 4*512*256  -> 262144 floats
#define OFF_W1B   8179728L    // bf16 4*256*256  -> 131072 floats
#define OFF_WO0B  8310800L    // bf16 1024*64    -> 32768 floats
#define FARENA_SZ 8400000L

#define OFF_CNT   0
#define OFF_RP    4096
#define OFF_MSK   8208        // 4096*128 uints = 524288
#define OFF_CI    532496
#define IARENA_SZ 2200000

__device__ float g_farena[FARENA_SZ];
__device__ int   g_iarena[IARENA_SZ];

// ---------------- CSR construction (bitmask two-pass) ----------------
__global__ void k_count(const float* __restrict__ adj, unsigned* __restrict__ msk,
                        int* __restrict__ cnt) {
    int row = blockIdx.x, tid = threadIdx.x;
    int lane = tid & 31, wid = tid >> 5;
    const float4* p = reinterpret_cast<const float4*>(adj + (long)row * NN);
    unsigned* mrow = msk + (long)row * 128;
    int c = 0;
    for (int seg = wid; seg < 32; seg += 8) {
        float4 v = p[seg * 32 + lane];
        unsigned b0 = __ballot_sync(0xFFFFFFFFu, v.x > 0.f);
        unsigned b1 = __ballot_sync(0xFFFFFFFFu, v.y > 0.f);
        unsigned b2 = __ballot_sync(0xFFFFFFFFu, v.z > 0.f);
        unsigned b3 = __ballot_sync(0xFFFFFFFFu, v.w > 0.f);
        c += (v.x > 0.f) + (v.y > 0.f) + (v.z > 0.f) + (v.w > 0.f);
        if (lane == 0) {
            mrow[seg * 4 + 0] = b0; mrow[seg * 4 + 1] = b1;
            mrow[seg * 4 + 2] = b2; mrow[seg * 4 + 3] = b3;
        }
    }
    for (int o = 16; o; o >>= 1) c += __shfl_xor_sync(0xFFFFFFFFu, c, o);
    __shared__ int ws[8];
    if (lane == 0) ws[wid] = c;
    __syncthreads();
    if (tid == 0)
        cnt[row] = ws[0] + ws[1] + ws[2] + ws[3] + ws[4] + ws[5] + ws[6] + ws[7];
}

__global__ void k_scan(const int* __restrict__ cnt, int* __restrict__ rp) {
    __shared__ int s[1024];
    int t = threadIdx.x;
    int v[4]; int loc = 0;
#pragma unroll
    for (int k = 0; k < 4; k++) { v[k] = cnt[t * 4 + k]; loc += v[k]; }
    s[t] = loc; __syncthreads();
    for (int off = 1; off < 1024; off <<= 1) {
        int add = (t >= off) ? s[t - off] : 0;
        __syncthreads();
        s[t] += add;
        __syncthreads();
    }
    int run = (t == 0) ? 0 : s[t - 1];
#pragma unroll
    for (int k = 0; k < 4; k++) { rp[t * 4 + k] = run; run += v[k]; }
    if (t == 1023) rp[NN] = run;
}

// decode bitmask -> column indices. 128 threads, one 32-bit word each.
// word layout from k_count: word (seg*4+sub), bit l  <->  col seg*128 + l*4 + sub
__global__ void k_fill(const unsigned* __restrict__ msk, const int* __restrict__ rp,
                       int* __restrict__ ci) {
    int row = blockIdx.x, tid = threadIdx.x;
    int lane = tid & 31, wid = tid >> 5;
    unsigned m = msk[(long)row * 128 + tid];
    int c = __popc(m);
    int pre = c;
    for (int o = 1; o < 32; o <<= 1) {
        int v = __shfl_up_sync(0xFFFFFFFFu, pre, o);
        if (lane >= o) pre += v;
    }
    __shared__ int wt[4];
    if (lane == 31) wt[wid] = pre;
    __syncthreads();
    int woff = 0;
    for (int i = 0; i < wid; i++) woff += wt[i];
    int pos = rp[row] + woff + pre - c;
    int base = (tid >> 2) * 128 + (tid & 3);
    while (m) {
        int b = __ffs(m) - 1;
        m &= m - 1;
        ci[pos++] = base + b * 4;
    }
}

// ---------------- misc ----------------
__global__ void k_rowsum(const float* __restrict__ sm, float* __restrict__ dv) {
    int row = blockIdx.x, tid = threadIdx.x;
    const float4* p = reinterpret_cast<const float4*>(sm + (long)row * NN);
    float acc = 0.f;
    for (int i = tid; i < NN / 4; i += 256) { float4 v = p[i]; acc += v.x + v.y + v.z + v.w; }
    __shared__ float s[256];
    s[tid] = acc; __syncthreads();
    for (int st = 128; st; st >>= 1) { if (tid < st) s[tid] += s[tid + st]; __syncthreads(); }
    if (tid == 0) dv[row] = s[0];
}

__global__ void k_mergeb(const float4* __restrict__ x, const int* __restrict__ obs,
                         const float4* __restrict__ theta, uint2* __restrict__ out) {
    long i = (long)blockIdx.x * blockDim.x + threadIdx.x;
    int row = (int)(i >> 7);
    int f4 = (int)(i & 127);
    float4 v = x[i];
    if (obs[row] == 1) { float4 t = theta[f4]; v.x += t.x; v.y += t.y; v.z += t.z; v.w += t.w; }
    __nv_bfloat162 p0 = __float22bfloat162_rn(make_float2(v.x, v.y));
    __nv_bfloat162 p1 = __float22bfloat162_rn(make_float2(v.z, v.w));
    uint2 w;
    w.x = *reinterpret_cast<unsigned int*>(&p0);
    w.y = *reinterpret_cast<unsigned int*>(&p1);
    out[i] = w;
}

__global__ void k_cvt(const float4* __restrict__ in, uint2* __restrict__ out, int n4) {
    int i = blockIdx.x * blockDim.x + threadIdx.x;
    if (i >= n4) return;
    float4 v = in[i];
    __nv_bfloat162 p0 = __float22bfloat162_rn(make_float2(v.x, v.y));
    __nv_bfloat162 p1 = __float22bfloat162_rn(make_float2(v.z, v.w));
    uint2 w;
    w.x = *reinterpret_cast<unsigned int*>(&p0);
    w.y = *reinterpret_cast<unsigned int*>(&p1);
    out[i] = w;
}

// P[(2h+c)*Fin + f] = sum_d W[h,f,d] * a[h, c*256 + d]
__global__ void k_wa(const float* __restrict__ W, const float* __restrict__ a,
                     float* __restrict__ P, int Fin) {
    int h = blockIdx.y;
    int idx = blockIdx.x * 8 + (threadIdx.x >> 5);
    int lane = threadIdx.x & 31;
    if (idx >= 2 * Fin) return;
    int c = idx / Fin, f = idx % Fin;
    const float* wrow = W + ((long)h * Fin + f) * 256;
    const float* av = a + h * 512 + c * 256;
    float d = 0.f;
    for (int k = lane; k < 256; k += 32) d = fmaf(wrow[k], av[k], d);
    for (int o = 16; o; o >>= 1) d += __shfl_xor_sync(0xFFFFFFFFu, d, o);
    if (lane == 0) P[(2 * h + c) * Fin + f] = d;
}

// s1/s2 from bf16 activations
__global__ void __launch_bounds__(256) k_sb(
    const __nv_bfloat16* __restrict__ act, long headStride,
    const float* __restrict__ P, int K,
    float* __restrict__ s1, float* __restrict__ s2) {
    __shared__ float Ps[4096];
    int tid = threadIdx.x;
    for (int i = tid; i < 8 * K; i += 256) Ps[i] = P[i];
    __syncthreads();
    int gw = blockIdx.x * 8 + (tid >> 5);
    int lane = tid & 31;
    int row = gw >> 2, h = gw & 3;
    const __nv_bfloat16* a = act + (long)h * headStride + (long)row * K;
    const float* p1 = Ps + (2 * h) * K;
    const float* p2 = p1 + K;
    float d1 = 0.f, d2 = 0.f;
    for (int f = lane * 2; f < K; f += 64) {
        unsigned u = *reinterpret_cast<const unsigned*>(a + f);
        float x0 = __uint_as_float(u << 16);
        float x1 = __uint_as_float(u & 0xFFFF0000u);
        d1 = fmaf(x0, p1[f], fmaf(x1, p1[f + 1], d1));
        d2 = fmaf(x0, p2[f], fmaf(x1, p2[f + 1], d2));
    }
    for (int o = 16; o; o >>= 1) {
        d1 += __shfl_xor_sync(0xFFFFFFFFu, d1, o);
        d2 += __shfl_xor_sync(0xFFFFFFFFu, d2, o);
    }
    if (lane == 0) { s1[h * NN + row] = d1; s2[h * NN + row] = d2; }
}

// s for out layer 0 (fout=64, fp32)
__global__ void k_s(const float* __restrict__ Wh, const float* __restrict__ a, int fout,
                    float* __restrict__ s1, float* __restrict__ s2) {
    int gw = (blockIdx.x * blockDim.x + threadIdx.x) >> 5;
    int lane = threadIdx.x & 31;
    if (gw >= NN) return;
    const float* row = Wh + (long)gw * fout;
    float d1 = 0.f, d2 = 0.f;
    for (int f = lane; f < fout; f += 32) {
        float v = row[f];
        d1 += v * a[f];
        d2 += v * a[fout + f];
    }
    for (int o = 16; o; o >>= 1) {
        d1 += __shfl_xor_sync(0xFFFFFFFFu, d1, o);
        d2 += __shfl_xor_sync(0xFFFFFFFFu, d2, o);
    }
    if (lane == 0) { s1[gw] = d1; s2[gw] = d2; }
}

// per-head M = leaky(max s1 + max s2)
__global__ void k_max4(const float* __restrict__ s1, const float* __restrict__ s2,
                       float* __restrict__ Mp, int nheads) {
    int h = blockIdx.x;
    const float* a = s1 + (long)h * NN;
    const float* b = s2 + (long)h * NN;
    __shared__ float m1s[512], m2s[512];
    int t = threadIdx.x;
    float m1 = -1e30f, m2 = -1e30f;
    for (int i = t; i < NN; i += 512) { m1 = fmaxf(m1, a[i]); m2 = fmaxf(m2, b[i]); }
    m1s[t] = m1; m2s[t] = m2; __syncthreads();
    for (int s = 256; s; s >>= 1) {
        if (t < s) { m1s[t] = fmaxf(m1s[t], m1s[t + s]); m2s[t] = fmaxf(m2s[t], m2s[t + s]); }
        __syncthreads();
    }
    if (t == 0) Mp[h] = lrelu(m1s[0] + m2s[0]);
}

// ---------------- bf16 sparse aggregation (FOUT=256), HFMA2 inner loop --------
__global__ void __launch_bounds__(256) k_aggb(
    const __nv_bfloat16* __restrict__ WhbAll,
    const float* __restrict__ s1, const float* __restrict__ s2,
    const float* __restrict__ Mp,
    const int* __restrict__ rp, const int* __restrict__ ci,
    __nv_bfloat16* __restrict__ outBase, long headStride, int ostride) {
    int row = blockIdx.x;
    int h = blockIdx.y;
    const char* Wb = (const char*)WhbAll + (long)h * NN * 512;
    const float* s1h = s1 + (long)h * NN;
    const float* s2h = s2 + (long)h * NN;
    __nv_bfloat16* out = outBase + (long)h * headStride + (long)row * ostride;

    int tid = threadIdx.x;
    int tx = tid & 31;
    int ty = tid >> 5;

    __shared__ unsigned swp[260];     // bf162(w,w) packed
    __shared__ unsigned soff[260];    // byte offsets
    __shared__ float    sacc[2048];
    __shared__ float    szw[8];

    float s1i = s1h[row];
    float M = Mp[h];
    int rs = rp[row], re = rp[row + 1];

    __nv_bfloat162 zero2 = __float2bfloat162_rn(0.f);
    __nv_bfloat162 A0[4] = {zero2, zero2, zero2, zero2};
    __nv_bfloat162 A1[4] = {zero2, zero2, zero2, zero2};
    __nv_bfloat162 A2[4] = {zero2, zero2, zero2, zero2};
    __nv_bfloat162 A3[4] = {zero2, zero2, zero2, zero2};
    float z = 0.f;

#define BC2(u) (*reinterpret_cast<const __nv_bfloat162*>(&(u)))
#define HF4(A, wu, v) { __nv_bfloat162 Wv = BC2(wu); \
    A[0] = __hfma2(Wv, BC2(v.x), A[0]); A[1] = __hfma2(Wv, BC2(v.y), A[1]); \
    A[2] = __hfma2(Wv, BC2(v.z), A[2]); A[3] = __hfma2(Wv, BC2(v.w), A[3]); }

    for (int base = rs; base < re; base += 256) {
        int n = min(256, re - base);
        __syncthreads();
        if (tid < n) {
            int j = ci[base + tid];
            soff[tid] = (unsigned)j << 9;
            float w = __expf(lrelu(s1i + s2h[j]) - M);
            z += w;
            __nv_bfloat162 wb = __float2bfloat162_rn(w);
            swp[tid] = *reinterpret_cast<unsigned*>(&wb);
        }
        if (tid < 4) { swp[n + tid] = 0u; soff[n + tid] = 0u; }
        __syncthreads();
        unsigned lof = tx * 16;
        for (int t = 4 * ty; t < n; t += 32) {
            unsigned w0 = swp[t], w1 = swp[t + 1], w2 = swp[t + 2], w3 = swp[t + 3];
            unsigned o0 = soff[t], o1 = soff[t + 1], o2 = soff[t + 2], o3 = soff[t + 3];
            uint4 v0 = *reinterpret_cast<const uint4*>(Wb + o0 + lof);
            uint4 v1 = *reinterpret_cast<const uint4*>(Wb + o1 + lof);
            uint4 v2 = *reinterpret_cast<const uint4*>(Wb + o2 + lof);
            uint4 v3 = *reinterpret_cast<const uint4*>(Wb + o3 + lof);
            HF4(A0, w0, v0) HF4(A1, w1, v1) HF4(A2, w2, v2) HF4(A3, w3, v3)
        }
    }
#undef HF4
#undef BC2
#pragma unroll
    for (int k = 0; k < 4; k++) {
        A0[k] = __hadd2(A0[k], A1[k]);
        A2[k] = __hadd2(A2[k], A3[k]);
        A0[k] = __hadd2(A0[k], A2[k]);
    }

    // z: warp reduce then per-warp slot
    for (int o = 16; o; o >>= 1) z += __shfl_xor_sync(0xFFFFFFFFu, z, o);
    if (tx == 0) szw[ty] = z;

    // feature reduce across 8 warps (fp32)
    {
        float2 f0 = __bfloat1622float2(A0[0]);
        float2 f1 = __bfloat1622float2(A0[1]);
        float2 f2 = __bfloat1622float2(A0[2]);
        float2 f3 = __bfloat1622float2(A0[3]);
        *reinterpret_cast<float4*>(&sacc[ty * 256 + tx * 8]) =
            make_float4(f0.x, f0.y, f1.x, f1.y);
        *reinterpret_cast<float4*>(&sacc[ty * 256 + tx * 8 + 4]) =
            make_float4(f2.x, f2.y, f3.x, f3.y);
    }
    __syncthreads();
#pragma unroll
    for (int s = 4; s; s >>= 1) {
        if (ty < s) {
            float4* d0 = reinterpret_cast<float4*>(&sacc[ty * 256 + tx * 8]);
            float4* o0 = reinterpret_cast<float4*>(&sacc[(ty + s) * 256 + tx * 8]);
            float4 a = d0[0], b = o0[0];
            a.x += b.x; a.y += b.y; a.z += b.z; a.w += b.w; d0[0] = a;
            float4 c = d0[1], e = o0[1];
            c.x += e.x; c.y += e.y; c.z += e.z; c.w += e.w; d0[1] = c;
        }
        __syncthreads();
    }
    if (ty == 0) {
        float Z = szw[0] + szw[1] + szw[2] + szw[3] + szw[4] + szw[5] + szw[6] + szw[7];
        float inv = 1.0f / Z;
        float o[8];
#pragma unroll
        for (int k = 0; k < 8; k++) {
            float t = sacc[tx * 8 + k] * inv;
            o[k] = t > 0.f ? t : expm1f(t);   // elu
        }
        uint4 w;
        __nv_bfloat162 p;
        p = __float22bfloat162_rn(make_float2(o[0], o[1])); w.x = *(unsigned int*)&p;
        p = __float22bfloat162_rn(make_float2(o[2], o[3])); w.y = *(unsigned int*)&p;
        p = __float22bfloat162_rn(make_float2(o[4], o[5])); w.z = *(unsigned int*)&p;
        p = __float22bfloat162_rn(make_float2(o[6], o[7])); w.w = *(unsigned int*)&p;
        *reinterpret_cast<uint4*>(out + tx * 8) = w;
    }
}

// fp32 aggregation (FOUT=64, out layer 0, no elu)
__global__ void k_agg64(const float* __restrict__ Wh, const float* __restrict__ s1,
                        const float* __restrict__ s2, const float* __restrict__ Mp,
                        const int* __restrict__ rp, const int* __restrict__ ci,
                        float* __restrict__ out) {
    constexpr int TX = 16, TY = 16;
    int row = blockIdx.x;
    int tid = threadIdx.x;
    int tx = tid % TX, ty = tid / TX;
    __shared__ float sw[256];
    __shared__ int sj[256];
    __shared__ float4 sacc[256];
    __shared__ float sz[256];
    float s1i = s1[row];
    float M = Mp[0];
    int rs = rp[row], re = rp[row + 1];
    float4 acc = make_float4(0.f, 0.f, 0.f, 0.f);
    float z = 0.f;
    for (int base = rs; base < re; base += 256) {
        int n = min(256, re - base);
        __syncthreads();
        for (int t = tid; t < n; t += 256) {
            int j = ci[base + t];
            sj[t] = j;
            float w = __expf(lrelu(s1i + s2[j]) - M);
            sw[t] = w;
            z += w;
        }
        __syncthreads();
        for (int t = ty; t < n; t += TY) {
            float w = sw[t];
            float4 v = reinterpret_cast<const float4*>(Wh + (long)sj[t] * 64)[tx];
            acc.x += w * v.x; acc.y += w * v.y; acc.z += w * v.z; acc.w += w * v.w;
        }
    }
    sacc[tid] = acc; sz[tid] = z; __syncthreads();
    for (int s = 128; s; s >>= 1) { if (tid < s) sz[tid] += sz[tid + s]; __syncthreads(); }
    if (ty == 0) {
        float4 a = sacc[tx];
#pragma unroll
        for (int yy = 1; yy < TY; yy++) {
            float4 b = sacc[yy * TX + tx];
            a.x += b.x; a.y += b.y; a.z += b.z; a.w += b.w;
        }
        float inv = 1.0f / sz[0];
        *reinterpret_cast<float4*>(out + (long)row * 64 + tx * 4) =
            make_float4(a.x * inv, a.y * inv, a.z * inv, a.w * inv);
    }
}

// FOUT == 1 aggregation
__global__ void k_agg1(const float* __restrict__ whc, const float* __restrict__ s1,
                       const float* __restrict__ s2, const float* __restrict__ Mp,
                       const int* __restrict__ rp, const int* __restrict__ ci,
                       float* __restrict__ out) {
    int row = blockIdx.x, tid = threadIdx.x;
    __shared__ float sa[256], szz[256];
    float s1i = s1[row], M = Mp[0];
    int rs = rp[row], re = rp[row + 1];
    float acc = 0.f, z = 0.f;
    for (int e = rs + tid; e < re; e += 256) {
        int j = ci[e];
        float w = __expf(lrelu(s1i + s2[j]) - M);
        z += w;
        acc += w * whc[j];
    }
    sa[tid] = acc; szz[tid] = z; __syncthreads();
    for (int s = 128; s; s >>= 1) {
        if (tid < s) { sa[tid] += sa[tid + s]; szz[tid] += szz[tid + s]; }
        __syncthreads();
    }
    if (tid == 0) out[row] = sa[0] / szz[0];
}

__global__ void k_out1s(const float* __restrict__ h, const float* __restrict__ Wo1,
                        const float* __restrict__ ao1, float* __restrict__ whc,
                        float* __restrict__ s1, float* __restrict__ s2) {
    int gw = (blockIdx.x * blockDim.x + threadIdx.x) >> 5;
    int lane = threadIdx.x & 31;
    if (gw >= NN) return;
    float d = 0.f;
    for (int f = lane; f < 64; f += 32) d += h[(long)gw * 64 + f] * Wo1[f];
    for (int o = 16; o; o >>= 1) d += __shfl_xor_sync(0xFFFFFFFFu, d, o);
    if (lane == 0) { whc[gw] = d; s1[gw] = d * ao1[0]; s2[gw] = d * ao1[1]; }
}

// ---------------- bf16 tensor-core GEMM ----------------
__device__ __forceinline__ void ldsm4(unsigned& r0, unsigned& r1, unsigned& r2, unsigned& r3,
                                      unsigned addr) {
    asm volatile("ldmatrix.sync.aligned.m8n8.x4.shared.b16 {%0,%1,%2,%3}, [%4];"
                 : "=r"(r0), "=r"(r1), "=r"(r2), "=r"(r3) : "r"(addr));
}
__device__ __forceinline__ void ldsm4t(unsigned& r0, unsigned& r1, unsigned& r2, unsigned& r3,
                                       unsigned addr) {
    asm volatile("ldmatrix.sync.aligned.m8n8.x4.trans.shared.b16 {%0,%1,%2,%3}, [%4];"
                 : "=r"(r0), "=r"(r1), "=r"(r2), "=r"(r3) : "r"(addr));
}
__device__ __forceinline__ void mma16816(float* c, unsigned a0, unsigned a1, unsigned a2,
                                         unsigned a3, unsigned b0, unsigned b1) {
    asm volatile(
        "mma.sync.aligned.m16n8k16.row.col.f32.bf16.bf16.f32 "
        "{%0,%1,%2,%3},{%4,%5,%6,%7},{%8,%9},{%0,%1,%2,%3};"
        : "+f"(c[0]), "+f"(c[1]), "+f"(c[2]), "+f"(c[3])
        : "r"(a0), "r"(a1), "r"(a2), "r"(a3), "r"(b0), "r"(b1));
}

#define GA_ROWB 80
#define GB_ROWB 272
#define GA_BYTES (128 * GA_ROWB)

__global__ void __launch_bounds__(256, 2) k_bgemm(
    const __nv_bfloat16* __restrict__ A, const __nv_bfloat16* __restrict__ B,
    float* __restrict__ C, unsigned int* __restrict__ Cb,
    int M, int N, int K, long sA, long sB, long sC, long sCb) {
    __shared__ __align__(16) unsigned char sm[GA_BYTES + 32 * GB_ROWB];
    A += (long)blockIdx.z * sA;
    B += (long)blockIdx.z * sB;
    if (C) C += (long)blockIdx.z * sC;
    if (Cb) Cb += (long)blockIdx.z * sCb;

    int tid = threadIdx.x;
    int warp = tid >> 5, lane = tid & 31;
    int wm = warp & 3, wn = warp >> 2;
    int m0 = blockIdx.y * 128, n0 = blockIdx.x * 128;

    uint4* As4 = reinterpret_cast<uint4*>(sm);
    uint4* Bs4 = reinterpret_cast<uint4*>(sm + GA_BYTES);

    int ar = tid >> 2;
    int ac = tid & 3;
    int br = tid >> 4;
    int bc = tid & 15;
    bool bok = (n0 + bc * 8) < N;

    unsigned sA_base = (unsigned)__cvta_generic_to_shared(sm);
    unsigned sB_base = sA_base + GA_BYTES;
    int sub = lane >> 3, r = lane & 7;

    float acc[2][8][4] = {};
    int KT = K / 32;
    uint4 av0, av1, bv0, bv1;
    const uint4 zero4 = make_uint4(0, 0, 0, 0);

    av0 = reinterpret_cast<const uint4*>(A + (long)(m0 + ar) * K)[ac];
    av1 = reinterpret_cast<const uint4*>(A + (long)(m0 + ar + 64) * K)[ac];
    bv0 = bok ? *reinterpret_cast<const uint4*>(B + (long)br * N + n0 + bc * 8) : zero4;
    bv1 = bok ? *reinterpret_cast<const uint4*>(B + (long)(br + 16) * N + n0 + bc * 8) : zero4;

    for (int it = 0; it < KT; it++) {
        As4[ar * 5 + ac] = av0;
        As4[(ar + 64) * 5 + ac] = av1;
        Bs4[br * 17 + bc] = bv0;
        Bs4[(br + 16) * 17 + bc] = bv1;
        __syncthreads();

        if (it + 1 < KT) {
            int kof = (it + 1) * 32;
            av0 = reinterpret_cast<const uint4*>(A + (long)(m0 + ar) * K + kof)[ac];
            av1 = reinterpret_cast<const uint4*>(A + (long)(m0 + ar + 64) * K + kof)[ac];
            bv0 = bok ? *reinterpret_cast<const uint4*>(B + (long)(kof + br) * N + n0 + bc * 8) : zero4;
            bv1 = bok ? *reinterpret_cast<const uint4*>(B + (long)(kof + br + 16) * N + n0 + bc * 8) : zero4;
        }

#pragma unroll
        for (int ks = 0; ks < 2; ks++) {
            unsigned a[2][4];
#pragma unroll
            for (int i = 0; i < 2; i++) {
                unsigned addr = sA_base
                    + (unsigned)((wm * 32 + i * 16 + (sub & 1) * 8 + r) * GA_ROWB
                                 + ks * 32 + (sub >> 1) * 16);
                ldsm4(a[i][0], a[i][1], a[i][2], a[i][3], addr);
            }
            unsigned b[4][4];
#pragma unroll
            for (int j = 0; j < 4; j++) {
                unsigned addr = sB_base
                    + (unsigned)((ks * 16 + (sub & 1) * 8 + r) * GB_ROWB
                                 + (wn * 64 + j * 16 + (sub >> 1) * 8) * 2);
                ldsm4t(b[j][0], b[j][1], b[j][2], b[j][3], addr);
            }
#pragma unroll
            for (int i = 0; i < 2; i++) {
#pragma unroll
                for (int j = 0; j < 4; j++) {
                    mma16816(acc[i][2 * j],     a[i][0], a[i][1], a[i][2], a[i][3],
                             b[j][0], b[j][1]);
                    mma16816(acc[i][2 * j + 1], a[i][0], a[i][1], a[i][2], a[i][3],
                             b[j][2], b[j][3]);
                }
            }
        }
        __syncthreads();
    }

    int g = lane >> 2, ti = lane & 3;
#pragma unroll
    for (int i = 0; i < 2; i++) {
#pragma unroll
        for (int jj = 0; jj < 8; jj++) {
            int row = m0 + wm * 32 + i * 16 + g;
            int col = n0 + wn * 64 + jj * 8 + ti * 2;
            if (col < N) {
                float* c = acc[i][jj];
                if (C) {
                    *reinterpret_cast<float2*>(C + (long)row * N + col) = make_float2(c[0], c[1]);
                    *reinterpret_cast<float2*>(C + (long)(row + 8) * N + col) = make_float2(c[2], c[3]);
                }
                if (Cb) {
                    __nv_bfloat162 p0 = __float22bfloat162_rn(make_float2(c[0], c[1]));
                    __nv_bfloat162 p1 = __float22bfloat162_rn(make_float2(c[2], c[3]));
                    Cb[((long)row * N + col) >> 1] = *reinterpret_cast<unsigned int*>(&p0);
                    Cb[((long)(row + 8) * N + col) >> 1] = *reinterpret_cast<unsigned int*>(&p1);
                }
            }
        }
    }
}

// ---------------- final degree MLP ----------------
__global__ void k_mlp(const float* __restrict__ hout, const float* __restrict__ dv,
                      const float* __restrict__ dW, const float* __restrict__ dW0,
                      const float* __restrict__ dW1, const float* __restrict__ dW01,
                      const float* __restrict__ dW2, const float* __restrict__ dW02,
                      const float* __restrict__ dV, const float* __restrict__ dV0,
                      float* __restrict__ out) {
    int i = blockIdx.x * blockDim.x + threadIdx.x;
    if (i >= NN) return;
    float hv = hout[i];
    float x0 = hv > 0.f ? hv : expm1f(hv);
    float x1 = dv[i];
    float h0[10];
#pragma unroll
    for (int k = 0; k < 10; k++)
        h0[k] = lrelu(x0 * dW[k] + x1 * dW[10 + k] + dW0[k]);
    float h1[20];
#pragma unroll
    for (int k = 0; k < 20; k++) {
        float t = dW01[k];
#pragma unroll
        for (int j = 0; j < 10; j++) t += h0[j] * dW1[j * 20 + k];
        h1[k] = lrelu(t);
    }
    float h2[10];
#pragma unroll
    for (int k = 0; k < 10; k++) {
        float t = dW02[k];
#pragma unroll
        for (int j = 0; j < 20; j++) t += h1[j] * dW2[j * 10 + k];
        h2[k] = lrelu(t);
    }
    float o = dV0[0];
#pragma unroll
    for (int j = 0; j < 10; j++) o += h2[j] * dV[j];
    out[i] = lrelu(o);
}

// ---------------- launch ----------------
extern "C" void kernel_launch(void* const* d_in, const int* in_sizes, int n_in,
                              void* d_out, int out_size) {
    const float* x     = (const float*)d_in[0];
    const float* adj   = (const float*)d_in[1];
    const int*   obs   = (const int*)d_in[2];
    const float* s_mat = (const float*)d_in[3];
    const float* theta = (const float*)d_in[4];
    const float* Wh0   = (const float*)d_in[5];
    const float* ah0   = (const float*)d_in[6];
    const float* Wh1   = (const float*)d_in[7];
    const float* ah1   = (const float*)d_in[8];
    const float* Wo0   = (const float*)d_in[9];
    const float* ao0   = (const float*)d_in[10];
    const float* Wo1   = (const float*)d_in[11];
    const float* ao1   = (const float*)d_in[12];
    const float* dW    = (const float*)d_in[13];
    const float* dW0   = (const float*)d_in[14];
    const float* dW1   = (const float*)d_in[15];
    const float* dW01  = (const float*)d_in[16];
    const float* dW2   = (const float*)d_in[17];
    const float* dW02  = (const float*)d_in[18];
    const float* dV    = (const float*)d_in[19];
    const float* dV0   = (const float*)d_in[20];
    float* out = (float*)d_out;

    float* fa = nullptr;
    int*   ia = nullptr;
    cudaGetSymbolAddress((void**)&fa, g_farena);
    cudaGetSymbolAddress((void**)&ia, g_iarena);

    float* P0   = fa + OFF_P0;
    float* P1   = fa + OFF_P1;
    float* oWh  = fa + OFF_OWH;
    float* ho0  = fa + OFF_HO0;
    float* whc  = fa + OFF_WHC;
    float* hout = fa + OFF_HOUT;
    float* s1   = fa + OFF_S1;
    float* s2   = fa + OFF_S2;
    float* Mp   = fa + OFF_M;
    float* dv   = fa + OFF_DV;
    __nv_bfloat16* Whb   = (__nv_bfloat16*)(fa + OFF_WHB);
    __nv_bfloat16* hinb  = (__nv_bfloat16*)(fa + OFF_HINB);
    __nv_bfloat16* h1bb  = (__nv_bfloat16*)(fa + OFF_H1B);
    __nv_bfloat16* hcatb = (__nv_bfloat16*)(fa + OFF_HCATB);
    __nv_bfloat16* W0b   = (__nv_bfloat16*)(fa + OFF_W0B);
    __nv_bfloat16* W1b   = (__nv_bfloat16*)(fa + OFF_W1B);
    __nv_bfloat16* Wo0b  = (__nv_bfloat16*)(fa + OFF_WO0B);
    int* cnt = ia + OFF_CNT;
    int* rp  = ia + OFF_RP;
    unsigned* msk = (unsigned*)(ia + OFF_MSK);
    int* ci  = ia + OFF_CI;

    const long NM = (long)NN * 256;

    // CSR (launches 1-3): bitmask + scan + decode
    k_count<<<NN, 256>>>(adj, msk, cnt);
    k_scan<<<1, 1024>>>(cnt, rp);
    k_fill<<<NN, 128>>>(msk, rp, ci);

    // launch 4: ncu PROBE — representative k_aggb on fresh CSR + steady-state data.
    // Writes only h1bb head-0 rows 0..1023, fully overwritten by the real L0 agg.
    k_aggb<<<dim3(1024, 1), 256>>>(Whb, s1, s2, Mp, rp, ci, h1bb, NM, 256);

    // degree vector
    k_rowsum<<<NN, 256>>>(s_mat, dv);

    // bf16 conversions + merged input + P projections
    k_mergeb<<<2048, 256>>>((const float4*)x, obs, (const float4*)theta, (uint2*)hinb);
    k_cvt<<<512, 256>>>((const float4*)Wh0, (uint2*)W0b, 131072);
    k_cvt<<<256, 256>>>((const float4*)Wh1, (uint2*)W1b, 65536);
    k_cvt<<<64, 256>>>((const float4*)Wo0, (uint2*)Wo0b, 16384);
    k_wa<<<dim3(128, 4), 256>>>(Wh0, ah0, P0, 512);
    k_wa<<<dim3(64, 4), 256>>>(Wh1, ah1, P1, 256);

    // ---- head layer 0 ----
    k_bgemm<<<dim3(2, 32, 4), 256>>>(hinb, W0b, nullptr, (unsigned int*)Whb,
                                     NN, 256, 512, 0L, 512L * 256, 0L, (long)NN * 128);
    k_sb<<<2048, 256>>>(hinb, 0L, P0, 512, s1, s2);
    k_max4<<<4, 512>>>(s1, s2, Mp, 4);
    k_aggb<<<dim3(NN, 4), 256>>>(Whb, s1, s2, Mp, rp, ci, h1bb, NM, 256);

    // ---- head layer 1 ----
    k_bgemm<<<dim3(2, 32, 4), 256>>>(h1bb, W1b, nullptr, (unsigned int*)Whb,
                                     NN, 256, 256, NM, 256L * 256, 0L, (long)NN * 128);
    k_sb<<<2048, 256>>>(h1bb, NM, P1, 256, s1, s2);
    k_max4<<<4, 512>>>(s1, s2, Mp, 4);
    k_aggb<<<dim3(NN, 4), 256>>>(Whb, s1, s2, Mp, rp, ci, hcatb, 256L, 1024);

    // ---- output layer 0 ----
    k_bgemm<<<dim3(1, 32, 1), 256>>>(hcatb, Wo0b, oWh, nullptr,
                                     NN, 64, 1024, 0L, 0L, 0L, 0L);
    k_s<<<512, 256>>>(oWh, ao0, 64, s1, s2);
    k_max4<<<1, 512>>>(s1, s2, Mp, 1);
    k_agg64<<<NN, 256>>>(oWh, s1, s2, Mp, rp, ci, ho0);

    // ---- output layer 1 ----
    k_out1s<<<512, 256>>>(ho0, Wo1, ao1, whc, s1, s2);
    k_max4<<<1, 512>>>(s1, s2, Mp, 1);
    k_agg1<<<NN, 256>>>(whc, s1, s2, Mp, rp, ci, hout);

    // ---- elu + degree MLP ----
    k_mlp<<<16, 256>>>(hout, dv, dW, dW0, dW1, dW01, dW2, dW02, dV, dV0, out);
}

// round 6
// speedup vs baseline: 1.0959x; 1.0959x over previous
#include <cuda_runtime.h>
#include <cuda_bf16.h>
#include <cuda_fp8.h>
#include <math.h>

#define NN 4096
#define ALPHA 0.2f

__device__ __forceinline__ float lrelu(float v){ return v >= 0.f ? v : ALPHA * v; }

// ---------------- scratch arenas (device globals; no allocation) -------------
#define OFF_P0    0L          // fp32 P0: 8*512 = 4096
#define OFF_P1    4096L       // fp32 P1: 8*256 = 2048
#define OFF_OWH   8192L       // 4096*64
#define OFF_HO0   270336L     // 4096*64
#define OFF_WHC   532480L     // 4096
#define OFF_HOUT  536576L     // 4096
#define OFF_S1    540672L     // 4*4096
#define OFF_S2    557056L     // 4*4096
#define OFF_M     573440L     // 16
#define OFF_DV    573456L     // 4096
#define OFF_WHB   577552L     // fp8 4*4096*256 bytes -> 1048576 floats
#define OFF_HINB  2674704L    // bf16 4096*512   -> 1048576 floats
#define OFF_H1B   3723280L    // bf16 4*4096*256 -> 2097152 floats
#define OFF_HCATB 5820432L    // bf16 4096*1024  -> 2097152 floats
#define OFF_W0B   7917584L    // bf16 4*512*256  -> 262144 floats
#define OFF_W1B   8179728L    // bf16 4*256*256  -> 131072 floats
#define OFF_WO0B  8310800L    // bf16 1024*64    -> 32768 floats
#define FARENA_SZ 8400000L

#define OFF_CNT   0
#define OFF_RP    4096
#define OFF_MSK   8208        // 4096*128 uints
#define OFF_CI    532496
#define IARENA_SZ 2200000

__device__ float g_farena[FARENA_SZ];
__device__ int   g_iarena[IARENA_SZ];

// ---------------- CSR construction (bitmask two-pass) ----------------
__global__ void k_count(const float* __restrict__ adj, unsigned* __restrict__ msk,
                        int* __restrict__ cnt) {
    int row = blockIdx.x, tid = threadIdx.x;
    int lane = tid & 31, wid = tid >> 5;
    const float4* p = reinterpret_cast<const float4*>(adj + (long)row * NN);
    unsigned* mrow = msk + (long)row * 128;
    int c = 0;
    for (int seg = wid; seg < 32; seg += 8) {
        float4 v = p[seg * 32 + lane];
        unsigned b0 = __ballot_sync(0xFFFFFFFFu, v.x > 0.f);
        unsigned b1 = __ballot_sync(0xFFFFFFFFu, v.y > 0.f);
        unsigned b2 = __ballot_sync(0xFFFFFFFFu, v.z > 0.f);
        unsigned b3 = __ballot_sync(0xFFFFFFFFu, v.w > 0.f);
        c += (v.x > 0.f) + (v.y > 0.f) + (v.z > 0.f) + (v.w > 0.f);
        if (lane == 0) {
            mrow[seg * 4 + 0] = b0; mrow[seg * 4 + 1] = b1;
            mrow[seg * 4 + 2] = b2; mrow[seg * 4 + 3] = b3;
        }
    }
    for (int o = 16; o; o >>= 1) c += __shfl_xor_sync(0xFFFFFFFFu, c, o);
    __shared__ int ws[8];
    if (lane == 0) ws[wid] = c;
    __syncthreads();
    if (tid == 0)
        cnt[row] = ws[0] + ws[1] + ws[2] + ws[3] + ws[4] + ws[5] + ws[6] + ws[7];
}

__global__ void k_scan(const int* __restrict__ cnt, int* __restrict__ rp) {
    __shared__ int s[1024];
    int t = threadIdx.x;
    int v[4]; int loc = 0;
#pragma unroll
    for (int k = 0; k < 4; k++) { v[k] = cnt[t * 4 + k]; loc += v[k]; }
    s[t] = loc; __syncthreads();
    for (int off = 1; off < 1024; off <<= 1) {
        int add = (t >= off) ? s[t - off] : 0;
        __syncthreads();
        s[t] += add;
        __syncthreads();
    }
    int run = (t == 0) ? 0 : s[t - 1];
#pragma unroll
    for (int k = 0; k < 4; k++) { rp[t * 4 + k] = run; run += v[k]; }
    if (t == 1023) rp[NN] = run;
}

__global__ void k_fill(const unsigned* __restrict__ msk, const int* __restrict__ rp,
                       int* __restrict__ ci) {
    int row = blockIdx.x, tid = threadIdx.x;
    int lane = tid & 31, wid = tid >> 5;
    unsigned m = msk[(long)row * 128 + tid];
    int c = __popc(m);
    int pre = c;
    for (int o = 1; o < 32; o <<= 1) {
        int v = __shfl_up_sync(0xFFFFFFFFu, pre, o);
        if (lane >= o) pre += v;
    }
    __shared__ int wt[4];
    if (lane == 31) wt[wid] = pre;
    __syncthreads();
    int woff = 0;
    for (int i = 0; i < wid; i++) woff += wt[i];
    int pos = rp[row] + woff + pre - c;
    int base = (tid >> 2) * 128 + (tid & 3);
    while (m) {
        int b = __ffs(m) - 1;
        m &= m - 1;
        ci[pos++] = base + b * 4;
    }
}

// ---------------- misc ----------------
__global__ void k_rowsum(const float* __restrict__ sm, float* __restrict__ dv) {
    int row = blockIdx.x, tid = threadIdx.x;
    const float4* p = reinterpret_cast<const float4*>(sm + (long)row * NN);
    float acc = 0.f;
    for (int i = tid; i < NN / 4; i += 256) { float4 v = p[i]; acc += v.x + v.y + v.z + v.w; }
    __shared__ float s[256];
    s[tid] = acc; __syncthreads();
    for (int st = 128; st; st >>= 1) { if (tid < st) s[tid] += s[tid + st]; __syncthreads(); }
    if (tid == 0) dv[row] = s[0];
}

__global__ void k_mergeb(const float4* __restrict__ x, const int* __restrict__ obs,
                         const float4* __restrict__ theta, uint2* __restrict__ out) {
    long i = (long)blockIdx.x * blockDim.x + threadIdx.x;
    int row = (int)(i >> 7);
    int f4 = (int)(i & 127);
    float4 v = x[i];
    if (obs[row] == 1) { float4 t = theta[f4]; v.x += t.x; v.y += t.y; v.z += t.z; v.w += t.w; }
    __nv_bfloat162 p0 = __float22bfloat162_rn(make_float2(v.x, v.y));
    __nv_bfloat162 p1 = __float22bfloat162_rn(make_float2(v.z, v.w));
    uint2 w;
    w.x = *reinterpret_cast<unsigned int*>(&p0);
    w.y = *reinterpret_cast<unsigned int*>(&p1);
    out[i] = w;
}

__global__ void k_cvt(const float4* __restrict__ in, uint2* __restrict__ out, int n4) {
    int i = blockIdx.x * blockDim.x + threadIdx.x;
    if (i >= n4) return;
    float4 v = in[i];
    __nv_bfloat162 p0 = __float22bfloat162_rn(make_float2(v.x, v.y));
    __nv_bfloat162 p1 = __float22bfloat162_rn(make_float2(v.z, v.w));
    uint2 w;
    w.x = *reinterpret_cast<unsigned int*>(&p0);
    w.y = *reinterpret_cast<unsigned int*>(&p1);
    out[i] = w;
}

// P[(2h+c)*Fin + f] = sum_d W[h,f,d] * a[h, c*256 + d]
__global__ void k_wa(const float* __restrict__ W, const float* __restrict__ a,
                     float* __restrict__ P, int Fin) {
    int h = blockIdx.y;
    int idx = blockIdx.x * 8 + (threadIdx.x >> 5);
    int lane = threadIdx.x & 31;
    if (idx >= 2 * Fin) return;
    int c = idx / Fin, f = idx % Fin;
    const float* wrow = W + ((long)h * Fin + f) * 256;
    const float* av = a + h * 512 + c * 256;
    float d = 0.f;
    for (int k = lane; k < 256; k += 32) d = fmaf(wrow[k], av[k], d);
    for (int o = 16; o; o >>= 1) d += __shfl_xor_sync(0xFFFFFFFFu, d, o);
    if (lane == 0) P[(2 * h + c) * Fin + f] = d;
}

// s1/s2 from bf16 activations
__global__ void __launch_bounds__(256) k_sb(
    const __nv_bfloat16* __restrict__ act, long headStride,
    const float* __restrict__ P, int K,
    float* __restrict__ s1, float* __restrict__ s2) {
    __shared__ float Ps[4096];
    int tid = threadIdx.x;
    for (int i = tid; i < 8 * K; i += 256) Ps[i] = P[i];
    __syncthreads();
    int gw = blockIdx.x * 8 + (tid >> 5);
    int lane = tid & 31;
    int row = gw >> 2, h = gw & 3;
    const __nv_bfloat16* a = act + (long)h * headStride + (long)row * K;
    const float* p1 = Ps + (2 * h) * K;
    const float* p2 = p1 + K;
    float d1 = 0.f, d2 = 0.f;
    for (int f = lane * 2; f < K; f += 64) {
        unsigned u = *reinterpret_cast<const unsigned*>(a + f);
        float x0 = __uint_as_float(u << 16);
        float x1 = __uint_as_float(u & 0xFFFF0000u);
        d1 = fmaf(x0, p1[f], fmaf(x1, p1[f + 1], d1));
        d2 = fmaf(x0, p2[f], fmaf(x1, p2[f + 1], d2));
    }
    for (int o = 16; o; o >>= 1) {
        d1 += __shfl_xor_sync(0xFFFFFFFFu, d1, o);
        d2 += __shfl_xor_sync(0xFFFFFFFFu, d2, o);
    }
    if (lane == 0) { s1[h * NN + row] = d1; s2[h * NN + row] = d2; }
}

// s for out layer 0 (fout=64, fp32)
__global__ void k_s(const float* __restrict__ Wh, const float* __restrict__ a, int fout,
                    float* __restrict__ s1, float* __restrict__ s2) {
    int gw = (blockIdx.x * blockDim.x + threadIdx.x) >> 5;
    int lane = threadIdx.x & 31;
    if (gw >= NN) return;
    const float* row = Wh + (long)gw * fout;
    float d1 = 0.f, d2 = 0.f;
    for (int f = lane; f < fout; f += 32) {
        float v = row[f];
        d1 += v * a[f];
        d2 += v * a[fout + f];
    }
    for (int o = 16; o; o >>= 1) {
        d1 += __shfl_xor_sync(0xFFFFFFFFu, d1, o);
        d2 += __shfl_xor_sync(0xFFFFFFFFu, d2, o);
    }
    if (lane == 0) { s1[gw] = d1; s2[gw] = d2; }
}

// per-head M = leaky(max s1 + max s2)
__global__ void k_max4(const float* __restrict__ s1, const float* __restrict__ s2,
                       float* __restrict__ Mp, int nheads) {
    int h = blockIdx.x;
    const float* a = s1 + (long)h * NN;
    const float* b = s2 + (long)h * NN;
    __shared__ float m1s[512], m2s[512];
    int t = threadIdx.x;
    float m1 = -1e30f, m2 = -1e30f;
    for (int i = t; i < NN; i += 512) { m1 = fmaxf(m1, a[i]); m2 = fmaxf(m2, b[i]); }
    m1s[t] = m1; m2s[t] = m2; __syncthreads();
    for (int s = 256; s; s >>= 1) {
        if (t < s) { m1s[t] = fmaxf(m1s[t], m1s[t + s]); m2s[t] = fmaxf(m2s[t], m2s[t + s]); }
        __syncthreads();
    }
    if (t == 0) Mp[h] = lrelu(m1s[0] + m2s[0]);
}

// ---------------- FP8 sparse aggregation (FOUT=256, e4m3 gather) -------------
__global__ void __launch_bounds__(256) k_aggb(
    const unsigned char* __restrict__ WhbAll,   // fp8 e4m3, 256 B per row
    const float* __restrict__ s1, const float* __restrict__ s2,
    const float* __restrict__ Mp,
    const int* __restrict__ rp, const int* __restrict__ ci,
    __nv_bfloat16* __restrict__ outBase, long headStride, int ostride) {
    int row = blockIdx.x;
    int h = blockIdx.y;
    const unsigned char* Wb = WhbAll + (long)h * NN * 256;
    const float* s1h = s1 + (long)h * NN;
    const float* s2h = s2 + (long)h * NN;
    __nv_bfloat16* out = outBase + (long)h * headStride + (long)row * ostride;

    int tid = threadIdx.x;
    int tx = tid & 31;
    int ty = tid >> 5;

    __shared__ unsigned swp[260];     // half2(w,w)
    __shared__ unsigned soff[260];    // byte offsets (j*256)
    __shared__ float    sacc[2048];
    __shared__ float    szw[8];

    float s1i = s1h[row];
    float M = Mp[h];
    int rs = rp[row], re = rp[row + 1];

    __half2 zero2 = __float2half2_rn(0.f);
    __half2 A0[4] = {zero2, zero2, zero2, zero2};
    __half2 A1[4] = {zero2, zero2, zero2, zero2};
    __half2 A2[4] = {zero2, zero2, zero2, zero2};
    __half2 A3[4] = {zero2, zero2, zero2, zero2};
    float z = 0.f;

#define CVT8(us) (*reinterpret_cast<__half2*>(&(hrtmp = __nv_cvt_fp8x2_to_halfraw2((us), __NV_E4M3))))
    __half2_raw hrtmp;
#define HF4(A, wu, v) { __half2 Wv = *reinterpret_cast<const __half2*>(&(wu)); \
    A[0] = __hfma2(Wv, CVT8((unsigned short)((v).x & 0xFFFFu)), A[0]); \
    A[1] = __hfma2(Wv, CVT8((unsigned short)((v).x >> 16)),     A[1]); \
    A[2] = __hfma2(Wv, CVT8((unsigned short)((v).y & 0xFFFFu)), A[2]); \
    A[3] = __hfma2(Wv, CVT8((unsigned short)((v).y >> 16)),     A[3]); }

    for (int base = rs; base < re; base += 256) {
        int n = min(256, re - base);
        __syncthreads();
        if (tid < n) {
            int j = ci[base + tid];
            soff[tid] = (unsigned)j << 8;
            float w = __expf(lrelu(s1i + s2h[j]) - M);
            z += w;
            __half2 wb = __float2half2_rn(w);
            swp[tid] = *reinterpret_cast<unsigned*>(&wb);
        }
        if (tid < 4) { swp[n + tid] = 0u; soff[n + tid] = 0u; }
        __syncthreads();
        unsigned lof = tx * 8;
        for (int t = 4 * ty; t < n; t += 32) {
            unsigned w0 = swp[t], w1 = swp[t + 1], w2 = swp[t + 2], w3 = swp[t + 3];
            unsigned o0 = soff[t], o1 = soff[t + 1], o2 = soff[t + 2], o3 = soff[t + 3];
            uint2 v0 = *reinterpret_cast<const uint2*>(Wb + o0 + lof);
            uint2 v1 = *reinterpret_cast<const uint2*>(Wb + o1 + lof);
            uint2 v2 = *reinterpret_cast<const uint2*>(Wb + o2 + lof);
            uint2 v3 = *reinterpret_cast<const uint2*>(Wb + o3 + lof);
            HF4(A0, w0, v0) HF4(A1, w1, v1) HF4(A2, w2, v2) HF4(A3, w3, v3)
        }
    }
#undef HF4
#undef CVT8
#pragma unroll
    for (int k = 0; k < 4; k++) {
        A0[k] = __hadd2(A0[k], A1[k]);
        A2[k] = __hadd2(A2[k], A3[k]);
        A0[k] = __hadd2(A0[k], A2[k]);
    }

    for (int o = 16; o; o >>= 1) z += __shfl_xor_sync(0xFFFFFFFFu, z, o);
    if (tx == 0) szw[ty] = z;

    {
        float2 f0 = __half22float2(A0[0]);
        float2 f1 = __half22float2(A0[1]);
        float2 f2 = __half22float2(A0[2]);
        float2 f3 = __half22float2(A0[3]);
        *reinterpret_cast<float4*>(&sacc[ty * 256 + tx * 8]) =
            make_float4(f0.x, f0.y, f1.x, f1.y);
        *reinterpret_cast<float4*>(&sacc[ty * 256 + tx * 8 + 4]) =
            make_float4(f2.x, f2.y, f3.x, f3.y);
    }
    __syncthreads();
#pragma unroll
    for (int s = 4; s; s >>= 1) {
        if (ty < s) {
            float4* d0 = reinterpret_cast<float4*>(&sacc[ty * 256 + tx * 8]);
            float4* o0 = reinterpret_cast<float4*>(&sacc[(ty + s) * 256 + tx * 8]);
            float4 a = d0[0], b = o0[0];
            a.x += b.x; a.y += b.y; a.z += b.z; a.w += b.w; d0[0] = a;
            float4 c = d0[1], e = o0[1];
            c.x += e.x; c.y += e.y; c.z += e.z; c.w += e.w; d0[1] = c;
        }
        __syncthreads();
    }
    if (ty == 0) {
        float Z = szw[0] + szw[1] + szw[2] + szw[3] + szw[4] + szw[5] + szw[6] + szw[7];
        float inv = 1.0f / Z;
        float o[8];
#pragma unroll
        for (int k = 0; k < 8; k++) {
            float t = sacc[tx * 8 + k] * inv;
            o[k] = t > 0.f ? t : expm1f(t);   // elu
        }
        uint4 w;
        __nv_bfloat162 p;
        p = __float22bfloat162_rn(make_float2(o[0], o[1])); w.x = *(unsigned int*)&p;
        p = __float22bfloat162_rn(make_float2(o[2], o[3])); w.y = *(unsigned int*)&p;
        p = __float22bfloat162_rn(make_float2(o[4], o[5])); w.z = *(unsigned int*)&p;
        p = __float22bfloat162_rn(make_float2(o[6], o[7])); w.w = *(unsigned int*)&p;
        *reinterpret_cast<uint4*>(out + tx * 8) = w;
    }
}

// fp32 aggregation (FOUT=64, out layer 0, no elu)
__global__ void k_agg64(const float* __restrict__ Wh, const float* __restrict__ s1,
                        const float* __restrict__ s2, const float* __restrict__ Mp,
                        const int* __restrict__ rp, const int* __restrict__ ci,
                        float* __restrict__ out) {
    constexpr int TX = 16, TY = 16;
    int row = blockIdx.x;
    int tid = threadIdx.x;
    int tx = tid % TX, ty = tid / TX;
    __shared__ float sw[256];
    __shared__ int sj[256];
    __shared__ float4 sacc[256];
    __shared__ float sz[256];
    float s1i = s1[row];
    float M = Mp[0];
    int rs = rp[row], re = rp[row + 1];
    float4 acc = make_float4(0.f, 0.f, 0.f, 0.f);
    float z = 0.f;
    for (int base = rs; base < re; base += 256) {
        int n = min(256, re - base);
        __syncthreads();
        for (int t = tid; t < n; t += 256) {
            int j = ci[base + t];
            sj[t] = j;
            float w = __expf(lrelu(s1i + s2[j]) - M);
            sw[t] = w;
            z += w;
        }
        __syncthreads();
        for (int t = ty; t < n; t += TY) {
            float w = sw[t];
            float4 v = reinterpret_cast<const float4*>(Wh + (long)sj[t] * 64)[tx];
            acc.x += w * v.x; acc.y += w * v.y; acc.z += w * v.z; acc.w += w * v.w;
        }
    }
    sacc[tid] = acc; sz[tid] = z; __syncthreads();
    for (int s = 128; s; s >>= 1) { if (tid < s) sz[tid] += sz[tid + s]; __syncthreads(); }
    if (ty == 0) {
        float4 a = sacc[tx];
#pragma unroll
        for (int yy = 1; yy < TY; yy++) {
            float4 b = sacc[yy * TX + tx];
            a.x += b.x; a.y += b.y; a.z += b.z; a.w += b.w;
        }
        float inv = 1.0f / sz[0];
        *reinterpret_cast<float4*>(out + (long)row * 64 + tx * 4) =
            make_float4(a.x * inv, a.y * inv, a.z * inv, a.w * inv);
    }
}

// FOUT == 1 aggregation
__global__ void k_agg1(const float* __restrict__ whc, const float* __restrict__ s1,
                       const float* __restrict__ s2, const float* __restrict__ Mp,
                       const int* __restrict__ rp, const int* __restrict__ ci,
                       float* __restrict__ out) {
    int row = blockIdx.x, tid = threadIdx.x;
    __shared__ float sa[256], szz[256];
    float s1i = s1[row], M = Mp[0];
    int rs = rp[row], re = rp[row + 1];
    float acc = 0.f, z = 0.f;
    for (int e = rs + tid; e < re; e += 256) {
        int j = ci[e];
        float w = __expf(lrelu(s1i + s2[j]) - M);
        z += w;
        acc += w * whc[j];
    }
    sa[tid] = acc; szz[tid] = z; __syncthreads();
    for (int s = 128; s; s >>= 1) {
        if (tid < s) { sa[tid] += sa[tid + s]; szz[tid] += szz[tid + s]; }
        __syncthreads();
    }
    if (tid == 0) out[row] = sa[0] / szz[0];
}

__global__ void k_out1s(const float* __restrict__ h, const float* __restrict__ Wo1,
                        const float* __restrict__ ao1, float* __restrict__ whc,
                        float* __restrict__ s1, float* __restrict__ s2) {
    int gw = (blockIdx.x * blockDim.x + threadIdx.x) >> 5;
    int lane = threadIdx.x & 31;
    if (gw >= NN) return;
    float d = 0.f;
    for (int f = lane; f < 64; f += 32) d += h[(long)gw * 64 + f] * Wo1[f];
    for (int o = 16; o; o >>= 1) d += __shfl_xor_sync(0xFFFFFFFFu, d, o);
    if (lane == 0) { whc[gw] = d; s1[gw] = d * ao1[0]; s2[gw] = d * ao1[1]; }
}

// ---------------- bf16 tensor-core GEMM (fp8 side-output) ----------------
__device__ __forceinline__ void ldsm4(unsigned& r0, unsigned& r1, unsigned& r2, unsigned& r3,
                                      unsigned addr) {
    asm volatile("ldmatrix.sync.aligned.m8n8.x4.shared.b16 {%0,%1,%2,%3}, [%4];"
                 : "=r"(r0), "=r"(r1), "=r"(r2), "=r"(r3) : "r"(addr));
}
__device__ __forceinline__ void ldsm4t(unsigned& r0, unsigned& r1, unsigned& r2, unsigned& r3,
                                       unsigned addr) {
    asm volatile("ldmatrix.sync.aligned.m8n8.x4.trans.shared.b16 {%0,%1,%2,%3}, [%4];"
                 : "=r"(r0), "=r"(r1), "=r"(r2), "=r"(r3) : "r"(addr));
}
__device__ __forceinline__ void mma16816(float* c, unsigned a0, unsigned a1, unsigned a2,
                                         unsigned a3, unsigned b0, unsigned b1) {
    asm volatile(
        "mma.sync.aligned.m16n8k16.row.col.f32.bf16.bf16.f32 "
        "{%0,%1,%2,%3},{%4,%5,%6,%7},{%8,%9},{%0,%1,%2,%3};"
        : "+f"(c[0]), "+f"(c[1]), "+f"(c[2]), "+f"(c[3])
        : "r"(a0), "r"(a1), "r"(a2), "r"(a3), "r"(b0), "r"(b1));
}

#define GA_ROWB 80
#define GB_ROWB 272
#define GA_BYTES (128 * GA_ROWB)

__global__ void __launch_bounds__(256, 2) k_bgemm(
    const __nv_bfloat16* __restrict__ A, const __nv_bfloat16* __restrict__ B,
    float* __restrict__ C, unsigned short* __restrict__ C8,
    int M, int N, int K, long sA, long sB, long sC, long sC8) {
    __shared__ __align__(16) unsigned char sm[GA_BYTES + 32 * GB_ROWB];
    A += (long)blockIdx.z * sA;
    B += (long)blockIdx.z * sB;
    if (C) C += (long)blockIdx.z * sC;
    if (C8) C8 += (long)blockIdx.z * sC8;

    int tid = threadIdx.x;
    int warp = tid >> 5, lane = tid & 31;
    int wm = warp & 3, wn = warp >> 2;
    int m0 = blockIdx.y * 128, n0 = blockIdx.x * 128;

    uint4* As4 = reinterpret_cast<uint4*>(sm);
    uint4* Bs4 = reinterpret_cast<uint4*>(sm + GA_BYTES);

    int ar = tid >> 2;
    int ac = tid & 3;
    int br = tid >> 4;
    int bc = tid & 15;
    bool bok = (n0 + bc * 8) < N;

    unsigned sA_base = (unsigned)__cvta_generic_to_shared(sm);
    unsigned sB_base = sA_base + GA_BYTES;
    int sub = lane >> 3, r = lane & 7;

    float acc[2][8][4] = {};
    int KT = K / 32;
    uint4 av0, av1, bv0, bv1;
    const uint4 zero4 = make_uint4(0, 0, 0, 0);

    av0 = reinterpret_cast<const uint4*>(A + (long)(m0 + ar) * K)[ac];
    av1 = reinterpret_cast<const uint4*>(A + (long)(m0 + ar + 64) * K)[ac];
    bv0 = bok ? *reinterpret_cast<const uint4*>(B + (long)br * N + n0 + bc * 8) : zero4;
    bv1 = bok ? *reinterpret_cast<const uint4*>(B + (long)(br + 16) * N + n0 + bc * 8) : zero4;

    for (int it = 0; it < KT; it++) {
        As4[ar * 5 + ac] = av0;
        As4[(ar + 64) * 5 + ac] = av1;
        Bs4[br * 17 + bc] = bv0;
        Bs4[(br + 16) * 17 + bc] = bv1;
        __syncthreads();

        if (it + 1 < KT) {
            int kof = (it + 1) * 32;
            av0 = reinterpret_cast<const uint4*>(A + (long)(m0 + ar) * K + kof)[ac];
            av1 = reinterpret_cast<const uint4*>(A + (long)(m0 + ar + 64) * K + kof)[ac];
            bv0 = bok ? *reinterpret_cast<const uint4*>(B + (long)(kof + br) * N + n0 + bc * 8) : zero4;
            bv1 = bok ? *reinterpret_cast<const uint4*>(B + (long)(kof + br + 16) * N + n0 + bc * 8) : zero4;
        }

#pragma unroll
        for (int ks = 0; ks < 2; ks++) {
            unsigned a[2][4];
#pragma unroll
            for (int i = 0; i < 2; i++) {
                unsigned addr = sA_base
                    + (unsigned)((wm * 32 + i * 16 + (sub & 1) * 8 + r) * GA_ROWB
                                 + ks * 32 + (sub >> 1) * 16);
                ldsm4(a[i][0], a[i][1], a[i][2], a[i][3], addr);
            }
            unsigned b[4][4];
#pragma unroll
            for (int j = 0; j < 4; j++) {
                unsigned addr = sB_base
                    + (unsigned)((ks * 16 + (sub & 1) * 8 + r) * GB_ROWB
                                 + (wn * 64 + j * 16 + (sub >> 1) * 8) * 2);
                ldsm4t(b[j][0], b[j][1], b[j][2], b[j][3], addr);
            }
#pragma unroll
            for (int i = 0; i < 2; i++) {
#pragma unroll
                for (int j = 0; j < 4; j++) {
                    mma16816(acc[i][2 * j],     a[i][0], a[i][1], a[i][2], a[i][3],
                             b[j][0], b[j][1]);
                    mma16816(acc[i][2 * j + 1], a[i][0], a[i][1], a[i][2], a[i][3],
                             b[j][2], b[j][3]);
                }
            }
        }
        __syncthreads();
    }

    int g = lane >> 2, ti = lane & 3;
#pragma unroll
    for (int i = 0; i < 2; i++) {
#pragma unroll
        for (int jj = 0; jj < 8; jj++) {
            int row = m0 + wm * 32 + i * 16 + g;
            int col = n0 + wn * 64 + jj * 8 + ti * 2;
            if (col < N) {
                float* c = acc[i][jj];
                if (C) {
                    *reinterpret_cast<float2*>(C + (long)row * N + col) = make_float2(c[0], c[1]);
                    *reinterpret_cast<float2*>(C + (long)(row + 8) * N + col) = make_float2(c[2], c[3]);
                }
                if (C8) {
                    C8[((long)row * N + col) >> 1] =
                        __nv_cvt_float2_to_fp8x2(make_float2(c[0], c[1]), __NV_SATFINITE, __NV_E4M3);
                    C8[((long)(row + 8) * N + col) >> 1] =
                        __nv_cvt_float2_to_fp8x2(make_float2(c[2], c[3]), __NV_SATFINITE, __NV_E4M3);
                }
            }
        }
    }
}

// ---------------- final degree MLP ----------------
__global__ void k_mlp(const float* __restrict__ hout, const float* __restrict__ dv,
                      const float* __restrict__ dW, const float* __restrict__ dW0,
                      const float* __restrict__ dW1, const float* __restrict__ dW01,
                      const float* __restrict__ dW2, const float* __restrict__ dW02,
                      const float* __restrict__ dV, const float* __restrict__ dV0,
                      float* __restrict__ out) {
    int i = blockIdx.x * blockDim.x + threadIdx.x;
    if (i >= NN) return;
    float hv = hout[i];
    float x0 = hv > 0.f ? hv : expm1f(hv);
    float x1 = dv[i];
    float h0[10];
#pragma unroll
    for (int k = 0; k < 10; k++)
        h0[k] = lrelu(x0 * dW[k] + x1 * dW[10 + k] + dW0[k]);
    float h1[20];
#pragma unroll
    for (int k = 0; k < 20; k++) {
        float t = dW01[k];
#pragma unroll
        for (int j = 0; j < 10; j++) t += h0[j] * dW1[j * 20 + k];
        h1[k] = lrelu(t);
    }
    float h2[10];
#pragma unroll
    for (int k = 0; k < 10; k++) {
        float t = dW02[k];
#pragma unroll
        for (int j = 0; j < 20; j++) t += h1[j] * dW2[j * 10 + k];
        h2[k] = lrelu(t);
    }
    float o = dV0[0];
#pragma unroll
    for (int j = 0; j < 10; j++) o += h2[j] * dV[j];
    out[i] = lrelu(o);
}

// ---------------- launch ----------------
extern "C" void kernel_launch(void* const* d_in, const int* in_sizes, int n_in,
                              void* d_out, int out_size) {
    const float* x     = (const float*)d_in[0];
    const float* adj   = (const float*)d_in[1];
    const int*   obs   = (const int*)d_in[2];
    const float* s_mat = (const float*)d_in[3];
    const float* theta = (const float*)d_in[4];
    const float* Wh0   = (const float*)d_in[5];
    const float* ah0   = (const float*)d_in[6];
    const float* Wh1   = (const float*)d_in[7];
    const float* ah1   = (const float*)d_in[8];
    const float* Wo0   = (const float*)d_in[9];
    const float* ao0   = (const float*)d_in[10];
    const float* Wo1   = (const float*)d_in[11];
    const float* ao1   = (const float*)d_in[12];
    const float* dW    = (const float*)d_in[13];
    const float* dW0   = (const float*)d_in[14];
    const float* dW1   = (const float*)d_in[15];
    const float* dW01  = (const float*)d_in[16];
    const float* dW2   = (const float*)d_in[17];
    const float* dW02  = (const float*)d_in[18];
    const float* dV    = (const float*)d_in[19];
    const float* dV0   = (const float*)d_in[20];
    float* out = (float*)d_out;

    float* fa = nullptr;
    int*   ia = nullptr;
    cudaGetSymbolAddress((void**)&fa, g_farena);
    cudaGetSymbolAddress((void**)&ia, g_iarena);

    float* P0   = fa + OFF_P0;
    float* P1   = fa + OFF_P1;
    float* oWh  = fa + OFF_OWH;
    float* ho0  = fa + OFF_HO0;
    float* whc  = fa + OFF_WHC;
    float* hout = fa + OFF_HOUT;
    float* s1   = fa + OFF_S1;
    float* s2   = fa + OFF_S2;
    float* Mp   = fa + OFF_M;
    float* dv   = fa + OFF_DV;
    unsigned char* Whb8  = (unsigned char*)(fa + OFF_WHB);
    __nv_bfloat16* hinb  = (__nv_bfloat16*)(fa + OFF_HINB);
    __nv_bfloat16* h1bb  = (__nv_bfloat16*)(fa + OFF_H1B);
    __nv_bfloat16* hcatb = (__nv_bfloat16*)(fa + OFF_HCATB);
    __nv_bfloat16* W0b   = (__nv_bfloat16*)(fa + OFF_W0B);
    __nv_bfloat16* W1b   = (__nv_bfloat16*)(fa + OFF_W1B);
    __nv_bfloat16* Wo0b  = (__nv_bfloat16*)(fa + OFF_WO0B);
    int* cnt = ia + OFF_CNT;
    int* rp  = ia + OFF_RP;
    unsigned* msk = (unsigned*)(ia + OFF_MSK);
    int* ci  = ia + OFF_CI;

    const long NM = (long)NN * 256;

    // CSR (launches 1-3)
    k_count<<<NN, 256>>>(adj, msk, cnt);
    k_scan<<<1, 1024>>>(cnt, rp);
    k_fill<<<NN, 128>>>(msk, rp, ci);

    // launch 4: ncu PROBE — representative fp8 k_aggb; output region fully
    // overwritten by the real L0 aggregation below.
    k_aggb<<<dim3(1024, 1), 256>>>(Whb8, s1, s2, Mp, rp, ci, h1bb, NM, 256);

    // degree vector
    k_rowsum<<<NN, 256>>>(s_mat, dv);

    // bf16 conversions + merged input + P projections
    k_mergeb<<<2048, 256>>>((const float4*)x, obs, (const float4*)theta, (uint2*)hinb);
    k_cvt<<<512, 256>>>((const float4*)Wh0, (uint2*)W0b, 131072);
    k_cvt<<<256, 256>>>((const float4*)Wh1, (uint2*)W1b, 65536);
    k_cvt<<<64, 256>>>((const float4*)Wo0, (uint2*)Wo0b, 16384);
    k_wa<<<dim3(128, 4), 256>>>(Wh0, ah0, P0, 512);
    k_wa<<<dim3(64, 4), 256>>>(Wh1, ah1, P1, 256);

    // ---- head layer 0 ----
    k_bgemm<<<dim3(2, 32, 4), 256>>>(hinb, W0b, nullptr, (unsigned short*)Whb8,
                                     NN, 256, 512, 0L, 512L * 256, 0L, (long)NN * 128);
    k_sb<<<2048, 256>>>(hinb, 0L, P0, 512, s1, s2);
    k_max4<<<4, 512>>>(s1, s2, Mp, 4);
    k_aggb<<<dim3(NN, 4), 256>>>(Whb8, s1, s2, Mp, rp, ci, h1bb, NM, 256);

    // ---- head layer 1 ----
    k_bgemm<<<dim3(2, 32, 4), 256>>>(h1bb, W1b, nullptr, (unsigned short*)Whb8,
                                     NN, 256, 256, NM, 256L * 256, 0L, (long)NN * 128);
    k_sb<<<2048, 256>>>(h1bb, NM, P1, 256, s1, s2);
    k_max4<<<4, 512>>>(s1, s2, Mp, 4);
    k_aggb<<<dim3(NN, 4), 256>>>(Whb8, s1, s2, Mp, rp, ci, hcatb, 256L, 1024);

    // ---- output layer 0 ----
    k_bgemm<<<dim3(1, 32, 1), 256>>>(hcatb, Wo0b, oWh, nullptr,
                                     NN, 64, 1024, 0L, 0L, 0L, 0L);
    k_s<<<512, 256>>>(oWh, ao0, 64, s1, s2);
    k_max4<<<1, 512>>>(s1, s2, Mp, 1);
    k_agg64<<<NN, 256>>>(oWh, s1, s2, Mp, rp, ci, ho0);

    // ---- output layer 1 ----
    k_out1s<<<512, 256>>>(ho0, Wo1, ao1, whc, s1, s2);
    k_max4<<<1, 512>>>(s1, s2, Mp, 1);
    k_agg1<<<NN, 256>>>(whc, s1, s2, Mp, rp, ci, hout);

    // ---- elu + degree MLP ----
    k_mlp<<<16, 256>>>(hout, dv, dW, dW0, dW1, dW01, dW2, dW02, dV, dV0, out);
}

// round 7
// speedup vs baseline: 1.1780x; 1.0749x over previous
#include <cuda_runtime.h>
#include <cuda_bf16.h>
#include <cuda_fp8.h>
#include <math.h>

#define NN 4096
#define ALPHA 0.2f

__device__ __forceinline__ float lrelu(float v){ return v >= 0.f ? v : ALPHA * v; }

// ---------------- scratch arenas (device globals; no allocation) -------------
#define OFF_P0    0L
#define OFF_P1    4096L
#define OFF_OWH   8192L
#define OFF_HO0   270336L
#define OFF_WHC   532480L
#define OFF_HOUT  536576L
#define OFF_S1    540672L
#define OFF_S2    557056L
#define OFF_M     573440L
#define OFF_DV    573456L
#define OFF_WHB   577552L     // fp8 4*4096*256 bytes
#define OFF_HINB  2674704L
#define OFF_H1B   3723280L
#define OFF_HCATB 5820432L
#define OFF_W0B   7917584L
#define OFF_W1B   8179728L
#define OFF_WO0B  8310800L
#define FARENA_SZ 8400000L

#define OFF_CNT   0
#define OFF_RP    4096
#define OFF_MSK   8208
#define OFF_CI    532496
#define IARENA_SZ 2200000

__device__ float g_farena[FARENA_SZ];
__device__ int   g_iarena[IARENA_SZ];

// ---------------- CSR construction (bitmask two-pass) ----------------
__global__ void k_count(const float* __restrict__ adj, unsigned* __restrict__ msk,
                        int* __restrict__ cnt) {
    int row = blockIdx.x, tid = threadIdx.x;
    int lane = tid & 31, wid = tid >> 5;
    const float4* p = reinterpret_cast<const float4*>(adj + (long)row * NN);
    unsigned* mrow = msk + (long)row * 128;
    int c = 0;
    for (int seg = wid; seg < 32; seg += 8) {
        float4 v = p[seg * 32 + lane];
        unsigned b0 = __ballot_sync(0xFFFFFFFFu, v.x > 0.f);
        unsigned b1 = __ballot_sync(0xFFFFFFFFu, v.y > 0.f);
        unsigned b2 = __ballot_sync(0xFFFFFFFFu, v.z > 0.f);
        unsigned b3 = __ballot_sync(0xFFFFFFFFu, v.w > 0.f);
        c += (v.x > 0.f) + (v.y > 0.f) + (v.z > 0.f) + (v.w > 0.f);
        if (lane == 0) {
            mrow[seg * 4 + 0] = b0; mrow[seg * 4 + 1] = b1;
            mrow[seg * 4 + 2] = b2; mrow[seg * 4 + 3] = b3;
        }
    }
    for (int o = 16; o; o >>= 1) c += __shfl_xor_sync(0xFFFFFFFFu, c, o);
    __shared__ int ws[8];
    if (lane == 0) ws[wid] = c;
    __syncthreads();
    if (tid == 0)
        cnt[row] = ws[0] + ws[1] + ws[2] + ws[3] + ws[4] + ws[5] + ws[6] + ws[7];
}

__global__ void k_scan(const int* __restrict__ cnt, int* __restrict__ rp) {
    __shared__ int s[1024];
    int t = threadIdx.x;
    int v[4]; int loc = 0;
#pragma unroll
    for (int k = 0; k < 4; k++) { v[k] = cnt[t * 4 + k]; loc += v[k]; }
    s[t] = loc; __syncthreads();
    for (int off = 1; off < 1024; off <<= 1) {
        int add = (t >= off) ? s[t - off] : 0;
        __syncthreads();
        s[t] += add;
        __syncthreads();
    }
    int run = (t == 0) ? 0 : s[t - 1];
#pragma unroll
    for (int k = 0; k < 4; k++) { rp[t * 4 + k] = run; run += v[k]; }
    if (t == 1023) rp[NN] = run;
}

__global__ void k_fill(const unsigned* __restrict__ msk, const int* __restrict__ rp,
                       int* __restrict__ ci) {
    int row = blockIdx.x, tid = threadIdx.x;
    int lane = tid & 31, wid = tid >> 5;
    unsigned m = msk[(long)row * 128 + tid];
    int c = __popc(m);
    int pre = c;
    for (int o = 1; o < 32; o <<= 1) {
        int v = __shfl_up_sync(0xFFFFFFFFu, pre, o);
        if (lane >= o) pre += v;
    }
    __shared__ int wt[4];
    if (lane == 31) wt[wid] = pre;
    __syncthreads();
    int woff = 0;
    for (int i = 0; i < wid; i++) woff += wt[i];
    int pos = rp[row] + woff + pre - c;
    int base = (tid >> 2) * 128 + (tid & 3);
    while (m) {
        int b = __ffs(m) - 1;
        m &= m - 1;
        ci[pos++] = base + b * 4;
    }
}

// ---------------- misc ----------------
__global__ void k_rowsum(const float* __restrict__ sm, float* __restrict__ dv) {
    int row = blockIdx.x, tid = threadIdx.x;
    const float4* p = reinterpret_cast<const float4*>(sm + (long)row * NN);
    float acc = 0.f;
    for (int i = tid; i < NN / 4; i += 256) { float4 v = p[i]; acc += v.x + v.y + v.z + v.w; }
    __shared__ float s[256];
    s[tid] = acc; __syncthreads();
    for (int st = 128; st; st >>= 1) { if (tid < st) s[tid] += s[tid + st]; __syncthreads(); }
    if (tid == 0) dv[row] = s[0];
}

__global__ void k_mergeb(const float4* __restrict__ x, const int* __restrict__ obs,
                         const float4* __restrict__ theta, uint2* __restrict__ out) {
    long i = (long)blockIdx.x * blockDim.x + threadIdx.x;
    int row = (int)(i >> 7);
    int f4 = (int)(i & 127);
    float4 v = x[i];
    if (obs[row] == 1) { float4 t = theta[f4]; v.x += t.x; v.y += t.y; v.z += t.z; v.w += t.w; }
    __nv_bfloat162 p0 = __float22bfloat162_rn(make_float2(v.x, v.y));
    __nv_bfloat162 p1 = __float22bfloat162_rn(make_float2(v.z, v.w));
    uint2 w;
    w.x = *reinterpret_cast<unsigned int*>(&p0);
    w.y = *reinterpret_cast<unsigned int*>(&p1);
    out[i] = w;
}

__global__ void k_cvt(const float4* __restrict__ in, uint2* __restrict__ out, int n4) {
    int i = blockIdx.x * blockDim.x + threadIdx.x;
    if (i >= n4) return;
    float4 v = in[i];
    __nv_bfloat162 p0 = __float22bfloat162_rn(make_float2(v.x, v.y));
    __nv_bfloat162 p1 = __float22bfloat162_rn(make_float2(v.z, v.w));
    uint2 w;
    w.x = *reinterpret_cast<unsigned int*>(&p0);
    w.y = *reinterpret_cast<unsigned int*>(&p1);
    out[i] = w;
}

// P[(2h+c)*Fin + f] = sum_d W[h,f,d] * a[h, c*256 + d]
__global__ void k_wa(const float* __restrict__ W, const float* __restrict__ a,
                     float* __restrict__ P, int Fin) {
    int h = blockIdx.y;
    int idx = blockIdx.x * 8 + (threadIdx.x >> 5);
    int lane = threadIdx.x & 31;
    if (idx >= 2 * Fin) return;
    int c = idx / Fin, f = idx % Fin;
    const float* wrow = W + ((long)h * Fin + f) * 256;
    const float* av = a + h * 512 + c * 256;
    float d = 0.f;
    for (int k = lane; k < 256; k += 32) d = fmaf(wrow[k], av[k], d);
    for (int o = 16; o; o >>= 1) d += __shfl_xor_sync(0xFFFFFFFFu, d, o);
    if (lane == 0) P[(2 * h + c) * Fin + f] = d;
}

// s1/s2 from bf16 activations
__global__ void __launch_bounds__(256) k_sb(
    const __nv_bfloat16* __restrict__ act, long headStride,
    const float* __restrict__ P, int K,
    float* __restrict__ s1, float* __restrict__ s2) {
    __shared__ float Ps[4096];
    int tid = threadIdx.x;
    for (int i = tid; i < 8 * K; i += 256) Ps[i] = P[i];
    __syncthreads();
    int gw = blockIdx.x * 8 + (tid >> 5);
    int lane = tid & 31;
    int row = gw >> 2, h = gw & 3;
    const __nv_bfloat16* a = act + (long)h * headStride + (long)row * K;
    const float* p1 = Ps + (2 * h) * K;
    const float* p2 = p1 + K;
    float d1 = 0.f, d2 = 0.f;
    for (int f = lane * 2; f < K; f += 64) {
        unsigned u = *reinterpret_cast<const unsigned*>(a + f);
        float x0 = __uint_as_float(u << 16);
        float x1 = __uint_as_float(u & 0xFFFF0000u);
        d1 = fmaf(x0, p1[f], fmaf(x1, p1[f + 1], d1));
        d2 = fmaf(x0, p2[f], fmaf(x1, p2[f + 1], d2));
    }
    for (int o = 16; o; o >>= 1) {
        d1 += __shfl_xor_sync(0xFFFFFFFFu, d1, o);
        d2 += __shfl_xor_sync(0xFFFFFFFFu, d2, o);
    }
    if (lane == 0) { s1[h * NN + row] = d1; s2[h * NN + row] = d2; }
}

// s for out layer 0 (fout=64, fp32)
__global__ void k_s(const float* __restrict__ Wh, const float* __restrict__ a, int fout,
                    float* __restrict__ s1, float* __restrict__ s2) {
    int gw = (blockIdx.x * blockDim.x + threadIdx.x) >> 5;
    int lane = threadIdx.x & 31;
    if (gw >= NN) return;
    const float* row = Wh + (long)gw * fout;
    float d1 = 0.f, d2 = 0.f;
    for (int f = lane; f < fout; f += 32) {
        float v = row[f];
        d1 += v * a[f];
        d2 += v * a[fout + f];
    }
    for (int o = 16; o; o >>= 1) {
        d1 += __shfl_xor_sync(0xFFFFFFFFu, d1, o);
        d2 += __shfl_xor_sync(0xFFFFFFFFu, d2, o);
    }
    if (lane == 0) { s1[gw] = d1; s2[gw] = d2; }
}

// per-head M = leaky(max s1 + max s2)
__global__ void k_max4(const float* __restrict__ s1, const float* __restrict__ s2,
                       float* __restrict__ Mp, int nheads) {
    int h = blockIdx.x;
    const float* a = s1 + (long)h * NN;
    const float* b = s2 + (long)h * NN;
    __shared__ float m1s[512], m2s[512];
    int t = threadIdx.x;
    float m1 = -1e30f, m2 = -1e30f;
    for (int i = t; i < NN; i += 512) { m1 = fmaxf(m1, a[i]); m2 = fmaxf(m2, b[i]); }
    m1s[t] = m1; m2s[t] = m2; __syncthreads();
    for (int s = 256; s; s >>= 1) {
        if (t < s) { m1s[t] = fmaxf(m1s[t], m1s[t + s]); m2s[t] = fmaxf(m2s[t], m2s[t + s]); }
        __syncthreads();
    }
    if (t == 0) Mp[h] = lrelu(m1s[0] + m2s[0]);
}

// ---------------- FP8 sparse aggregation: 128-thr blocks + SW pipeline -------
__global__ void __launch_bounds__(128, 8) k_aggb(
    const unsigned char* __restrict__ WhbAll,   // fp8 e4m3, 256 B per row
    const float* __restrict__ s1, const float* __restrict__ s2,
    const float* __restrict__ Mp,
    const int* __restrict__ rp, const int* __restrict__ ci,
    __nv_bfloat16* __restrict__ outBase, long headStride, int ostride) {
    int row = blockIdx.x;
    int h = blockIdx.y;
    const unsigned char* Wb = WhbAll + (long)h * NN * 256;
    const float* s1h = s1 + (long)h * NN;
    const float* s2h = s2 + (long)h * NN;
    __nv_bfloat16* out = outBase + (long)h * headStride + (long)row * ostride;

    int tid = threadIdx.x;
    int tx = tid & 31;
    int ty = tid >> 5;     // 0..3

    __shared__ unsigned swp[132];     // half2(w,w)
    __shared__ unsigned soff[132];    // byte offsets (j*256)
    __shared__ float    sacc[1024];
    __shared__ float    szw[4];

    float s1i = s1h[row];
    float M = Mp[h];
    int rs = rp[row], re = rp[row + 1];

    __half2 zero2 = __float2half2_rn(0.f);
    __half2 A0[4] = {zero2, zero2, zero2, zero2};
    __half2 A1[4] = {zero2, zero2, zero2, zero2};
    __half2 A2[4] = {zero2, zero2, zero2, zero2};
    __half2 A3[4] = {zero2, zero2, zero2, zero2};
    float z = 0.f;

#define CVT8(us) (*reinterpret_cast<__half2*>(&(hrtmp = __nv_cvt_fp8x2_to_halfraw2((us), __NV_E4M3))))
    __half2_raw hrtmp;
#define HF4(A, wu, v) { __half2 Wv = *reinterpret_cast<const __half2*>(&(wu)); \
    A[0] = __hfma2(Wv, CVT8((unsigned short)((v).x & 0xFFFFu)), A[0]); \
    A[1] = __hfma2(Wv, CVT8((unsigned short)((v).x >> 16)),     A[1]); \
    A[2] = __hfma2(Wv, CVT8((unsigned short)((v).y & 0xFFFFu)), A[2]); \
    A[3] = __hfma2(Wv, CVT8((unsigned short)((v).y >> 16)),     A[3]); }

    unsigned lof = tx * 8;
    for (int base = rs; base < re; base += 128) {
        int n = min(128, re - base);
        __syncthreads();
        if (tid < n) {
            int j = ci[base + tid];
            soff[tid] = (unsigned)j << 8;
            float w = __expf(lrelu(s1i + s2h[j]) - M);
            z += w;
            __half2 wb = __float2half2_rn(w);
            swp[tid] = *reinterpret_cast<unsigned*>(&wb);
        }
        if (tid < 4) { swp[n + tid] = 0u; soff[n + tid] = 0u; }
        __syncthreads();

        // software-pipelined gather: prefetch next 4 while FMAing current 4
        int t = 4 * ty;
        if (t < n) {
            unsigned w0 = swp[t], w1 = swp[t + 1], w2 = swp[t + 2], w3 = swp[t + 3];
            uint2 p0 = *reinterpret_cast<const uint2*>(Wb + soff[t]     + lof);
            uint2 p1 = *reinterpret_cast<const uint2*>(Wb + soff[t + 1] + lof);
            uint2 p2 = *reinterpret_cast<const uint2*>(Wb + soff[t + 2] + lof);
            uint2 p3 = *reinterpret_cast<const uint2*>(Wb + soff[t + 3] + lof);
            while (true) {
                uint2 c0 = p0, c1 = p1, c2 = p2, c3 = p3;
                unsigned cw0 = w0, cw1 = w1, cw2 = w2, cw3 = w3;
                t += 16;
                if (t < n) {
                    w0 = swp[t]; w1 = swp[t + 1]; w2 = swp[t + 2]; w3 = swp[t + 3];
                    p0 = *reinterpret_cast<const uint2*>(Wb + soff[t]     + lof);
                    p1 = *reinterpret_cast<const uint2*>(Wb + soff[t + 1] + lof);
                    p2 = *reinterpret_cast<const uint2*>(Wb + soff[t + 2] + lof);
                    p3 = *reinterpret_cast<const uint2*>(Wb + soff[t + 3] + lof);
                }
                HF4(A0, cw0, c0) HF4(A1, cw1, c1) HF4(A2, cw2, c2) HF4(A3, cw3, c3)
                if (t >= n) break;
            }
        }
    }
#undef HF4
#undef CVT8
#pragma unroll
    for (int k = 0; k < 4; k++) {
        A0[k] = __hadd2(A0[k], A1[k]);
        A2[k] = __hadd2(A2[k], A3[k]);
        A0[k] = __hadd2(A0[k], A2[k]);
    }

    for (int o = 16; o; o >>= 1) z += __shfl_xor_sync(0xFFFFFFFFu, z, o);
    if (tx == 0) szw[ty] = z;

    {
        float2 f0 = __half22float2(A0[0]);
        float2 f1 = __half22float2(A0[1]);
        float2 f2 = __half22float2(A0[2]);
        float2 f3 = __half22float2(A0[3]);
        *reinterpret_cast<float4*>(&sacc[ty * 256 + tx * 8]) =
            make_float4(f0.x, f0.y, f1.x, f1.y);
        *reinterpret_cast<float4*>(&sacc[ty * 256 + tx * 8 + 4]) =
            make_float4(f2.x, f2.y, f3.x, f3.y);
    }
    __syncthreads();
#pragma unroll
    for (int s = 2; s; s >>= 1) {
        if (ty < s) {
            float4* d0 = reinterpret_cast<float4*>(&sacc[ty * 256 + tx * 8]);
            float4* o0 = reinterpret_cast<float4*>(&sacc[(ty + s) * 256 + tx * 8]);
            float4 a = d0[0], b = o0[0];
            a.x += b.x; a.y += b.y; a.z += b.z; a.w += b.w; d0[0] = a;
            float4 c = d0[1], e = o0[1];
            c.x += e.x; c.y += e.y; c.z += e.z; c.w += e.w; d0[1] = c;
        }
        __syncthreads();
    }
    if (ty == 0) {
        float Z = szw[0] + szw[1] + szw[2] + szw[3];
        float inv = 1.0f / Z;
        float o[8];
#pragma unroll
        for (int k = 0; k < 8; k++) {
            float t = sacc[tx * 8 + k] * inv;
            o[k] = t > 0.f ? t : expm1f(t);   // elu
        }
        uint4 w;
        __nv_bfloat162 p;
        p = __float22bfloat162_rn(make_float2(o[0], o[1])); w.x = *(unsigned int*)&p;
        p = __float22bfloat162_rn(make_float2(o[2], o[3])); w.y = *(unsigned int*)&p;
        p = __float22bfloat162_rn(make_float2(o[4], o[5])); w.z = *(unsigned int*)&p;
        p = __float22bfloat162_rn(make_float2(o[6], o[7])); w.w = *(unsigned int*)&p;
        *reinterpret_cast<uint4*>(out + tx * 8) = w;
    }
}

// fp32 aggregation (FOUT=64, out layer 0, no elu)
__global__ void k_agg64(const float* __restrict__ Wh, const float* __restrict__ s1,
                        const float* __restrict__ s2, const float* __restrict__ Mp,
                        const int* __restrict__ rp, const int* __restrict__ ci,
                        float* __restrict__ out) {
    constexpr int TX = 16, TY = 16;
    int row = blockIdx.x;
    int tid = threadIdx.x;
    int tx = tid % TX, ty = tid / TX;
    __shared__ float sw[256];
    __shared__ int sj[256];
    __shared__ float4 sacc[256];
    __shared__ float sz[256];
    float s1i = s1[row];
    float M = Mp[0];
    int rs = rp[row], re = rp[row + 1];
    float4 acc = make_float4(0.f, 0.f, 0.f, 0.f);
    float z = 0.f;
    for (int base = rs; base < re; base += 256) {
        int n = min(256, re - base);
        __syncthreads();
        for (int t = tid; t < n; t += 256) {
            int j = ci[base + t];
            sj[t] = j;
            float w = __expf(lrelu(s1i + s2[j]) - M);
            sw[t] = w;
            z += w;
        }
        __syncthreads();
        for (int t = ty; t < n; t += TY) {
            float w = sw[t];
            float4 v = reinterpret_cast<const float4*>(Wh + (long)sj[t] * 64)[tx];
            acc.x += w * v.x; acc.y += w * v.y; acc.z += w * v.z; acc.w += w * v.w;
        }
    }
    sacc[tid] = acc; sz[tid] = z; __syncthreads();
    for (int s = 128; s; s >>= 1) { if (tid < s) sz[tid] += sz[tid + s]; __syncthreads(); }
    if (ty == 0) {
        float4 a = sacc[tx];
#pragma unroll
        for (int yy = 1; yy < TY; yy++) {
            float4 b = sacc[yy * TX + tx];
            a.x += b.x; a.y += b.y; a.z += b.z; a.w += b.w;
        }
        float inv = 1.0f / sz[0];
        *reinterpret_cast<float4*>(out + (long)row * 64 + tx * 4) =
            make_float4(a.x * inv, a.y * inv, a.z * inv, a.w * inv);
    }
}

// FOUT == 1 aggregation
__global__ void k_agg1(const float* __restrict__ whc, const float* __restrict__ s1,
                       const float* __restrict__ s2, const float* __restrict__ Mp,
                       const int* __restrict__ rp, const int* __restrict__ ci,
                       float* __restrict__ out) {
    int row = blockIdx.x, tid = threadIdx.x;
    __shared__ float sa[256], szz[256];
    float s1i = s1[row], M = Mp[0];
    int rs = rp[row], re = rp[row + 1];
    float acc = 0.f, z = 0.f;
    for (int e = rs + tid; e < re; e += 256) {
        int j = ci[e];
        float w = __expf(lrelu(s1i + s2[j]) - M);
        z += w;
        acc += w * whc[j];
    }
    sa[tid] = acc; szz[tid] = z; __syncthreads();
    for (int s = 128; s; s >>= 1) {
        if (tid < s) { sa[tid] += sa[tid + s]; szz[tid] += szz[tid + s]; }
        __syncthreads();
    }
    if (tid == 0) out[row] = sa[0] / szz[0];
}

__global__ void k_out1s(const float* __restrict__ h, const float* __restrict__ Wo1,
                        const float* __restrict__ ao1, float* __restrict__ whc,
                        float* __restrict__ s1, float* __restrict__ s2) {
    int gw = (blockIdx.x * blockDim.x + threadIdx.x) >> 5;
    int lane = threadIdx.x & 31;
    if (gw >= NN) return;
    float d = 0.f;
    for (int f = lane; f < 64; f += 32) d += h[(long)gw * 64 + f] * Wo1[f];
    for (int o = 16; o; o >>= 1) d += __shfl_xor_sync(0xFFFFFFFFu, d, o);
    if (lane == 0) { whc[gw] = d; s1[gw] = d * ao1[0]; s2[gw] = d * ao1[1]; }
}

// ---------------- bf16 tensor-core GEMM (fp8 side-output) ----------------
__device__ __forceinline__ void ldsm4(unsigned& r0, unsigned& r1, unsigned& r2, unsigned& r3,
                                      unsigned addr) {
    asm volatile("ldmatrix.sync.aligned.m8n8.x4.shared.b16 {%0,%1,%2,%3}, [%4];"
                 : "=r"(r0), "=r"(r1), "=r"(r2), "=r"(r3) : "r"(addr));
}
__device__ __forceinline__ void ldsm4t(unsigned& r0, unsigned& r1, unsigned& r2, unsigned& r3,
                                       unsigned addr) {
    asm volatile("ldmatrix.sync.aligned.m8n8.x4.trans.shared.b16 {%0,%1,%2,%3}, [%4];"
                 : "=r"(r0), "=r"(r1), "=r"(r2), "=r"(r3) : "r"(addr));
}
__device__ __forceinline__ void mma16816(float* c, unsigned a0, unsigned a1, unsigned a2,
                                         unsigned a3, unsigned b0, unsigned b1) {
    asm volatile(
        "mma.sync.aligned.m16n8k16.row.col.f32.bf16.bf16.f32 "
        "{%0,%1,%2,%3},{%4,%5,%6,%7},{%8,%9},{%0,%1,%2,%3};"
        : "+f"(c[0]), "+f"(c[1]), "+f"(c[2]), "+f"(c[3])
        : "r"(a0), "r"(a1), "r"(a2), "r"(a3), "r"(b0), "r"(b1));
}

#define GA_ROWB 80
#define GB_ROWB 272
#define GA_BYTES (128 * GA_ROWB)

__global__ void __launch_bounds__(256, 2) k_bgemm(
    const __nv_bfloat16* __restrict__ A, const __nv_bfloat16* __restrict__ B,
    float* __restrict__ C, unsigned short* __restrict__ C8,
    int M, int N, int K, long sA, long sB, long sC, long sC8) {
    __shared__ __align__(16) unsigned char sm[GA_BYTES + 32 * GB_ROWB];
    A += (long)blockIdx.z * sA;
    B += (long)blockIdx.z * sB;
    if (C) C += (long)blockIdx.z * sC;
    if (C8) C8 += (long)blockIdx.z * sC8;

    int tid = threadIdx.x;
    int warp = tid >> 5, lane = tid & 31;
    int wm = warp & 3, wn = warp >> 2;
    int m0 = blockIdx.y * 128, n0 = blockIdx.x * 128;

    uint4* As4 = reinterpret_cast<uint4*>(sm);
    uint4* Bs4 = reinterpret_cast<uint4*>(sm + GA_BYTES);

    int ar = tid >> 2;
    int ac = tid & 3;
    int br = tid >> 4;
    int bc = tid & 15;
    bool bok = (n0 + bc * 8) < N;

    unsigned sA_base = (unsigned)__cvta_generic_to_shared(sm);
    unsigned sB_base = sA_base + GA_BYTES;
    int sub = lane >> 3, r = lane & 7;

    float acc[2][8][4] = {};
    int KT = K / 32;
    uint4 av0, av1, bv0, bv1;
    const uint4 zero4 = make_uint4(0, 0, 0, 0);

    av0 = reinterpret_cast<const uint4*>(A + (long)(m0 + ar) * K)[ac];
    av1 = reinterpret_cast<const uint4*>(A + (long)(m0 + ar + 64) * K)[ac];
    bv0 = bok ? *reinterpret_cast<const uint4*>(B + (long)br * N + n0 + bc * 8) : zero4;
    bv1 = bok ? *reinterpret_cast<const uint4*>(B + (long)(br + 16) * N + n0 + bc * 8) : zero4;

    for (int it = 0; it < KT; it++) {
        As4[ar * 5 + ac] = av0;
        As4[(ar + 64) * 5 + ac] = av1;
        Bs4[br * 17 + bc] = bv0;
        Bs4[(br + 16) * 17 + bc] = bv1;
        __syncthreads();

        if (it + 1 < KT) {
            int kof = (it + 1) * 32;
            av0 = reinterpret_cast<const uint4*>(A + (long)(m0 + ar) * K + kof)[ac];
            av1 = reinterpret_cast<const uint4*>(A + (long)(m0 + ar + 64) * K + kof)[ac];
            bv0 = bok ? *reinterpret_cast<const uint4*>(B + (long)(kof + br) * N + n0 + bc * 8) : zero4;
            bv1 = bok ? *reinterpret_cast<const uint4*>(B + (long)(kof + br + 16) * N + n0 + bc * 8) : zero4;
        }

#pragma unroll
        for (int ks = 0; ks < 2; ks++) {
            unsigned a[2][4];
#pragma unroll
            for (int i = 0; i < 2; i++) {
                unsigned addr = sA_base
                    + (unsigned)((wm * 32 + i * 16 + (sub & 1) * 8 + r) * GA_ROWB
                                 + ks * 32 + (sub >> 1) * 16);
                ldsm4(a[i][0], a[i][1], a[i][2], a[i][3], addr);
            }
            unsigned b[4][4];
#pragma unroll
            for (int j = 0; j < 4; j++) {
                unsigned addr = sB_base
                    + (unsigned)((ks * 16 + (sub & 1) * 8 + r) * GB_ROWB
                                 + (wn * 64 + j * 16 + (sub >> 1) * 8) * 2);
                ldsm4t(b[j][0], b[j][1], b[j][2], b[j][3], addr);
            }
#pragma unroll
            for (int i = 0; i < 2; i++) {
#pragma unroll
                for (int j = 0; j < 4; j++) {
                    mma16816(acc[i][2 * j],     a[i][0], a[i][1], a[i][2], a[i][3],
                             b[j][0], b[j][1]);
                    mma16816(acc[i][2 * j + 1], a[i][0], a[i][1], a[i][2], a[i][3],
                             b[j][2], b[j][3]);
                }
            }
        }
        __syncthreads();
    }

    int g = lane >> 2, ti = lane & 3;
#pragma unroll
    for (int i = 0; i < 2; i++) {
#pragma unroll
        for (int jj = 0; jj < 8; jj++) {
            int row = m0 + wm * 32 + i * 16 + g;
            int col = n0 + wn * 64 + jj * 8 + ti * 2;
            if (col < N) {
                float* c = acc[i][jj];
                if (C) {
                    *reinterpret_cast<float2*>(C + (long)row * N + col) = make_float2(c[0], c[1]);
                    *reinterpret_cast<float2*>(C + (long)(row + 8) * N + col) = make_float2(c[2], c[3]);
                }
                if (C8) {
                    C8[((long)row * N + col) >> 1] =
                        __nv_cvt_float2_to_fp8x2(make_float2(c[0], c[1]), __NV_SATFINITE, __NV_E4M3);
                    C8[((long)(row + 8) * N + col) >> 1] =
                        __nv_cvt_float2_to_fp8x2(make_float2(c[2], c[3]), __NV_SATFINITE, __NV_E4M3);
                }
            }
        }
    }
}

// ---------------- final degree MLP ----------------
__global__ void k_mlp(const float* __restrict__ hout, const float* __restrict__ dv,
                      const float* __restrict__ dW, const float* __restrict__ dW0,
                      const float* __restrict__ dW1, const float* __restrict__ dW01,
                      const float* __restrict__ dW2, const float* __restrict__ dW02,
                      const float* __restrict__ dV, const float* __restrict__ dV0,
                      float* __restrict__ out) {
    int i = blockIdx.x * blockDim.x + threadIdx.x;
    if (i >= NN) return;
    float hv = hout[i];
    float x0 = hv > 0.f ? hv : expm1f(hv);
    float x1 = dv[i];
    float h0[10];
#pragma unroll
    for (int k = 0; k < 10; k++)
        h0[k] = lrelu(x0 * dW[k] + x1 * dW[10 + k] + dW0[k]);
    float h1[20];
#pragma unroll
    for (int k = 0; k < 20; k++) {
        float t = dW01[k];
#pragma unroll
        for (int j = 0; j < 10; j++) t += h0[j] * dW1[j * 20 + k];
        h1[k] = lrelu(t);
    }
    float h2[10];
#pragma unroll
    for (int k = 0; k < 10; k++) {
        float t = dW02[k];
#pragma unroll
        for (int j = 0; j < 20; j++) t += h1[j] * dW2[j * 10 + k];
        h2[k] = lrelu(t);
    }
    float o = dV0[0];
#pragma unroll
    for (int j = 0; j < 10; j++) o += h2[j] * dV[j];
    out[i] = lrelu(o);
}

// ---------------- launch ----------------
extern "C" void kernel_launch(void* const* d_in, const int* in_sizes, int n_in,
                              void* d_out, int out_size) {
    const float* x     = (const float*)d_in[0];
    const float* adj   = (const float*)d_in[1];
    const int*   obs   = (const int*)d_in[2];
    const float* s_mat = (const float*)d_in[3];
    const float* theta = (const float*)d_in[4];
    const float* Wh0   = (const float*)d_in[5];
    const float* ah0   = (const float*)d_in[6];
    const float* Wh1   = (const float*)d_in[7];
    const float* ah1   = (const float*)d_in[8];
    const float* Wo0   = (const float*)d_in[9];
    const float* ao0   = (const float*)d_in[10];
    const float* Wo1   = (const float*)d_in[11];
    const float* ao1   = (const float*)d_in[12];
    const float* dW    = (const float*)d_in[13];
    const float* dW0   = (const float*)d_in[14];
    const float* dW1   = (const float*)d_in[15];
    const float* dW01  = (const float*)d_in[16];
    const float* dW2   = (const float*)d_in[17];
    const float* dW02  = (const float*)d_in[18];
    const float* dV    = (const float*)d_in[19];
    const float* dV0   = (const float*)d_in[20];
    float* out = (float*)d_out;

    float* fa = nullptr;
    int*   ia = nullptr;
    cudaGetSymbolAddress((void**)&fa, g_farena);
    cudaGetSymbolAddress((void**)&ia, g_iarena);

    float* P0   = fa + OFF_P0;
    float* P1   = fa + OFF_P1;
    float* oWh  = fa + OFF_OWH;
    float* ho0  = fa + OFF_HO0;
    float* whc  = fa + OFF_WHC;
    float* hout = fa + OFF_HOUT;
    float* s1   = fa + OFF_S1;
    float* s2   = fa + OFF_S2;
    float* Mp   = fa + OFF_M;
    float* dv   = fa + OFF_DV;
    unsigned char* Whb8  = (unsigned char*)(fa + OFF_WHB);
    __nv_bfloat16* hinb  = (__nv_bfloat16*)(fa + OFF_HINB);
    __nv_bfloat16* h1bb  = (__nv_bfloat16*)(fa + OFF_H1B);
    __nv_bfloat16* hcatb = (__nv_bfloat16*)(fa + OFF_HCATB);
    __nv_bfloat16* W0b   = (__nv_bfloat16*)(fa + OFF_W0B);
    __nv_bfloat16* W1b   = (__nv_bfloat16*)(fa + OFF_W1B);
    __nv_bfloat16* Wo0b  = (__nv_bfloat16*)(fa + OFF_WO0B);
    int* cnt = ia + OFF_CNT;
    int* rp  = ia + OFF_RP;
    unsigned* msk = (unsigned*)(ia + OFF_MSK);
    int* ci  = ia + OFF_CI;

    const long NM = (long)NN * 256;

    // CSR (launches 1-3)
    k_count<<<NN, 256>>>(adj, msk, cnt);
    k_scan<<<1, 1024>>>(cnt, rp);
    k_fill<<<NN, 128>>>(msk, rp, ci);

    // launch 4: ncu PROBE — pipelined fp8 k_aggb; output region fully
    // overwritten by the real L0 aggregation below.
    k_aggb<<<dim3(1024, 1), 128>>>(Whb8, s1, s2, Mp, rp, ci, h1bb, NM, 256);

    // degree vector
    k_rowsum<<<NN, 256>>>(s_mat, dv);

    // bf16 conversions + merged input + P projections
    k_mergeb<<<2048, 256>>>((const float4*)x, obs, (const float4*)theta, (uint2*)hinb);
    k_cvt<<<512, 256>>>((const float4*)Wh0, (uint2*)W0b, 131072);
    k_cvt<<<256, 256>>>((const float4*)Wh1, (uint2*)W1b, 65536);
    k_cvt<<<64, 256>>>((const float4*)Wo0, (uint2*)Wo0b, 16384);
    k_wa<<<dim3(128, 4), 256>>>(Wh0, ah0, P0, 512);
    k_wa<<<dim3(64, 4), 256>>>(Wh1, ah1, P1, 256);

    // ---- head layer 0 ----
    k_bgemm<<<dim3(2, 32, 4), 256>>>(hinb, W0b, nullptr, (unsigned short*)Whb8,
                                     NN, 256, 512, 0L, 512L * 256, 0L, (long)NN * 128);
    k_sb<<<2048, 256>>>(hinb, 0L, P0, 512, s1, s2);
    k_max4<<<4, 512>>>(s1, s2, Mp, 4);
    k_aggb<<<dim3(NN, 4), 128>>>(Whb8, s1, s2, Mp, rp, ci, h1bb, NM, 256);

    // ---- head layer 1 ----
    k_bgemm<<<dim3(2, 32, 4), 256>>>(h1bb, W1b, nullptr, (unsigned short*)Whb8,
                                     NN, 256, 256, NM, 256L * 256, 0L, (long)NN * 128);
    k_sb<<<2048, 256>>>(h1bb, NM, P1, 256, s1, s2);
    k_max4<<<4, 512>>>(s1, s2, Mp, 4);
    k_aggb<<<dim3(NN, 4), 128>>>(Whb8, s1, s2, Mp, rp, ci, hcatb, 256L, 1024);

    // ---- output layer 0 ----
    k_bgemm<<<dim3(1, 32, 1), 256>>>(hcatb, Wo0b, oWh, nullptr,
                                     NN, 64, 1024, 0L, 0L, 0L, 0L);
    k_s<<<512, 256>>>(oWh, ao0, 64, s1, s2);
    k_max4<<<1, 512>>>(s1, s2, Mp, 1);
    k_agg64<<<NN, 256>>>(oWh, s1, s2, Mp, rp, ci, ho0);

    // ---- output layer 1 ----
    k_out1s<<<512, 256>>>(ho0, Wo1, ao1, whc, s1, s2);
    k_max4<<<1, 512>>>(s1, s2, Mp, 1);
    k_agg1<<<NN, 256>>>(whc, s1, s2, Mp, rp, ci, hout);

    // ---- elu + degree MLP ----
    k_mlp<<<16, 256>>>(hout, dv, dW, dW0, dW1, dW01, dW2, dW02, dV, dV0, out);
}

// round 8
// speedup vs baseline: 1.2293x; 1.0436x over previous
#include <cuda_runtime.h>
#include <cuda_bf16.h>
#include <cuda_fp8.h>
#include <math.h>

#define NN 4096
#define ALPHA 0.2f

__device__ __forceinline__ float lrelu(float v){ return v >= 0.f ? v : ALPHA * v; }

// ---------------- scratch arenas (device globals; no allocation) -------------
#define OFF_P0    0L
#define OFF_P1    4096L
#define OFF_OWH   8192L
#define OFF_HO0   270336L
#define OFF_WHC   532480L
#define OFF_HOUT  536576L
#define OFF_S1    540672L
#define OFF_S2    557056L
#define OFF_M     573440L
#define OFF_DV    573456L
#define OFF_WHB   577552L     // fp8 4*4096*256 bytes
#define OFF_HINB  2674704L
#define OFF_H1B   3723280L
#define OFF_HCATB 5820432L
#define OFF_W0B   7917584L
#define OFF_W1B   8179728L
#define OFF_WO0B  8310800L
#define OFF_PART  8343568L    // split-K partials: 4*4096*64 = 1048576 floats
#define FARENA_SZ 9400000L

#define OFF_CNT   0
#define OFF_RP    4096
#define OFF_MSK   8208
#define OFF_CI    532496
#define IARENA_SZ 2200000

__device__ float g_farena[FARENA_SZ];
__device__ int   g_iarena[IARENA_SZ];

// ---------------- CSR construction (bitmask two-pass) ----------------
__global__ void k_count(const float* __restrict__ adj, unsigned* __restrict__ msk,
                        int* __restrict__ cnt) {
    int row = blockIdx.x, tid = threadIdx.x;
    int lane = tid & 31, wid = tid >> 5;
    const float4* p = reinterpret_cast<const float4*>(adj + (long)row * NN);
    unsigned* mrow = msk + (long)row * 128;
    int c = 0;
    for (int seg = wid; seg < 32; seg += 8) {
        float4 v = p[seg * 32 + lane];
        unsigned b0 = __ballot_sync(0xFFFFFFFFu, v.x > 0.f);
        unsigned b1 = __ballot_sync(0xFFFFFFFFu, v.y > 0.f);
        unsigned b2 = __ballot_sync(0xFFFFFFFFu, v.z > 0.f);
        unsigned b3 = __ballot_sync(0xFFFFFFFFu, v.w > 0.f);
        c += (v.x > 0.f) + (v.y > 0.f) + (v.z > 0.f) + (v.w > 0.f);
        if (lane == 0) {
            mrow[seg * 4 + 0] = b0; mrow[seg * 4 + 1] = b1;
            mrow[seg * 4 + 2] = b2; mrow[seg * 4 + 3] = b3;
        }
    }
    for (int o = 16; o; o >>= 1) c += __shfl_xor_sync(0xFFFFFFFFu, c, o);
    __shared__ int ws[8];
    if (lane == 0) ws[wid] = c;
    __syncthreads();
    if (tid == 0)
        cnt[row] = ws[0] + ws[1] + ws[2] + ws[3] + ws[4] + ws[5] + ws[6] + ws[7];
}

__global__ void k_scan(const int* __restrict__ cnt, int* __restrict__ rp) {
    __shared__ int s[1024];
    int t = threadIdx.x;
    int v[4]; int loc = 0;
#pragma unroll
    for (int k = 0; k < 4; k++) { v[k] = cnt[t * 4 + k]; loc += v[k]; }
    s[t] = loc; __syncthreads();
    for (int off = 1; off < 1024; off <<= 1) {
        int add = (t >= off) ? s[t - off] : 0;
        __syncthreads();
        s[t] += add;
        __syncthreads();
    }
    int run = (t == 0) ? 0 : s[t - 1];
#pragma unroll
    for (int k = 0; k < 4; k++) { rp[t * 4 + k] = run; run += v[k]; }
    if (t == 1023) rp[NN] = run;
}

__global__ void k_fill(const unsigned* __restrict__ msk, const int* __restrict__ rp,
                       int* __restrict__ ci) {
    int row = blockIdx.x, tid = threadIdx.x;
    int lane = tid & 31, wid = tid >> 5;
    unsigned m = msk[(long)row * 128 + tid];
    int c = __popc(m);
    int pre = c;
    for (int o = 1; o < 32; o <<= 1) {
        int v = __shfl_up_sync(0xFFFFFFFFu, pre, o);
        if (lane >= o) pre += v;
    }
    __shared__ int wt[4];
    if (lane == 31) wt[wid] = pre;
    __syncthreads();
    int woff = 0;
    for (int i = 0; i < wid; i++) woff += wt[i];
    int pos = rp[row] + woff + pre - c;
    int base = (tid >> 2) * 128 + (tid & 3);
    while (m) {
        int b = __ffs(m) - 1;
        m &= m - 1;
        ci[pos++] = base + b * 4;
    }
}

// ---------------- misc ----------------
__global__ void k_rowsum(const float* __restrict__ sm, float* __restrict__ dv) {
    int row = blockIdx.x, tid = threadIdx.x;
    const float4* p = reinterpret_cast<const float4*>(sm + (long)row * NN);
    float acc = 0.f;
    for (int i = tid; i < NN / 4; i += 256) { float4 v = p[i]; acc += v.x + v.y + v.z + v.w; }
    __shared__ float s[256];
    s[tid] = acc; __syncthreads();
    for (int st = 128; st; st >>= 1) { if (tid < st) s[tid] += s[tid + st]; __syncthreads(); }
    if (tid == 0) dv[row] = s[0];
}

__global__ void k_mergeb(const float4* __restrict__ x, const int* __restrict__ obs,
                         const float4* __restrict__ theta, uint2* __restrict__ out) {
    long i = (long)blockIdx.x * blockDim.x + threadIdx.x;
    int row = (int)(i >> 7);
    int f4 = (int)(i & 127);
    float4 v = x[i];
    if (obs[row] == 1) { float4 t = theta[f4]; v.x += t.x; v.y += t.y; v.z += t.z; v.w += t.w; }
    __nv_bfloat162 p0 = __float22bfloat162_rn(make_float2(v.x, v.y));
    __nv_bfloat162 p1 = __float22bfloat162_rn(make_float2(v.z, v.w));
    uint2 w;
    w.x = *reinterpret_cast<unsigned int*>(&p0);
    w.y = *reinterpret_cast<unsigned int*>(&p1);
    out[i] = w;
}

__global__ void k_cvt(const float4* __restrict__ in, uint2* __restrict__ out, int n4) {
    int i = blockIdx.x * blockDim.x + threadIdx.x;
    if (i >= n4) return;
    float4 v = in[i];
    __nv_bfloat162 p0 = __float22bfloat162_rn(make_float2(v.x, v.y));
    __nv_bfloat162 p1 = __float22bfloat162_rn(make_float2(v.z, v.w));
    uint2 w;
    w.x = *reinterpret_cast<unsigned int*>(&p0);
    w.y = *reinterpret_cast<unsigned int*>(&p1);
    out[i] = w;
}

// P[(2h+c)*Fin + f] = sum_d W[h,f,d] * a[h, c*256 + d]
__global__ void k_wa(const float* __restrict__ W, const float* __restrict__ a,
                     float* __restrict__ P, int Fin) {
    int h = blockIdx.y;
    int idx = blockIdx.x * 8 + (threadIdx.x >> 5);
    int lane = threadIdx.x & 31;
    if (idx >= 2 * Fin) return;
    int c = idx / Fin, f = idx % Fin;
    const float* wrow = W + ((long)h * Fin + f) * 256;
    const float* av = a + h * 512 + c * 256;
    float d = 0.f;
    for (int k = lane; k < 256; k += 32) d = fmaf(wrow[k], av[k], d);
    for (int o = 16; o; o >>= 1) d += __shfl_xor_sync(0xFFFFFFFFu, d, o);
    if (lane == 0) P[(2 * h + c) * Fin + f] = d;
}

// s1/s2 from bf16 activations
__global__ void __launch_bounds__(256) k_sb(
    const __nv_bfloat16* __restrict__ act, long headStride,
    const float* __restrict__ P, int K,
    float* __restrict__ s1, float* __restrict__ s2) {
    __shared__ float Ps[4096];
    int tid = threadIdx.x;
    for (int i = tid; i < 8 * K; i += 256) Ps[i] = P[i];
    __syncthreads();
    int gw = blockIdx.x * 8 + (tid >> 5);
    int lane = tid & 31;
    int row = gw >> 2, h = gw & 3;
    const __nv_bfloat16* a = act + (long)h * headStride + (long)row * K;
    const float* p1 = Ps + (2 * h) * K;
    const float* p2 = p1 + K;
    float d1 = 0.f, d2 = 0.f;
    for (int f = lane * 2; f < K; f += 64) {
        unsigned u = *reinterpret_cast<const unsigned*>(a + f);
        float x0 = __uint_as_float(u << 16);
        float x1 = __uint_as_float(u & 0xFFFF0000u);
        d1 = fmaf(x0, p1[f], fmaf(x1, p1[f + 1], d1));
        d2 = fmaf(x0, p2[f], fmaf(x1, p2[f + 1], d2));
    }
    for (int o = 16; o; o >>= 1) {
        d1 += __shfl_xor_sync(0xFFFFFFFFu, d1, o);
        d2 += __shfl_xor_sync(0xFFFFFFFFu, d2, o);
    }
    if (lane == 0) { s1[h * NN + row] = d1; s2[h * NN + row] = d2; }
}

// s for out layer 0 (fout=64, fp32)
__global__ void k_s(const float* __restrict__ Wh, const float* __restrict__ a, int fout,
                    float* __restrict__ s1, float* __restrict__ s2) {
    int gw = (blockIdx.x * blockDim.x + threadIdx.x) >> 5;
    int lane = threadIdx.x & 31;
    if (gw >= NN) return;
    const float* row = Wh + (long)gw * fout;
    float d1 = 0.f, d2 = 0.f;
    for (int f = lane; f < fout; f += 32) {
        float v = row[f];
        d1 += v * a[f];
        d2 += v * a[fout + f];
    }
    for (int o = 16; o; o >>= 1) {
        d1 += __shfl_xor_sync(0xFFFFFFFFu, d1, o);
        d2 += __shfl_xor_sync(0xFFFFFFFFu, d2, o);
    }
    if (lane == 0) { s1[gw] = d1; s2[gw] = d2; }
}

// per-head M = leaky(max s1 + max s2)
__global__ void k_max4(const float* __restrict__ s1, const float* __restrict__ s2,
                       float* __restrict__ Mp, int nheads) {
    int h = blockIdx.x;
    const float* a = s1 + (long)h * NN;
    const float* b = s2 + (long)h * NN;
    __shared__ float m1s[512], m2s[512];
    int t = threadIdx.x;
    float m1 = -1e30f, m2 = -1e30f;
    for (int i = t; i < NN; i += 512) { m1 = fmaxf(m1, a[i]); m2 = fmaxf(m2, b[i]); }
    m1s[t] = m1; m2s[t] = m2; __syncthreads();
    for (int s = 256; s; s >>= 1) {
        if (t < s) { m1s[t] = fmaxf(m1s[t], m1s[t + s]); m2s[t] = fmaxf(m2s[t], m2s[t + s]); }
        __syncthreads();
    }
    if (t == 0) Mp[h] = lrelu(m1s[0] + m2s[0]);
}

// ---------------- FP8 sparse aggregation: 128-thr blocks + SW pipeline -------
__global__ void __launch_bounds__(128, 8) k_aggb(
    const unsigned char* __restrict__ WhbAll,
    const float* __restrict__ s1, const float* __restrict__ s2,
    const float* __restrict__ Mp,
    const int* __restrict__ rp, const int* __restrict__ ci,
    __nv_bfloat16* __restrict__ outBase, long headStride, int ostride) {
    int row = blockIdx.x;
    int h = blockIdx.y;
    const unsigned char* Wb = WhbAll + (long)h * NN * 256;
    const float* s1h = s1 + (long)h * NN;
    const float* s2h = s2 + (long)h * NN;
    __nv_bfloat16* out = outBase + (long)h * headStride + (long)row * ostride;

    int tid = threadIdx.x;
    int tx = tid & 31;
    int ty = tid >> 5;

    __shared__ unsigned swp[132];
    __shared__ unsigned soff[132];
    __shared__ float    sacc[1024];
    __shared__ float    szw[4];

    float s1i = s1h[row];
    float M = Mp[h];
    int rs = rp[row], re = rp[row + 1];

    __half2 zero2 = __float2half2_rn(0.f);
    __half2 A0[4] = {zero2, zero2, zero2, zero2};
    __half2 A1[4] = {zero2, zero2, zero2, zero2};
    __half2 A2[4] = {zero2, zero2, zero2, zero2};
    __half2 A3[4] = {zero2, zero2, zero2, zero2};
    float z = 0.f;

#define CVT8(us) (*reinterpret_cast<__half2*>(&(hrtmp = __nv_cvt_fp8x2_to_halfraw2((us), __NV_E4M3))))
    __half2_raw hrtmp;
#define HF4(A, wu, v) { __half2 Wv = *reinterpret_cast<const __half2*>(&(wu)); \
    A[0] = __hfma2(Wv, CVT8((unsigned short)((v).x & 0xFFFFu)), A[0]); \
    A[1] = __hfma2(Wv, CVT8((unsigned short)((v).x >> 16)),     A[1]); \
    A[2] = __hfma2(Wv, CVT8((unsigned short)((v).y & 0xFFFFu)), A[2]); \
    A[3] = __hfma2(Wv, CVT8((unsigned short)((v).y >> 16)),     A[3]); }

    unsigned lof = tx * 8;
    for (int base = rs; base < re; base += 128) {
        int n = min(128, re - base);
        __syncthreads();
        if (tid < n) {
            int j = ci[base + tid];
            soff[tid] = (unsigned)j << 8;
            float w = __expf(lrelu(s1i + s2h[j]) - M);
            z += w;
            __half2 wb = __float2half2_rn(w);
            swp[tid] = *reinterpret_cast<unsigned*>(&wb);
        }
        if (tid < 4) { swp[n + tid] = 0u; soff[n + tid] = 0u; }
        __syncthreads();

        int t = 4 * ty;
        if (t < n) {
            unsigned w0 = swp[t], w1 = swp[t + 1], w2 = swp[t + 2], w3 = swp[t + 3];
            uint2 p0 = *reinterpret_cast<const uint2*>(Wb + soff[t]     + lof);
            uint2 p1 = *reinterpret_cast<const uint2*>(Wb + soff[t + 1] + lof);
            uint2 p2 = *reinterpret_cast<const uint2*>(Wb + soff[t + 2] + lof);
            uint2 p3 = *reinterpret_cast<const uint2*>(Wb + soff[t + 3] + lof);
            while (true) {
                uint2 c0 = p0, c1 = p1, c2 = p2, c3 = p3;
                unsigned cw0 = w0, cw1 = w1, cw2 = w2, cw3 = w3;
                t += 16;
                if (t < n) {
                    w0 = swp[t]; w1 = swp[t + 1]; w2 = swp[t + 2]; w3 = swp[t + 3];
                    p0 = *reinterpret_cast<const uint2*>(Wb + soff[t]     + lof);
                    p1 = *reinterpret_cast<const uint2*>(Wb + soff[t + 1] + lof);
                    p2 = *reinterpret_cast<const uint2*>(Wb + soff[t + 2] + lof);
                    p3 = *reinterpret_cast<const uint2*>(Wb + soff[t + 3] + lof);
                }
                HF4(A0, cw0, c0) HF4(A1, cw1, c1) HF4(A2, cw2, c2) HF4(A3, cw3, c3)
                if (t >= n) break;
            }
        }
    }
#undef HF4
#undef CVT8
#pragma unroll
    for (int k = 0; k < 4; k++) {
        A0[k] = __hadd2(A0[k], A1[k]);
        A2[k] = __hadd2(A2[k], A3[k]);
        A0[k] = __hadd2(A0[k], A2[k]);
    }

    for (int o = 16; o; o >>= 1) z += __shfl_xor_sync(0xFFFFFFFFu, z, o);
    if (tx == 0) szw[ty] = z;

    {
        float2 f0 = __half22float2(A0[0]);
        float2 f1 = __half22float2(A0[1]);
        float2 f2 = __half22float2(A0[2]);
        float2 f3 = __half22float2(A0[3]);
        *reinterpret_cast<float4*>(&sacc[ty * 256 + tx * 8]) =
            make_float4(f0.x, f0.y, f1.x, f1.y);
        *reinterpret_cast<float4*>(&sacc[ty * 256 + tx * 8 + 4]) =
            make_float4(f2.x, f2.y, f3.x, f3.y);
    }
    __syncthreads();
#pragma unroll
    for (int s = 2; s; s >>= 1) {
        if (ty < s) {
            float4* d0 = reinterpret_cast<float4*>(&sacc[ty * 256 + tx * 8]);
            float4* o0 = reinterpret_cast<float4*>(&sacc[(ty + s) * 256 + tx * 8]);
            float4 a = d0[0], b = o0[0];
            a.x += b.x; a.y += b.y; a.z += b.z; a.w += b.w; d0[0] = a;
            float4 c = d0[1], e = o0[1];
            c.x += e.x; c.y += e.y; c.z += e.z; c.w += e.w; d0[1] = c;
        }
        __syncthreads();
    }
    if (ty == 0) {
        float Z = szw[0] + szw[1] + szw[2] + szw[3];
        float inv = 1.0f / Z;
        float o[8];
#pragma unroll
        for (int k = 0; k < 8; k++) {
            float t = sacc[tx * 8 + k] * inv;
            o[k] = t > 0.f ? t : expm1f(t);   // elu
        }
        uint4 w;
        __nv_bfloat162 p;
        p = __float22bfloat162_rn(make_float2(o[0], o[1])); w.x = *(unsigned int*)&p;
        p = __float22bfloat162_rn(make_float2(o[2], o[3])); w.y = *(unsigned int*)&p;
        p = __float22bfloat162_rn(make_float2(o[4], o[5])); w.z = *(unsigned int*)&p;
        p = __float22bfloat162_rn(make_float2(o[6], o[7])); w.w = *(unsigned int*)&p;
        *reinterpret_cast<uint4*>(out + tx * 8) = w;
    }
}

// fp32 aggregation (FOUT=64, out layer 0, no elu)
__global__ void k_agg64(const float* __restrict__ Wh, const float* __restrict__ s1,
                        const float* __restrict__ s2, const float* __restrict__ Mp,
                        const int* __restrict__ rp, const int* __restrict__ ci,
                        float* __restrict__ out) {
    constexpr int TX = 16, TY = 16;
    int row = blockIdx.x;
    int tid = threadIdx.x;
    int tx = tid % TX, ty = tid / TX;
    __shared__ float sw[256];
    __shared__ int sj[256];
    __shared__ float4 sacc[256];
    __shared__ float sz[256];
    float s1i = s1[row];
    float M = Mp[0];
    int rs = rp[row], re = rp[row + 1];
    float4 acc = make_float4(0.f, 0.f, 0.f, 0.f);
    float z = 0.f;
    for (int base = rs; base < re; base += 256) {
        int n = min(256, re - base);
        __syncthreads();
        for (int t = tid; t < n; t += 256) {
            int j = ci[base + t];
            sj[t] = j;
            float w = __expf(lrelu(s1i + s2[j]) - M);
            sw[t] = w;
            z += w;
        }
        __syncthreads();
        for (int t = ty; t < n; t += TY) {
            float w = sw[t];
            float4 v = reinterpret_cast<const float4*>(Wh + (long)sj[t] * 64)[tx];
            acc.x += w * v.x; acc.y += w * v.y; acc.z += w * v.z; acc.w += w * v.w;
        }
    }
    sacc[tid] = acc; sz[tid] = z; __syncthreads();
    for (int s = 128; s; s >>= 1) { if (tid < s) sz[tid] += sz[tid + s]; __syncthreads(); }
    if (ty == 0) {
        float4 a = sacc[tx];
#pragma unroll
        for (int yy = 1; yy < TY; yy++) {
            float4 b = sacc[yy * TX + tx];
            a.x += b.x; a.y += b.y; a.z += b.z; a.w += b.w;
        }
        float inv = 1.0f / sz[0];
        *reinterpret_cast<float4*>(out + (long)row * 64 + tx * 4) =
            make_float4(a.x * inv, a.y * inv, a.z * inv, a.w * inv);
    }
}

// FOUT == 1 aggregation
__global__ void k_agg1(const float* __restrict__ whc, const float* __restrict__ s1,
                       const float* __restrict__ s2, const float* __restrict__ Mp,
                       const int* __restrict__ rp, const int* __restrict__ ci,
                       float* __restrict__ out) {
    int row = blockIdx.x, tid = threadIdx.x;
    __shared__ float sa[256], szz[256];
    float s1i = s1[row], M = Mp[0];
    int rs = rp[row], re = rp[row + 1];
    float acc = 0.f, z = 0.f;
    for (int e = rs + tid; e < re; e += 256) {
        int j = ci[e];
        float w = __expf(lrelu(s1i + s2[j]) - M);
        z += w;
        acc += w * whc[j];
    }
    sa[tid] = acc; szz[tid] = z; __syncthreads();
    for (int s = 128; s; s >>= 1) {
        if (tid < s) { sa[tid] += sa[tid + s]; szz[tid] += szz[tid + s]; }
        __syncthreads();
    }
    if (tid == 0) out[row] = sa[0] / szz[0];
}

__global__ void k_out1s(const float* __restrict__ h, const float* __restrict__ Wo1,
                        const float* __restrict__ ao1, float* __restrict__ whc,
                        float* __restrict__ s1, float* __restrict__ s2) {
    int gw = (blockIdx.x * blockDim.x + threadIdx.x) >> 5;
    int lane = threadIdx.x & 31;
    if (gw >= NN) return;
    float d = 0.f;
    for (int f = lane; f < 64; f += 32) d += h[(long)gw * 64 + f] * Wo1[f];
    for (int o = 16; o; o >>= 1) d += __shfl_xor_sync(0xFFFFFFFFu, d, o);
    if (lane == 0) { whc[gw] = d; s1[gw] = d * ao1[0]; s2[gw] = d * ao1[1]; }
}

// split-K partial reduce: oWh = p0+p1+p2+p3
__global__ void k_red4(const float4* __restrict__ part, float4* __restrict__ out) {
    int i = blockIdx.x * blockDim.x + threadIdx.x;   // 65536 float4s
    float4 a = part[i], b = part[i + 65536], c = part[i + 131072], d = part[i + 196608];
    a.x += b.x + c.x + d.x; a.y += b.y + c.y + d.y;
    a.z += b.z + c.z + d.z; a.w += b.w + c.w + d.w;
    out[i] = a;
}

// ---------------- bf16 tensor-core GEMM, double-buffered smem ----------------
__device__ __forceinline__ void ldsm4(unsigned& r0, unsigned& r1, unsigned& r2, unsigned& r3,
                                      unsigned addr) {
    asm volatile("ldmatrix.sync.aligned.m8n8.x4.shared.b16 {%0,%1,%2,%3}, [%4];"
                 : "=r"(r0), "=r"(r1), "=r"(r2), "=r"(r3) : "r"(addr));
}
__device__ __forceinline__ void ldsm4t(unsigned& r0, unsigned& r1, unsigned& r2, unsigned& r3,
                                       unsigned addr) {
    asm volatile("ldmatrix.sync.aligned.m8n8.x4.trans.shared.b16 {%0,%1,%2,%3}, [%4];"
                 : "=r"(r0), "=r"(r1), "=r"(r2), "=r"(r3) : "r"(addr));
}
__device__ __forceinline__ void mma16816(float* c, unsigned a0, unsigned a1, unsigned a2,
                                         unsigned a3, unsigned b0, unsigned b1) {
    asm volatile(
        "mma.sync.aligned.m16n8k16.row.col.f32.bf16.bf16.f32 "
        "{%0,%1,%2,%3},{%4,%5,%6,%7},{%8,%9},{%0,%1,%2,%3};"
        : "+f"(c[0]), "+f"(c[1]), "+f"(c[2]), "+f"(c[3])
        : "r"(a0), "r"(a1), "r"(a2), "r"(a3), "r"(b0), "r"(b1));
}

#define GA_ROWB 80
#define GB_ROWB 272
#define GA_BYTES (128 * GA_ROWB)
#define GB_BYTES (32 * GB_ROWB)
#define SBUF (GA_BYTES + GB_BYTES)

__global__ void __launch_bounds__(256, 2) k_bgemm(
    const __nv_bfloat16* __restrict__ A, const __nv_bfloat16* __restrict__ B,
    float* __restrict__ C, unsigned short* __restrict__ C8,
    int M, int N, int K, int lda,
    long sA, long sB, long sC, long sC8) {
    __shared__ __align__(16) unsigned char sm[2 * SBUF];
    A += (long)blockIdx.z * sA;
    B += (long)blockIdx.z * sB;
    if (C) C += (long)blockIdx.z * sC;
    if (C8) C8 += (long)blockIdx.z * sC8;

    int tid = threadIdx.x;
    int warp = tid >> 5, lane = tid & 31;
    int wm = warp & 3, wn = warp >> 2;
    int m0 = blockIdx.y * 128, n0 = blockIdx.x * 128;

    int ar = tid >> 2;
    int ac = tid & 3;
    int br = tid >> 4;
    int bc = tid & 15;
    bool bok = (n0 + bc * 8) < N;

    unsigned s_base = (unsigned)__cvta_generic_to_shared(sm);
    int sub = lane >> 3, r = lane & 7;

    float acc[2][8][4] = {};
    int KT = K / 32;
    uint4 av0, av1, bv0, bv1;
    const uint4 zero4 = make_uint4(0, 0, 0, 0);

    // iter-0 global load + store into buffer 0
    av0 = reinterpret_cast<const uint4*>(A + (long)(m0 + ar) * lda)[ac];
    av1 = reinterpret_cast<const uint4*>(A + (long)(m0 + ar + 64) * lda)[ac];
    bv0 = bok ? *reinterpret_cast<const uint4*>(B + (long)br * N + n0 + bc * 8) : zero4;
    bv1 = bok ? *reinterpret_cast<const uint4*>(B + (long)(br + 16) * N + n0 + bc * 8) : zero4;
    {
        uint4* As4 = reinterpret_cast<uint4*>(sm);
        uint4* Bs4 = reinterpret_cast<uint4*>(sm + GA_BYTES);
        As4[ar * 5 + ac] = av0;
        As4[(ar + 64) * 5 + ac] = av1;
        Bs4[br * 17 + bc] = bv0;
        Bs4[(br + 16) * 17 + bc] = bv1;
    }

    int p = 0;
    for (int it = 0; it < KT; it++) {
        __syncthreads();
        bool more = (it + 1 < KT);
        if (more) {
            int kof = (it + 1) * 32;
            av0 = reinterpret_cast<const uint4*>(A + (long)(m0 + ar) * lda + kof)[ac];
            av1 = reinterpret_cast<const uint4*>(A + (long)(m0 + ar + 64) * lda + kof)[ac];
            bv0 = bok ? *reinterpret_cast<const uint4*>(B + (long)(kof + br) * N + n0 + bc * 8) : zero4;
            bv1 = bok ? *reinterpret_cast<const uint4*>(B + (long)(kof + br + 16) * N + n0 + bc * 8) : zero4;
        }

        unsigned sA_base = s_base + p * SBUF;
        unsigned sB_base = sA_base + GA_BYTES;
#pragma unroll
        for (int ks = 0; ks < 2; ks++) {
            unsigned a[2][4];
#pragma unroll
            for (int i = 0; i < 2; i++) {
                unsigned addr = sA_base
                    + (unsigned)((wm * 32 + i * 16 + (sub & 1) * 8 + r) * GA_ROWB
                                 + ks * 32 + (sub >> 1) * 16);
                ldsm4(a[i][0], a[i][1], a[i][2], a[i][3], addr);
            }
            unsigned b[4][4];
#pragma unroll
            for (int j = 0; j < 4; j++) {
                unsigned addr = sB_base
                    + (unsigned)((ks * 16 + (sub & 1) * 8 + r) * GB_ROWB
                                 + (wn * 64 + j * 16 + (sub >> 1) * 8) * 2);
                ldsm4t(b[j][0], b[j][1], b[j][2], b[j][3], addr);
            }
#pragma unroll
            for (int i = 0; i < 2; i++) {
#pragma unroll
                for (int j = 0; j < 4; j++) {
                    mma16816(acc[i][2 * j],     a[i][0], a[i][1], a[i][2], a[i][3],
                             b[j][0], b[j][1]);
                    mma16816(acc[i][2 * j + 1], a[i][0], a[i][1], a[i][2], a[i][3],
                             b[j][2], b[j][3]);
                }
            }
        }
        if (more) {
            uint4* As4 = reinterpret_cast<uint4*>(sm + (p ^ 1) * SBUF);
            uint4* Bs4 = reinterpret_cast<uint4*>(sm + (p ^ 1) * SBUF + GA_BYTES);
            As4[ar * 5 + ac] = av0;
            As4[(ar + 64) * 5 + ac] = av1;
            Bs4[br * 17 + bc] = bv0;
            Bs4[(br + 16) * 17 + bc] = bv1;
        }
        p ^= 1;
    }

    int g = lane >> 2, ti = lane & 3;
#pragma unroll
    for (int i = 0; i < 2; i++) {
#pragma unroll
        for (int jj = 0; jj < 8; jj++) {
            int row = m0 + wm * 32 + i * 16 + g;
            int col = n0 + wn * 64 + jj * 8 + ti * 2;
            if (col < N) {
                float* c = acc[i][jj];
                if (C) {
                    *reinterpret_cast<float2*>(C + (long)row * N + col) = make_float2(c[0], c[1]);
                    *reinterpret_cast<float2*>(C + (long)(row + 8) * N + col) = make_float2(c[2], c[3]);
                }
                if (C8) {
                    C8[((long)row * N + col) >> 1] =
                        __nv_cvt_float2_to_fp8x2(make_float2(c[0], c[1]), __NV_SATFINITE, __NV_E4M3);
                    C8[((long)(row + 8) * N + col) >> 1] =
                        __nv_cvt_float2_to_fp8x2(make_float2(c[2], c[3]), __NV_SATFINITE, __NV_E4M3);
                }
            }
        }
    }
}

// ---------------- final degree MLP ----------------
__global__ void k_mlp(const float* __restrict__ hout, const float* __restrict__ dv,
                      const float* __restrict__ dW, const float* __restrict__ dW0,
                      const float* __restrict__ dW1, const float* __restrict__ dW01,
                      const float* __restrict__ dW2, const float* __restrict__ dW02,
                      const float* __restrict__ dV, const float* __restrict__ dV0,
                      float* __restrict__ out) {
    int i = blockIdx.x * blockDim.x + threadIdx.x;
    if (i >= NN) return;
    float hv = hout[i];
    float x0 = hv > 0.f ? hv : expm1f(hv);
    float x1 = dv[i];
    float h0[10];
#pragma unroll
    for (int k = 0; k < 10; k++)
        h0[k] = lrelu(x0 * dW[k] + x1 * dW[10 + k] + dW0[k]);
    float h1[20];
#pragma unroll
    for (int k = 0; k < 20; k++) {
        float t = dW01[k];
#pragma unroll
        for (int j = 0; j < 10; j++) t += h0[j] * dW1[j * 20 + k];
        h1[k] = lrelu(t);
    }
    float h2[10];
#pragma unroll
    for (int k = 0; k < 10; k++) {
        float t = dW02[k];
#pragma unroll
        for (int j = 0; j < 20; j++) t += h1[j] * dW2[j * 10 + k];
        h2[k] = lrelu(t);
    }
    float o = dV0[0];
#pragma unroll
    for (int j = 0; j < 10; j++) o += h2[j] * dV[j];
    out[i] = lrelu(o);
}

// ---------------- launch ----------------
extern "C" void kernel_launch(void* const* d_in, const int* in_sizes, int n_in,
                              void* d_out, int out_size) {
    const float* x     = (const float*)d_in[0];
    const float* adj   = (const float*)d_in[1];
    const int*   obs   = (const int*)d_in[2];
    const float* s_mat = (const float*)d_in[3];
    const float* theta = (const float*)d_in[4];
    const float* Wh0   = (const float*)d_in[5];
    const float* ah0   = (const float*)d_in[6];
    const float* Wh1   = (const float*)d_in[7];
    const float* ah1   = (const float*)d_in[8];
    const float* Wo0   = (const float*)d_in[9];
    const float* ao0   = (const float*)d_in[10];
    const float* Wo1   = (const float*)d_in[11];
    const float* ao1   = (const float*)d_in[12];
    const float* dW    = (const float*)d_in[13];
    const float* dW0   = (const float*)d_in[14];
    const float* dW1   = (const float*)d_in[15];
    const float* dW01  = (const float*)d_in[16];
    const float* dW2   = (const float*)d_in[17];
    const float* dW02  = (const float*)d_in[18];
    const float* dV    = (const float*)d_in[19];
    const float* dV0   = (const float*)d_in[20];
    float* out = (float*)d_out;

    float* fa = nullptr;
    int*   ia = nullptr;
    cudaGetSymbolAddress((void**)&fa, g_farena);
    cudaGetSymbolAddress((void**)&ia, g_iarena);

    float* P0   = fa + OFF_P0;
    float* P1   = fa + OFF_P1;
    float* oWh  = fa + OFF_OWH;
    float* ho0  = fa + OFF_HO0;
    float* whc  = fa + OFF_WHC;
    float* hout = fa + OFF_HOUT;
    float* s1   = fa + OFF_S1;
    float* s2   = fa + OFF_S2;
    float* Mp   = fa + OFF_M;
    float* dv   = fa + OFF_DV;
    float* part = fa + OFF_PART;
    unsigned char* Whb8  = (unsigned char*)(fa + OFF_WHB);
    __nv_bfloat16* hinb  = (__nv_bfloat16*)(fa + OFF_HINB);
    __nv_bfloat16* h1bb  = (__nv_bfloat16*)(fa + OFF_H1B);
    __nv_bfloat16* hcatb = (__nv_bfloat16*)(fa + OFF_HCATB);
    __nv_bfloat16* W0b   = (__nv_bfloat16*)(fa + OFF_W0B);
    __nv_bfloat16* W1b   = (__nv_bfloat16*)(fa + OFF_W1B);
    __nv_bfloat16* Wo0b  = (__nv_bfloat16*)(fa + OFF_WO0B);
    int* cnt = ia + OFF_CNT;
    int* rp  = ia + OFF_RP;
    unsigned* msk = (unsigned*)(ia + OFF_MSK);
    int* ci  = ia + OFF_CI;

    const long NM = (long)NN * 256;

    // launches 1-3: inputs for the big GEMM
    k_mergeb<<<2048, 256>>>((const float4*)x, obs, (const float4*)theta, (uint2*)hinb);
    k_cvt<<<512, 256>>>((const float4*)Wh0, (uint2*)W0b, 131072);
    k_cvt<<<256, 256>>>((const float4*)Wh1, (uint2*)W1b, 65536);

    // launch 4: head-layer-0 GEMM  ← ncu capture slot
    k_bgemm<<<dim3(2, 32, 4), 256>>>(hinb, W0b, nullptr, (unsigned short*)Whb8,
                                     NN, 256, 512, 512, 0L, 512L * 256, 0L, (long)NN * 128);

    // remaining prep (independent of GEMM)
    k_cvt<<<64, 256>>>((const float4*)Wo0, (uint2*)Wo0b, 16384);
    k_wa<<<dim3(128, 4), 256>>>(Wh0, ah0, P0, 512);
    k_wa<<<dim3(64, 4), 256>>>(Wh1, ah1, P1, 256);
    k_sb<<<2048, 256>>>(hinb, 0L, P0, 512, s1, s2);
    k_count<<<NN, 256>>>(adj, msk, cnt);
    k_scan<<<1, 1024>>>(cnt, rp);
    k_fill<<<NN, 128>>>(msk, rp, ci);
    k_rowsum<<<NN, 256>>>(s_mat, dv);
    k_max4<<<4, 512>>>(s1, s2, Mp, 4);

    // ---- head layer 0 aggregation ----
    k_aggb<<<dim3(NN, 4), 128>>>(Whb8, s1, s2, Mp, rp, ci, h1bb, NM, 256);

    // ---- head layer 1 ----
    k_bgemm<<<dim3(2, 32, 4), 256>>>(h1bb, W1b, nullptr, (unsigned short*)Whb8,
                                     NN, 256, 256, 256, NM, 256L * 256, 0L, (long)NN * 128);
    k_sb<<<2048, 256>>>(h1bb, NM, P1, 256, s1, s2);
    k_max4<<<4, 512>>>(s1, s2, Mp, 4);
    k_aggb<<<dim3(NN, 4), 128>>>(Whb8, s1, s2, Mp, rp, ci, hcatb, 256L, 1024);

    // ---- output layer 0: split-K=4 GEMM + reduce ----
    k_bgemm<<<dim3(1, 32, 4), 256>>>(hcatb, Wo0b, part, nullptr,
                                     NN, 64, 256, 1024, 256L, 256L * 64, 262144L, 0L);
    k_red4<<<256, 256>>>((const float4*)part, (float4*)oWh);
    k_s<<<512, 256>>>(oWh, ao0, 64, s1, s2);
    k_max4<<<1, 512>>>(s1, s2, Mp, 1);
    k_agg64<<<NN, 256>>>(oWh, s1, s2, Mp, rp, ci, ho0);

    // ---- output layer 1 ----
    k_out1s<<<512, 256>>>(ho0, Wo1, ao1, whc, s1, s2);
    k_max4<<<1, 512>>>(s1, s2, Mp, 1);
    k_agg1<<<NN, 256>>>(whc, s1, s2, Mp, rp, ci, hout);

    // ---- elu + degree MLP ----
    k_mlp<<<16, 256>>>(hout, dv, dW, dW0, dW1, dW01, dW2, dW02, dV, dV0, out);
}

// round 9
// speedup vs baseline: 1.2621x; 1.0267x over previous
#include <cuda_runtime.h>
#include <cuda_bf16.h>
#include <cuda_fp8.h>
#include <math.h>

#define NN 4096
#define ALPHA 0.2f

__device__ __forceinline__ float lrelu(float v){ return v >= 0.f ? v : ALPHA * v; }

// ---------------- scratch arenas (device globals; no allocation) -------------
#define OFF_P0    0L
#define OFF_P1    4096L
#define OFF_OWH   8192L
#define OFF_HO0   270336L
#define OFF_WHC   532480L
#define OFF_HOUT  536576L
#define OFF_S1V   540672L     // [NN][4] interleaved
#define OFF_S2V   557056L     // [NN][4] interleaved
#define OFF_M     573440L
#define OFF_DV    573456L
#define OFF_S1O   577552L     // flat, out layers
#define OFF_S2O   581648L
#define OFF_WHB   585744L     // fp8 4*4096*256 bytes = 1048576 floats
#define OFF_HINB  1634320L    // bf16 4096*512
#define OFF_H1B   2682896L    // bf16 4*4096*256
#define OFF_HCATB 4780048L    // bf16 4096*1024
#define OFF_W0B   6877200L
#define OFF_W1B   7139344L
#define OFF_WO0B  7270416L
#define OFF_PART  7303184L    // split-K partials 4*4096*64
#define FARENA_SZ 8400000L

#define OFF_CNT   0
#define OFF_RP    4096
#define OFF_MSK   8208
#define OFF_CI    532496
#define IARENA_SZ 2200000

__device__ float g_farena[FARENA_SZ];
__device__ int   g_iarena[IARENA_SZ];

// ---------------- CSR construction (bitmask two-pass) ----------------
__global__ void k_count(const float* __restrict__ adj, unsigned* __restrict__ msk,
                        int* __restrict__ cnt) {
    int row = blockIdx.x, tid = threadIdx.x;
    int lane = tid & 31, wid = tid >> 5;
    const float4* p = reinterpret_cast<const float4*>(adj + (long)row * NN);
    unsigned* mrow = msk + (long)row * 128;
    int c = 0;
    for (int seg = wid; seg < 32; seg += 8) {
        float4 v = p[seg * 32 + lane];
        unsigned b0 = __ballot_sync(0xFFFFFFFFu, v.x > 0.f);
        unsigned b1 = __ballot_sync(0xFFFFFFFFu, v.y > 0.f);
        unsigned b2 = __ballot_sync(0xFFFFFFFFu, v.z > 0.f);
        unsigned b3 = __ballot_sync(0xFFFFFFFFu, v.w > 0.f);
        c += (v.x > 0.f) + (v.y > 0.f) + (v.z > 0.f) + (v.w > 0.f);
        if (lane == 0) {
            mrow[seg * 4 + 0] = b0; mrow[seg * 4 + 1] = b1;
            mrow[seg * 4 + 2] = b2; mrow[seg * 4 + 3] = b3;
        }
    }
    for (int o = 16; o; o >>= 1) c += __shfl_xor_sync(0xFFFFFFFFu, c, o);
    __shared__ int ws[8];
    if (lane == 0) ws[wid] = c;
    __syncthreads();
    if (tid == 0)
        cnt[row] = ws[0] + ws[1] + ws[2] + ws[3] + ws[4] + ws[5] + ws[6] + ws[7];
}

__global__ void k_scan(const int* __restrict__ cnt, int* __restrict__ rp) {
    __shared__ int s[1024];
    int t = threadIdx.x;
    int v[4]; int loc = 0;
#pragma unroll
    for (int k = 0; k < 4; k++) { v[k] = cnt[t * 4 + k]; loc += v[k]; }
    s[t] = loc; __syncthreads();
    for (int off = 1; off < 1024; off <<= 1) {
        int add = (t >= off) ? s[t - off] : 0;
        __syncthreads();
        s[t] += add;
        __syncthreads();
    }
    int run = (t == 0) ? 0 : s[t - 1];
#pragma unroll
    for (int k = 0; k < 4; k++) { rp[t * 4 + k] = run; run += v[k]; }
    if (t == 1023) rp[NN] = run;
}

__global__ void k_fill(const unsigned* __restrict__ msk, const int* __restrict__ rp,
                       int* __restrict__ ci) {
    int row = blockIdx.x, tid = threadIdx.x;
    int lane = tid & 31, wid = tid >> 5;
    unsigned m = msk[(long)row * 128 + tid];
    int c = __popc(m);
    int pre = c;
    for (int o = 1; o < 32; o <<= 1) {
        int v = __shfl_up_sync(0xFFFFFFFFu, pre, o);
        if (lane >= o) pre += v;
    }
    __shared__ int wt[4];
    if (lane == 31) wt[wid] = pre;
    __syncthreads();
    int woff = 0;
    for (int i = 0; i < wid; i++) woff += wt[i];
    int pos = rp[row] + woff + pre - c;
    int base = (tid >> 2) * 128 + (tid & 3);
    while (m) {
        int b = __ffs(m) - 1;
        m &= m - 1;
        ci[pos++] = base + b * 4;
    }
}

// ---------------- misc ----------------
__global__ void k_rowsum(const float* __restrict__ sm, float* __restrict__ dv) {
    int row = blockIdx.x, tid = threadIdx.x;
    const float4* p = reinterpret_cast<const float4*>(sm + (long)row * NN);
    float acc = 0.f;
    for (int i = tid; i < NN / 4; i += 256) { float4 v = p[i]; acc += v.x + v.y + v.z + v.w; }
    __shared__ float s[256];
    s[tid] = acc; __syncthreads();
    for (int st = 128; st; st >>= 1) { if (tid < st) s[tid] += s[tid + st]; __syncthreads(); }
    if (tid == 0) dv[row] = s[0];
}

__global__ void k_mergeb(const float4* __restrict__ x, const int* __restrict__ obs,
                         const float4* __restrict__ theta, uint2* __restrict__ out) {
    long i = (long)blockIdx.x * blockDim.x + threadIdx.x;
    int row = (int)(i >> 7);
    int f4 = (int)(i & 127);
    float4 v = x[i];
    if (obs[row] == 1) { float4 t = theta[f4]; v.x += t.x; v.y += t.y; v.z += t.z; v.w += t.w; }
    __nv_bfloat162 p0 = __float22bfloat162_rn(make_float2(v.x, v.y));
    __nv_bfloat162 p1 = __float22bfloat162_rn(make_float2(v.z, v.w));
    uint2 w;
    w.x = *reinterpret_cast<unsigned int*>(&p0);
    w.y = *reinterpret_cast<unsigned int*>(&p1);
    out[i] = w;
}

__global__ void k_cvt(const float4* __restrict__ in, uint2* __restrict__ out, int n4) {
    int i = blockIdx.x * blockDim.x + threadIdx.x;
    if (i >= n4) return;
    float4 v = in[i];
    __nv_bfloat162 p0 = __float22bfloat162_rn(make_float2(v.x, v.y));
    __nv_bfloat162 p1 = __float22bfloat162_rn(make_float2(v.z, v.w));
    uint2 w;
    w.x = *reinterpret_cast<unsigned int*>(&p0);
    w.y = *reinterpret_cast<unsigned int*>(&p1);
    out[i] = w;
}

// P[(2h+c)*Fin + f] = sum_d W[h,f,d] * a[h, c*256 + d]
__global__ void k_wa(const float* __restrict__ W, const float* __restrict__ a,
                     float* __restrict__ P, int Fin) {
    int h = blockIdx.y;
    int idx = blockIdx.x * 8 + (threadIdx.x >> 5);
    int lane = threadIdx.x & 31;
    if (idx >= 2 * Fin) return;
    int c = idx / Fin, f = idx % Fin;
    const float* wrow = W + ((long)h * Fin + f) * 256;
    const float* av = a + h * 512 + c * 256;
    float d = 0.f;
    for (int k = lane; k < 256; k += 32) d = fmaf(wrow[k], av[k], d);
    for (int o = 16; o; o >>= 1) d += __shfl_xor_sync(0xFFFFFFFFu, d, o);
    if (lane == 0) P[(2 * h + c) * Fin + f] = d;
}

// s1/s2 from bf16 activations -> interleaved [row][head] layout (gw = row*4+h)
__global__ void __launch_bounds__(256) k_sb(
    const __nv_bfloat16* __restrict__ act, long headStride,
    const float* __restrict__ P, int K,
    float* __restrict__ s1, float* __restrict__ s2) {
    __shared__ float Ps[4096];
    int tid = threadIdx.x;
    for (int i = tid; i < 8 * K; i += 256) Ps[i] = P[i];
    __syncthreads();
    int gw = blockIdx.x * 8 + (tid >> 5);
    int lane = tid & 31;
    int row = gw >> 2, h = gw & 3;
    const __nv_bfloat16* a = act + (long)h * headStride + (long)row * K;
    const float* p1 = Ps + (2 * h) * K;
    const float* p2 = p1 + K;
    float d1 = 0.f, d2 = 0.f;
    for (int f = lane * 2; f < K; f += 64) {
        unsigned u = *reinterpret_cast<const unsigned*>(a + f);
        float x0 = __uint_as_float(u << 16);
        float x1 = __uint_as_float(u & 0xFFFF0000u);
        d1 = fmaf(x0, p1[f], fmaf(x1, p1[f + 1], d1));
        d2 = fmaf(x0, p2[f], fmaf(x1, p2[f + 1], d2));
    }
    for (int o = 16; o; o >>= 1) {
        d1 += __shfl_xor_sync(0xFFFFFFFFu, d1, o);
        d2 += __shfl_xor_sync(0xFFFFFFFFu, d2, o);
    }
    if (lane == 0) { s1[gw] = d1; s2[gw] = d2; }   // gw = row*4 + h
}

// s for out layer 0 (fout=64, fp32, flat)
__global__ void k_s(const float* __restrict__ Wh, const float* __restrict__ a, int fout,
                    float* __restrict__ s1, float* __restrict__ s2) {
    int gw = (blockIdx.x * blockDim.x + threadIdx.x) >> 5;
    int lane = threadIdx.x & 31;
    if (gw >= NN) return;
    const float* row = Wh + (long)gw * fout;
    float d1 = 0.f, d2 = 0.f;
    for (int f = lane; f < fout; f += 32) {
        float v = row[f];
        d1 += v * a[f];
        d2 += v * a[fout + f];
    }
    for (int o = 16; o; o >>= 1) {
        d1 += __shfl_xor_sync(0xFFFFFFFFu, d1, o);
        d2 += __shfl_xor_sync(0xFFFFFFFFu, d2, o);
    }
    if (lane == 0) { s1[gw] = d1; s2[gw] = d2; }
}

// per-head M = leaky(max s1 + max s2); stride-indexed: s[i*stride + h]
__global__ void k_max4(const float* __restrict__ s1, const float* __restrict__ s2,
                       float* __restrict__ Mp, int stride) {
    int h = blockIdx.x;
    __shared__ float m1s[512], m2s[512];
    int t = threadIdx.x;
    float m1 = -1e30f, m2 = -1e30f;
    for (int i = t; i < NN; i += 512) {
        m1 = fmaxf(m1, s1[i * stride + h]);
        m2 = fmaxf(m2, s2[i * stride + h]);
    }
    m1s[t] = m1; m2s[t] = m2; __syncthreads();
    for (int s = 256; s; s >>= 1) {
        if (t < s) { m1s[t] = fmaxf(m1s[t], m1s[t + s]); m2s[t] = fmaxf(m2s[t], m2s[t + s]); }
        __syncthreads();
    }
    if (t == 0) Mp[h] = lrelu(m1s[0] + m2s[0]);
}

// ---------- fused 4-head FP8 aggregation: 1 block per row, 2 warps/head ------
__global__ void __launch_bounds__(256) k_agg4(
    const unsigned char* __restrict__ Whb,     // head-major fp8: h*NN*256 + j*256
    const float4* __restrict__ s1v, const float4* __restrict__ s2v,
    const float* __restrict__ Mp,
    const int* __restrict__ rp, const int* __restrict__ ci,
    __nv_bfloat16* __restrict__ outBase, long headStride, int ostride) {
    int row = blockIdx.x;
    int tid = threadIdx.x;
    int lane = tid & 31, warp = tid >> 5;
    int h = warp >> 1, par = warp & 1;

    __shared__ float4   swp[392];
    __shared__ unsigned soff[392];
    __shared__ float    sacc[8][256];
    __shared__ float    szw[8];

    int rs = rp[row], re = rp[row + 1];
    float4 s1r = s1v[row];
    float4 Mv = *reinterpret_cast<const float4*>(Mp);

    const unsigned char* Wb = Whb + (long)h * (NN * 256);
    unsigned lof = lane * 8;

    __half2 zero2 = __float2half2_rn(0.f);
    __half2 A0[4] = {zero2, zero2, zero2, zero2};
    __half2 A1[4] = {zero2, zero2, zero2, zero2};
    __half2 A2[4] = {zero2, zero2, zero2, zero2};
    __half2 A3[4] = {zero2, zero2, zero2, zero2};
    float z = 0.f;

#define CVT8(us) (*reinterpret_cast<__half2*>(&(hrtmp = __nv_cvt_fp8x2_to_halfraw2((us), __NV_E4M3))))
    __half2_raw hrtmp;
#define HF4(A, wh, v) { \
    A[0] = __hfma2(wh, CVT8((unsigned short)((v).x & 0xFFFFu)), A[0]); \
    A[1] = __hfma2(wh, CVT8((unsigned short)((v).x >> 16)),     A[1]); \
    A[2] = __hfma2(wh, CVT8((unsigned short)((v).y & 0xFFFFu)), A[2]); \
    A[3] = __hfma2(wh, CVT8((unsigned short)((v).y >> 16)),     A[3]); }

    for (int base = rs; base < re; base += 384) {
        int n = min(384, re - base);
        __syncthreads();
        for (int e = tid; e < n; e += 256) {
            int j = ci[base + e];
            soff[e] = (unsigned)j << 8;
            float4 s2r = s2v[j];
            float4 w;
            w.x = __expf(lrelu(s1r.x + s2r.x) - Mv.x);
            w.y = __expf(lrelu(s1r.y + s2r.y) - Mv.y);
            w.z = __expf(lrelu(s1r.z + s2r.z) - Mv.z);
            w.w = __expf(lrelu(s1r.w + s2r.w) - Mv.w);
            swp[e] = w;
        }
        if (tid < 8) { soff[n + tid] = 0u; swp[n + tid] = make_float4(0.f, 0.f, 0.f, 0.f); }
        __syncthreads();

        int t = 4 * par;
        if (t < n) {
            float w0 = reinterpret_cast<const float*>(&swp[t])[h];
            float w1 = reinterpret_cast<const float*>(&swp[t + 1])[h];
            float w2 = reinterpret_cast<const float*>(&swp[t + 2])[h];
            float w3 = reinterpret_cast<const float*>(&swp[t + 3])[h];
            uint2 p0 = *reinterpret_cast<const uint2*>(Wb + soff[t]     + lof);
            uint2 p1 = *reinterpret_cast<const uint2*>(Wb + soff[t + 1] + lof);
            uint2 p2 = *reinterpret_cast<const uint2*>(Wb + soff[t + 2] + lof);
            uint2 p3 = *reinterpret_cast<const uint2*>(Wb + soff[t + 3] + lof);
            while (true) {
                uint2 c0 = p0, c1 = p1, c2 = p2, c3 = p3;
                float cw0 = w0, cw1 = w1, cw2 = w2, cw3 = w3;
                t += 8;
                if (t < n) {
                    w0 = reinterpret_cast<const float*>(&swp[t])[h];
                    w1 = reinterpret_cast<const float*>(&swp[t + 1])[h];
                    w2 = reinterpret_cast<const float*>(&swp[t + 2])[h];
                    w3 = reinterpret_cast<const float*>(&swp[t + 3])[h];
                    p0 = *reinterpret_cast<const uint2*>(Wb + soff[t]     + lof);
                    p1 = *reinterpret_cast<const uint2*>(Wb + soff[t + 1] + lof);
                    p2 = *reinterpret_cast<const uint2*>(Wb + soff[t + 2] + lof);
                    p3 = *reinterpret_cast<const uint2*>(Wb + soff[t + 3] + lof);
                }
                z += cw0 + cw1 + cw2 + cw3;
                __half2 wh0 = __float2half2_rn(cw0);
                __half2 wh1 = __float2half2_rn(cw1);
                __half2 wh2 = __float2half2_rn(cw2);
                __half2 wh3 = __float2half2_rn(cw3);
                HF4(A0, wh0, c0) HF4(A1, wh1, c1) HF4(A2, wh2, c2) HF4(A3, wh3, c3)
                if (t >= n) break;
            }
        }
    }
#undef HF4
#undef CVT8
#pragma unroll
    for (int k = 0; k < 4; k++) {
        A0[k] = __hadd2(A0[k], A1[k]);
        A2[k] = __hadd2(A2[k], A3[k]);
        A0[k] = __hadd2(A0[k], A2[k]);
    }

    for (int o = 16; o; o >>= 1) z += __shfl_xor_sync(0xFFFFFFFFu, z, o);
    if (lane == 0) szw[warp] = z;

    {
        float2 f0 = __half22float2(A0[0]);
        float2 f1 = __half22float2(A0[1]);
        float2 f2 = __half22float2(A0[2]);
        float2 f3 = __half22float2(A0[3]);
        *reinterpret_cast<float4*>(&sacc[warp][lane * 8]) =
            make_float4(f0.x, f0.y, f1.x, f1.y);
        *reinterpret_cast<float4*>(&sacc[warp][lane * 8 + 4]) =
            make_float4(f2.x, f2.y, f3.x, f3.y);
    }
    __syncthreads();

    if (warp < 4) {
        int hh = warp;
        float Z = szw[2 * hh] + szw[2 * hh + 1];
        float inv = 1.0f / Z;
        float o[8];
#pragma unroll
        for (int k = 0; k < 8; k++) {
            float t = (sacc[2 * hh][lane * 8 + k] + sacc[2 * hh + 1][lane * 8 + k]) * inv;
            o[k] = t > 0.f ? t : expm1f(t);   // elu
        }
        uint4 w;
        __nv_bfloat162 p;
        p = __float22bfloat162_rn(make_float2(o[0], o[1])); w.x = *(unsigned int*)&p;
        p = __float22bfloat162_rn(make_float2(o[2], o[3])); w.y = *(unsigned int*)&p;
        p = __float22bfloat162_rn(make_float2(o[4], o[5])); w.z = *(unsigned int*)&p;
        p = __float22bfloat162_rn(make_float2(o[6], o[7])); w.w = *(unsigned int*)&p;
        *reinterpret_cast<uint4*>(outBase + (long)hh * headStride +
                                  (long)row * ostride + lane * 8) = w;
    }
}

// fp32 aggregation (FOUT=64, out layer 0, no elu)
__global__ void k_agg64(const float* __restrict__ Wh, const float* __restrict__ s1,
                        const float* __restrict__ s2, const float* __restrict__ Mp,
                        const int* __restrict__ rp, const int* __restrict__ ci,
                        float* __restrict__ out) {
    constexpr int TX = 16, TY = 16;
    int row = blockIdx.x;
    int tid = threadIdx.x;
    int tx = tid % TX, ty = tid / TX;
    __shared__ float sw[256];
    __shared__ int sj[256];
    __shared__ float4 sacc[256];
    __shared__ float sz[256];
    float s1i = s1[row];
    float M = Mp[0];
    int rs = rp[row], re = rp[row + 1];
    float4 acc = make_float4(0.f, 0.f, 0.f, 0.f);
    float z = 0.f;
    for (int base = rs; base < re; base += 256) {
        int n = min(256, re - base);
        __syncthreads();
        for (int t = tid; t < n; t += 256) {
            int j = ci[base + t];
            sj[t] = j;
            float w = __expf(lrelu(s1i + s2[j]) - M);
            sw[t] = w;
            z += w;
        }
        __syncthreads();
        for (int t = ty; t < n; t += TY) {
            float w = sw[t];
            float4 v = reinterpret_cast<const float4*>(Wh + (long)sj[t] * 64)[tx];
            acc.x += w * v.x; acc.y += w * v.y; acc.z += w * v.z; acc.w += w * v.w;
        }
    }
    sacc[tid] = acc; sz[tid] = z; __syncthreads();
    for (int s = 128; s; s >>= 1) { if (tid < s) sz[tid] += sz[tid + s]; __syncthreads(); }
    if (ty == 0) {
        float4 a = sacc[tx];
#pragma unroll
        for (int yy = 1; yy < TY; yy++) {
            float4 b = sacc[yy * TX + tx];
            a.x += b.x; a.y += b.y; a.z += b.z; a.w += b.w;
        }
        float inv = 1.0f / sz[0];
        *reinterpret_cast<float4*>(out + (long)row * 64 + tx * 4) =
            make_float4(a.x * inv, a.y * inv, a.z * inv, a.w * inv);
    }
}

// FOUT == 1 aggregation
__global__ void k_agg1(const float* __restrict__ whc, const float* __restrict__ s1,
                       const float* __restrict__ s2, const float* __restrict__ Mp,
                       const int* __restrict__ rp, const int* __restrict__ ci,
                       float* __restrict__ out) {
    int row = blockIdx.x, tid = threadIdx.x;
    __shared__ float sa[256], szz[256];
    float s1i = s1[row], M = Mp[0];
    int rs = rp[row], re = rp[row + 1];
    float acc = 0.f, z = 0.f;
    for (int e = rs + tid; e < re; e += 256) {
        int j = ci[e];
        float w = __expf(lrelu(s1i + s2[j]) - M);
        z += w;
        acc += w * whc[j];
    }
    sa[tid] = acc; szz[tid] = z; __syncthreads();
    for (int s = 128; s; s >>= 1) {
        if (tid < s) { sa[tid] += sa[tid + s]; szz[tid] += szz[tid + s]; }
        __syncthreads();
    }
    if (tid == 0) out[row] = sa[0] / szz[0];
}

__global__ void k_out1s(const float* __restrict__ h, const float* __restrict__ Wo1,
                        const float* __restrict__ ao1, float* __restrict__ whc,
                        float* __restrict__ s1, float* __restrict__ s2) {
    int gw = (blockIdx.x * blockDim.x + threadIdx.x) >> 5;
    int lane = threadIdx.x & 31;
    if (gw >= NN) return;
    float d = 0.f;
    for (int f = lane; f < 64; f += 32) d += h[(long)gw * 64 + f] * Wo1[f];
    for (int o = 16; o; o >>= 1) d += __shfl_xor_sync(0xFFFFFFFFu, d, o);
    if (lane == 0) { whc[gw] = d; s1[gw] = d * ao1[0]; s2[gw] = d * ao1[1]; }
}

// split-K partial reduce: oWh = p0+p1+p2+p3
__global__ void k_red4(const float4* __restrict__ part, float4* __restrict__ out) {
    int i = blockIdx.x * blockDim.x + threadIdx.x;
    float4 a = part[i], b = part[i + 65536], c = part[i + 131072], d = part[i + 196608];
    a.x += b.x + c.x + d.x; a.y += b.y + c.y + d.y;
    a.z += b.z + c.z + d.z; a.w += b.w + c.w + d.w;
    out[i] = a;
}

// ---------------- bf16 tensor-core GEMM, double-buffered smem ----------------
__device__ __forceinline__ void ldsm4(unsigned& r0, unsigned& r1, unsigned& r2, unsigned& r3,
                                      unsigned addr) {
    asm volatile("ldmatrix.sync.aligned.m8n8.x4.shared.b16 {%0,%1,%2,%3}, [%4];"
                 : "=r"(r0), "=r"(r1), "=r"(r2), "=r"(r3) : "r"(addr));
}
__device__ __forceinline__ void ldsm4t(unsigned& r0, unsigned& r1, unsigned& r2, unsigned& r3,
                                       unsigned addr) {
    asm volatile("ldmatrix.sync.aligned.m8n8.x4.trans.shared.b16 {%0,%1,%2,%3}, [%4];"
                 : "=r"(r0), "=r"(r1), "=r"(r2), "=r"(r3) : "r"(addr));
}
__device__ __forceinline__ void mma16816(float* c, unsigned a0, unsigned a1, unsigned a2,
                                         unsigned a3, unsigned b0, unsigned b1) {
    asm volatile(
        "mma.sync.aligned.m16n8k16.row.col.f32.bf16.bf16.f32 "
        "{%0,%1,%2,%3},{%4,%5,%6,%7},{%8,%9},{%0,%1,%2,%3};"
        : "+f"(c[0]), "+f"(c[1]), "+f"(c[2]), "+f"(c[3])
        : "r"(a0), "r"(a1), "r"(a2), "r"(a3), "r"(b0), "r"(b1));
}

#define GA_ROWB 80
#define GB_ROWB 272
#define GA_BYTES (128 * GA_ROWB)
#define GB_BYTES (32 * GB_ROWB)
#define SBUF (GA_BYTES + GB_BYTES)

__global__ void __launch_bounds__(256, 2) k_bgemm(
    const __nv_bfloat16* __restrict__ A, const __nv_bfloat16* __restrict__ B,
    float* __restrict__ C, unsigned short* __restrict__ C8,
    int M, int N, int K, int lda,
    long sA, long sB, long sC, long sC8) {
    __shared__ __align__(16) unsigned char sm[2 * SBUF];
    A += (long)blockIdx.z * sA;
    B += (long)blockIdx.z * sB;
    if (C) C += (long)blockIdx.z * sC;
    if (C8) C8 += (long)blockIdx.z * sC8;

    int tid = threadIdx.x;
    int warp = tid >> 5, lane = tid & 31;
    int wm = warp & 3, wn = warp >> 2;
    int m0 = blockIdx.y * 128, n0 = blockIdx.x * 128;

    int ar = tid >> 2;
    int ac = tid & 3;
    int br = tid >> 4;
    int bc = tid & 15;
    bool bok = (n0 + bc * 8) < N;

    unsigned s_base = (unsigned)__cvta_generic_to_shared(sm);
    int sub = lane >> 3, r = lane & 7;

    float acc[2][8][4] = {};
    int KT = K / 32;
    uint4 av0, av1, bv0, bv1;
    const uint4 zero4 = make_uint4(0, 0, 0, 0);

    av0 = reinterpret_cast<const uint4*>(A + (long)(m0 + ar) * lda)[ac];
    av1 = reinterpret_cast<const uint4*>(A + (long)(m0 + ar + 64) * lda)[ac];
    bv0 = bok ? *reinterpret_cast<const uint4*>(B + (long)br * N + n0 + bc * 8) : zero4;
    bv1 = bok ? *reinterpret_cast<const uint4*>(B + (long)(br + 16) * N + n0 + bc * 8) : zero4;
    {
        uint4* As4 = reinterpret_cast<uint4*>(sm);
        uint4* Bs4 = reinterpret_cast<uint4*>(sm + GA_BYTES);
        As4[ar * 5 + ac] = av0;
        As4[(ar + 64) * 5 + ac] = av1;
        Bs4[br * 17 + bc] = bv0;
        Bs4[(br + 16) * 17 + bc] = bv1;
    }

    int p = 0;
    for (int it = 0; it < KT; it++) {
        __syncthreads();
        bool more = (it + 1 < KT);
        if (more) {
            int kof = (it + 1) * 32;
            av0 = reinterpret_cast<const uint4*>(A + (long)(m0 + ar) * lda + kof)[ac];
            av1 = reinterpret_cast<const uint4*>(A + (long)(m0 + ar + 64) * lda + kof)[ac];
            bv0 = bok ? *reinterpret_cast<const uint4*>(B + (long)(kof + br) * N + n0 + bc * 8) : zero4;
            bv1 = bok ? *reinterpret_cast<const uint4*>(B + (long)(kof + br + 16) * N + n0 + bc * 8) : zero4;
        }

        unsigned sA_base = s_base + p * SBUF;
        unsigned sB_base = sA_base + GA_BYTES;
#pragma unroll
        for (int ks = 0; ks < 2; ks++) {
            unsigned a[2][4];
#pragma unroll
            for (int i = 0; i < 2; i++) {
                unsigned addr = sA_base
                    + (unsigned)((wm * 32 + i * 16 + (sub & 1) * 8 + r) * GA_ROWB
                                 + ks * 32 + (sub >> 1) * 16);
                ldsm4(a[i][0], a[i][1], a[i][2], a[i][3], addr);
            }
            unsigned b[4][4];
#pragma unroll
            for (int j = 0; j < 4; j++) {
                unsigned addr = sB_base
                    + (unsigned)((ks * 16 + (sub & 1) * 8 + r) * GB_ROWB
                                 + (wn * 64 + j * 16 + (sub >> 1) * 8) * 2);
                ldsm4t(b[j][0], b[j][1], b[j][2], b[j][3], addr);
            }
#pragma unroll
            for (int i = 0; i < 2; i++) {
#pragma unroll
                for (int j = 0; j < 4; j++) {
                    mma16816(acc[i][2 * j],     a[i][0], a[i][1], a[i][2], a[i][3],
                             b[j][0], b[j][1]);
                    mma16816(acc[i][2 * j + 1], a[i][0], a[i][1], a[i][2], a[i][3],
                             b[j][2], b[j][3]);
                }
            }
        }
        if (more) {
            uint4* As4 = reinterpret_cast<uint4*>(sm + (p ^ 1) * SBUF);
            uint4* Bs4 = reinterpret_cast<uint4*>(sm + (p ^ 1) * SBUF + GA_BYTES);
            As4[ar * 5 + ac] = av0;
            As4[(ar + 64) * 5 + ac] = av1;
            Bs4[br * 17 + bc] = bv0;
            Bs4[(br + 16) * 17 + bc] = bv1;
        }
        p ^= 1;
    }

    int g = lane >> 2, ti = lane & 3;
#pragma unroll
    for (int i = 0; i < 2; i++) {
#pragma unroll
        for (int jj = 0; jj < 8; jj++) {
            int row = m0 + wm * 32 + i * 16 + g;
            int col = n0 + wn * 64 + jj * 8 + ti * 2;
            if (col < N) {
                float* c = acc[i][jj];
                if (C) {
                    *reinterpret_cast<float2*>(C + (long)row * N + col) = make_float2(c[0], c[1]);
                    *reinterpret_cast<float2*>(C + (long)(row + 8) * N + col) = make_float2(c[2], c[3]);
                }
                if (C8) {
                    C8[((long)row * N + col) >> 1] =
                        __nv_cvt_float2_to_fp8x2(make_float2(c[0], c[1]), __NV_SATFINITE, __NV_E4M3);
                    C8[((long)(row + 8) * N + col) >> 1] =
                        __nv_cvt_float2_to_fp8x2(make_float2(c[2], c[3]), __NV_SATFINITE, __NV_E4M3);
                }
            }
        }
    }
}

// ---------------- final degree MLP ----------------
__global__ void k_mlp(const float* __restrict__ hout, const float* __restrict__ dv,
                      const float* __restrict__ dW, const float* __restrict__ dW0,
                      const float* __restrict__ dW1, const float* __restrict__ dW01,
                      const float* __restrict__ dW2, const float* __restrict__ dW02,
                      const float* __restrict__ dV, const float* __restrict__ dV0,
                      float* __restrict__ out) {
    int i = blockIdx.x * blockDim.x + threadIdx.x;
    if (i >= NN) return;
    float hv = hout[i];
    float x0 = hv > 0.f ? hv : expm1f(hv);
    float x1 = dv[i];
    float h0[10];
#pragma unroll
    for (int k = 0; k < 10; k++)
        h0[k] = lrelu(x0 * dW[k] + x1 * dW[10 + k] + dW0[k]);
    float h1[20];
#pragma unroll
    for (int k = 0; k < 20; k++) {
        float t = dW01[k];
#pragma unroll
        for (int j = 0; j < 10; j++) t += h0[j] * dW1[j * 20 + k];
        h1[k] = lrelu(t);
    }
    float h2[10];
#pragma unroll
    for (int k = 0; k < 10; k++) {
        float t = dW02[k];
#pragma unroll
        for (int j = 0; j < 20; j++) t += h1[j] * dW2[j * 10 + k];
        h2[k] = lrelu(t);
    }
    float o = dV0[0];
#pragma unroll
    for (int j = 0; j < 10; j++) o += h2[j] * dV[j];
    out[i] = lrelu(o);
}

// ---------------- launch ----------------
extern "C" void kernel_launch(void* const* d_in, const int* in_sizes, int n_in,
                              void* d_out, int out_size) {
    const float* x     = (const float*)d_in[0];
    const float* adj   = (const float*)d_in[1];
    const int*   obs   = (const int*)d_in[2];
    const float* s_mat = (const float*)d_in[3];
    const float* theta = (const float*)d_in[4];
    const float* Wh0   = (const float*)d_in[5];
    const float* ah0   = (const float*)d_in[6];
    const float* Wh1   = (const float*)d_in[7];
    const float* ah1   = (const float*)d_in[8];
    const float* Wo0   = (const float*)d_in[9];
    const float* ao0   = (const float*)d_in[10];
    const float* Wo1   = (const float*)d_in[11];
    const float* ao1   = (const float*)d_in[12];
    const float* dW    = (const float*)d_in[13];
    const float* dW0   = (const float*)d_in[14];
    const float* dW1   = (const float*)d_in[15];
    const float* dW01  = (const float*)d_in[16];
    const float* dW2   = (const float*)d_in[17];
    const float* dW02  = (const float*)d_in[18];
    const float* dV    = (const float*)d_in[19];
    const float* dV0   = (const float*)d_in[20];
    float* out = (float*)d_out;

    float* fa = nullptr;
    int*   ia = nullptr;
    cudaGetSymbolAddress((void**)&fa, g_farena);
    cudaGetSymbolAddress((void**)&ia, g_iarena);

    float* P0   = fa + OFF_P0;
    float* P1   = fa + OFF_P1;
    float* oWh  = fa + OFF_OWH;
    float* ho0  = fa + OFF_HO0;
    float* whc  = fa + OFF_WHC;
    float* hout = fa + OFF_HOUT;
    float* s1v  = fa + OFF_S1V;
    float* s2v  = fa + OFF_S2V;
    float* Mp   = fa + OFF_M;
    float* dv   = fa + OFF_DV;
    float* s1o  = fa + OFF_S1O;
    float* s2o  = fa + OFF_S2O;
    float* part = fa + OFF_PART;
    unsigned char* Whb8  = (unsigned char*)(fa + OFF_WHB);
    __nv_bfloat16* hinb  = (__nv_bfloat16*)(fa + OFF_HINB);
    __nv_bfloat16* h1bb  = (__nv_bfloat16*)(fa + OFF_H1B);
    __nv_bfloat16* hcatb = (__nv_bfloat16*)(fa + OFF_HCATB);
    __nv_bfloat16* W0b   = (__nv_bfloat16*)(fa + OFF_W0B);
    __nv_bfloat16* W1b   = (__nv_bfloat16*)(fa + OFF_W1B);
    __nv_bfloat16* Wo0b  = (__nv_bfloat16*)(fa + OFF_WO0B);
    int* cnt = ia + OFF_CNT;
    int* rp  = ia + OFF_RP;
    unsigned* msk = (unsigned*)(ia + OFF_MSK);
    int* ci  = ia + OFF_CI;

    const long NM = (long)NN * 256;

    // CSR (launches 1-3)
    k_count<<<NN, 256>>>(adj, msk, cnt);
    k_scan<<<1, 1024>>>(cnt, rp);
    k_fill<<<NN, 128>>>(msk, rp, ci);

    // launch 4: ncu PROBE — fused agg on 512 rows, stale-but-deterministic data;
    // h1bb rows 0..511 fully overwritten by the real L0 aggregation below.
    k_agg4<<<512, 256>>>(Whb8, (const float4*)s1v, (const float4*)s2v, Mp,
                         rp, ci, h1bb, NM, 256);

    // prep
    k_mergeb<<<2048, 256>>>((const float4*)x, obs, (const float4*)theta, (uint2*)hinb);
    k_cvt<<<512, 256>>>((const float4*)Wh0, (uint2*)W0b, 131072);
    k_cvt<<<256, 256>>>((const float4*)Wh1, (uint2*)W1b, 65536);
    k_cvt<<<64, 256>>>((const float4*)Wo0, (uint2*)Wo0b, 16384);
    k_wa<<<dim3(128, 4), 256>>>(Wh0, ah0, P0, 512);
    k_wa<<<dim3(64, 4), 256>>>(Wh1, ah1, P1, 256);
    k_rowsum<<<NN, 256>>>(s_mat, dv);

    // ---- head layer 0 ----
    k_bgemm<<<dim3(2, 32, 4), 256>>>(hinb, W0b, nullptr, (unsigned short*)Whb8,
                                     NN, 256, 512, 512, 0L, 512L * 256, 0L, (long)NN * 128);
    k_sb<<<2048, 256>>>(hinb, 0L, P0, 512, s1v, s2v);
    k_max4<<<4, 512>>>(s1v, s2v, Mp, 4);
    k_agg4<<<NN, 256>>>(Whb8, (const float4*)s1v, (const float4*)s2v, Mp,
                        rp, ci, h1bb, NM, 256);

    // ---- head layer 1 ----
    k_bgemm<<<dim3(2, 32, 4), 256>>>(h1bb, W1b, nullptr, (unsigned short*)Whb8,
                                     NN, 256, 256, 256, NM, 256L * 256, 0L, (long)NN * 128);
    k_sb<<<2048, 256>>>(h1bb, NM, P1, 256, s1v, s2v);
    k_max4<<<4, 512>>>(s1v, s2v, Mp, 4);
    k_agg4<<<NN, 256>>>(Whb8, (const float4*)s1v, (const float4*)s2v, Mp,
                        rp, ci, hcatb, 256L, 1024);

    // ---- output layer 0: split-K=4 GEMM + reduce ----
    k_bgemm<<<dim3(1, 32, 4), 256>>>(hcatb, Wo0b, part, nullptr,
                                     NN, 64, 256, 1024, 256L, 256L * 64, 262144L, 0L);
    k_red4<<<256, 256>>>((const float4*)part, (float4*)oWh);
    k_s<<<512, 256>>>(oWh, ao0, 64, s1o, s2o);
    k_max4<<<1, 512>>>(s1o, s2o, Mp, 1);
    k_agg64<<<NN, 256>>>(oWh, s1o, s2o, Mp, rp, ci, ho0);

    // ---- output layer 1 ----
    k_out1s<<<512, 256>>>(ho0, Wo1, ao1, whc, s1o, s2o);
    k_max4<<<1, 512>>>(s1o, s2o, Mp, 1);
    k_agg1<<<NN, 256>>>(whc, s1o, s2o, Mp, rp, ci, hout);

    // ---- elu + degree MLP ----
    k_mlp<<<16, 256>>>(hout, dv, dW, dW0, dW1, dW01, dW2, dW02, dV, dV0, out);
}

// round 10
// speedup vs baseline: 1.4300x; 1.1330x over previous
#include <cuda_runtime.h>
#include <cuda_bf16.h>
#include <cuda_fp8.h>
#include <math.h>

#define NN 4096
#define ALPHA 0.2f

__device__ __forceinline__ float lrelu(float v){ return v >= 0.f ? v : ALPHA * v; }

// ---------------- scratch arenas (device globals; no allocation) -------------
#define OFF_P0    0L
#define OFF_P1    4096L
#define OFF_OWH   8192L
#define OFF_HO0   270336L
#define OFF_WHC   532480L
#define OFF_HOUT  536576L
#define OFF_S1V   540672L     // [NN][4] interleaved
#define OFF_S2V   557056L     // [NN][4] interleaved
#define OFF_M     573440L
#define OFF_DV    573456L
#define OFF_S1O   577552L
#define OFF_S2O   581648L
#define OFF_WHB   585744L     // fp8 4*4096*256 bytes = 1048576 floats
#define OFF_HINB  1634320L    // bf16 4096*512
#define OFF_H1B   2682896L    // bf16 4*4096*256
#define OFF_HCATB 4780048L    // bf16 4096*1024
#define OFF_W0B   6877200L
#define OFF_W1B   7139344L
#define OFF_WO0B  7270416L
#define OFF_PART  7303184L    // split-K partials 4*4096*64
#define FARENA_SZ 8400000L

#define OFF_CNT   0
#define OFF_RP    4096
#define OFF_MSK   8208
#define OFF_CI    532496
#define IARENA_SZ 2200000

__device__ float g_farena[FARENA_SZ];
__device__ int   g_iarena[IARENA_SZ];

// ---------------- CSR construction (bitmask two-pass) ----------------
__global__ void k_count(const float* __restrict__ adj, unsigned* __restrict__ msk,
                        int* __restrict__ cnt) {
    int row = blockIdx.x, tid = threadIdx.x;
    int lane = tid & 31, wid = tid >> 5;
    const float4* p = reinterpret_cast<const float4*>(adj + (long)row * NN);
    unsigned* mrow = msk + (long)row * 128;
    int c = 0;
    for (int seg = wid; seg < 32; seg += 8) {
        float4 v = p[seg * 32 + lane];
        unsigned b0 = __ballot_sync(0xFFFFFFFFu, v.x > 0.f);
        unsigned b1 = __ballot_sync(0xFFFFFFFFu, v.y > 0.f);
        unsigned b2 = __ballot_sync(0xFFFFFFFFu, v.z > 0.f);
        unsigned b3 = __ballot_sync(0xFFFFFFFFu, v.w > 0.f);
        c += (v.x > 0.f) + (v.y > 0.f) + (v.z > 0.f) + (v.w > 0.f);
        if (lane == 0) {
            mrow[seg * 4 + 0] = b0; mrow[seg * 4 + 1] = b1;
            mrow[seg * 4 + 2] = b2; mrow[seg * 4 + 3] = b3;
        }
    }
    for (int o = 16; o; o >>= 1) c += __shfl_xor_sync(0xFFFFFFFFu, c, o);
    __shared__ int ws[8];
    if (lane == 0) ws[wid] = c;
    __syncthreads();
    if (tid == 0)
        cnt[row] = ws[0] + ws[1] + ws[2] + ws[3] + ws[4] + ws[5] + ws[6] + ws[7];
}

__global__ void k_scan(const int* __restrict__ cnt, int* __restrict__ rp) {
    __shared__ int s[1024];
    int t = threadIdx.x;
    int v[4]; int loc = 0;
#pragma unroll
    for (int k = 0; k < 4; k++) { v[k] = cnt[t * 4 + k]; loc += v[k]; }
    s[t] = loc; __syncthreads();
    for (int off = 1; off < 1024; off <<= 1) {
        int add = (t >= off) ? s[t - off] : 0;
        __syncthreads();
        s[t] += add;
        __syncthreads();
    }
    int run = (t == 0) ? 0 : s[t - 1];
#pragma unroll
    for (int k = 0; k < 4; k++) { rp[t * 4 + k] = run; run += v[k]; }
    if (t == 1023) rp[NN] = run;
}

__global__ void k_fill(const unsigned* __restrict__ msk, const int* __restrict__ rp,
                       int* __restrict__ ci) {
    int row = blockIdx.x, tid = threadIdx.x;
    int lane = tid & 31, wid = tid >> 5;
    unsigned m = msk[(long)row * 128 + tid];
    int c = __popc(m);
    int pre = c;
    for (int o = 1; o < 32; o <<= 1) {
        int v = __shfl_up_sync(0xFFFFFFFFu, pre, o);
        if (lane >= o) pre += v;
    }
    __shared__ int wt[4];
    if (lane == 31) wt[wid] = pre;
    __syncthreads();
    int woff = 0;
    for (int i = 0; i < wid; i++) woff += wt[i];
    int pos = rp[row] + woff + pre - c;
    int base = (tid >> 2) * 128 + (tid & 3);
    while (m) {
        int b = __ffs(m) - 1;
        m &= m - 1;
        ci[pos++] = base + b * 4;
    }
}

// ---------------- misc ----------------
__global__ void k_rowsum(const float* __restrict__ sm, float* __restrict__ dv) {
    int row = blockIdx.x, tid = threadIdx.x;
    const float4* p = reinterpret_cast<const float4*>(sm + (long)row * NN);
    float acc = 0.f;
    for (int i = tid; i < NN / 4; i += 256) { float4 v = p[i]; acc += v.x + v.y + v.z + v.w; }
    __shared__ float s[256];
    s[tid] = acc; __syncthreads();
    for (int st = 128; st; st >>= 1) { if (tid < st) s[tid] += s[tid + st]; __syncthreads(); }
    if (tid == 0) dv[row] = s[0];
}

__global__ void k_mergeb(const float4* __restrict__ x, const int* __restrict__ obs,
                         const float4* __restrict__ theta, uint2* __restrict__ out) {
    long i = (long)blockIdx.x * blockDim.x + threadIdx.x;
    int row = (int)(i >> 7);
    int f4 = (int)(i & 127);
    float4 v = x[i];
    if (obs[row] == 1) { float4 t = theta[f4]; v.x += t.x; v.y += t.y; v.z += t.z; v.w += t.w; }
    __nv_bfloat162 p0 = __float22bfloat162_rn(make_float2(v.x, v.y));
    __nv_bfloat162 p1 = __float22bfloat162_rn(make_float2(v.z, v.w));
    uint2 w;
    w.x = *reinterpret_cast<unsigned int*>(&p0);
    w.y = *reinterpret_cast<unsigned int*>(&p1);
    out[i] = w;
}

// three fp32->bf16 conversions in one launch
__global__ void k_cvt3(const float4* __restrict__ i0, uint2* __restrict__ o0, int n0,
                       const float4* __restrict__ i1, uint2* __restrict__ o1, int n1,
                       const float4* __restrict__ i2, uint2* __restrict__ o2, int n2) {
    int i = blockIdx.x * blockDim.x + threadIdx.x;
    const float4* in; uint2* out; int idx;
    if (i < n0) { in = i0; out = o0; idx = i; }
    else if (i < n0 + n1) { in = i1; out = o1; idx = i - n0; }
    else if (i < n0 + n1 + n2) { in = i2; out = o2; idx = i - n0 - n1; }
    else return;
    float4 v = in[idx];
    __nv_bfloat162 p0 = __float22bfloat162_rn(make_float2(v.x, v.y));
    __nv_bfloat162 p1 = __float22bfloat162_rn(make_float2(v.z, v.w));
    uint2 w;
    w.x = *reinterpret_cast<unsigned int*>(&p0);
    w.y = *reinterpret_cast<unsigned int*>(&p1);
    out[idx] = w;
}

// P[(2h+c)*Fin + f] = sum_d W[h,f,d] * a[h, c*256 + d]
__global__ void k_wa(const float* __restrict__ W, const float* __restrict__ a,
                     float* __restrict__ P, int Fin) {
    int h = blockIdx.y;
    int idx = blockIdx.x * 8 + (threadIdx.x >> 5);
    int lane = threadIdx.x & 31;
    if (idx >= 2 * Fin) return;
    int c = idx / Fin, f = idx % Fin;
    const float* wrow = W + ((long)h * Fin + f) * 256;
    const float* av = a + h * 512 + c * 256;
    float d = 0.f;
    for (int k = lane; k < 256; k += 32) d = fmaf(wrow[k], av[k], d);
    for (int o = 16; o; o >>= 1) d += __shfl_xor_sync(0xFFFFFFFFu, d, o);
    if (lane == 0) P[(2 * h + c) * Fin + f] = d;
}

// s1/s2 from bf16 activations -> interleaved [row][head] layout (gw = row*4+h)
__global__ void __launch_bounds__(256) k_sb(
    const __nv_bfloat16* __restrict__ act, long headStride,
    const float* __restrict__ P, int K,
    float* __restrict__ s1, float* __restrict__ s2) {
    __shared__ float Ps[4096];
    int tid = threadIdx.x;
    for (int i = tid; i < 8 * K; i += 256) Ps[i] = P[i];
    __syncthreads();
    int gw = blockIdx.x * 8 + (tid >> 5);
    int lane = tid & 31;
    int row = gw >> 2, h = gw & 3;
    const __nv_bfloat16* a = act + (long)h * headStride + (long)row * K;
    const float* p1 = Ps + (2 * h) * K;
    const float* p2 = p1 + K;
    float d1 = 0.f, d2 = 0.f;
    for (int f = lane * 2; f < K; f += 64) {
        unsigned u = *reinterpret_cast<const unsigned*>(a + f);
        float x0 = __uint_as_float(u << 16);
        float x1 = __uint_as_float(u & 0xFFFF0000u);
        d1 = fmaf(x0, p1[f], fmaf(x1, p1[f + 1], d1));
        d2 = fmaf(x0, p2[f], fmaf(x1, p2[f + 1], d2));
    }
    for (int o = 16; o; o >>= 1) {
        d1 += __shfl_xor_sync(0xFFFFFFFFu, d1, o);
        d2 += __shfl_xor_sync(0xFFFFFFFFu, d2, o);
    }
    if (lane == 0) { s1[gw] = d1; s2[gw] = d2; }
}

// fused split-K reduce + s projection (out layer 0, fout=64)
__global__ void k_red4s(const float2* __restrict__ part, float2* __restrict__ oWh,
                        const float* __restrict__ ao0,
                        float* __restrict__ s1, float* __restrict__ s2) {
    int gw = blockIdx.x * 8 + (threadIdx.x >> 5);   // row
    int lane = threadIdx.x & 31;
    long idx = (long)gw * 32 + lane;                // float2 index in [4096][64] plane
    float2 v0 = part[idx];
    float2 v1 = part[idx + 131072];
    float2 v2 = part[idx + 262144];
    float2 v3 = part[idx + 393216];
    float2 s;
    s.x = v0.x + v1.x + v2.x + v3.x;
    s.y = v0.y + v1.y + v2.y + v3.y;
    oWh[idx] = s;
    float d1 = s.x * ao0[lane * 2] + s.y * ao0[lane * 2 + 1];
    float d2 = s.x * ao0[64 + lane * 2] + s.y * ao0[64 + lane * 2 + 1];
    for (int o = 16; o; o >>= 1) {
        d1 += __shfl_xor_sync(0xFFFFFFFFu, d1, o);
        d2 += __shfl_xor_sync(0xFFFFFFFFu, d2, o);
    }
    if (lane == 0) { s1[gw] = d1; s2[gw] = d2; }
}

// per-head M = leaky(max s1 + max s2); stride-indexed: s[i*stride + h]
__global__ void k_max4(const float* __restrict__ s1, const float* __restrict__ s2,
                       float* __restrict__ Mp, int stride) {
    int h = blockIdx.x;
    __shared__ float m1s[512], m2s[512];
    int t = threadIdx.x;
    float m1 = -1e30f, m2 = -1e30f;
    for (int i = t; i < NN; i += 512) {
        m1 = fmaxf(m1, s1[i * stride + h]);
        m2 = fmaxf(m2, s2[i * stride + h]);
    }
    m1s[t] = m1; m2s[t] = m2; __syncthreads();
    for (int s = 256; s; s >>= 1) {
        if (t < s) { m1s[t] = fmaxf(m1s[t], m1s[t + s]); m2s[t] = fmaxf(m2s[t], m2s[t + s]); }
        __syncthreads();
    }
    if (t == 0) Mp[h] = lrelu(m1s[0] + m2s[0]);
}

// ---------- fused 4-head FP8 aggregation: 1 block per row, 2 warps/head ------
__global__ void __launch_bounds__(256, 4) k_agg4(
    const unsigned char* __restrict__ Whb,     // head-major fp8: h*NN*256 + j*256
    const float4* __restrict__ s1v, const float4* __restrict__ s2v,
    const float* __restrict__ Mp,
    const int* __restrict__ rp, const int* __restrict__ ci,
    __nv_bfloat16* __restrict__ outBase, long headStride, int ostride) {
    int row = blockIdx.x;
    int tid = threadIdx.x;
    int lane = tid & 31, warp = tid >> 5;
    int h = warp >> 1, par = warp & 1;

    __shared__ float4   swp[392];
    __shared__ unsigned soff[392];
    __shared__ float    sacc[8][256];
    __shared__ float    szw[8];

    int rs = rp[row], re = rp[row + 1];
    float4 s1r = s1v[row];
    float4 Mv = *reinterpret_cast<const float4*>(Mp);

    const unsigned char* Wb = Whb + (long)h * (NN * 256);
    unsigned lof = lane * 8;

    __half2 zero2 = __float2half2_rn(0.f);
    __half2 A0[4] = {zero2, zero2, zero2, zero2};
    __half2 A1[4] = {zero2, zero2, zero2, zero2};
    __half2 A2[4] = {zero2, zero2, zero2, zero2};
    __half2 A3[4] = {zero2, zero2, zero2, zero2};
    float z = 0.f;

#define CVT8(us) (*reinterpret_cast<__half2*>(&(hrtmp = __nv_cvt_fp8x2_to_halfraw2((us), __NV_E4M3))))
    __half2_raw hrtmp;
#define HF4(A, wh, v) { \
    A[0] = __hfma2(wh, CVT8((unsigned short)((v).x & 0xFFFFu)), A[0]); \
    A[1] = __hfma2(wh, CVT8((unsigned short)((v).x >> 16)),     A[1]); \
    A[2] = __hfma2(wh, CVT8((unsigned short)((v).y & 0xFFFFu)), A[2]); \
    A[3] = __hfma2(wh, CVT8((unsigned short)((v).y >> 16)),     A[3]); }

    for (int base = rs; base < re; base += 384) {
        int n = min(384, re - base);
        __syncthreads();
        for (int e = tid; e < n; e += 256) {
            int j = ci[base + e];
            soff[e] = (unsigned)j << 8;
            float4 s2r = s2v[j];
            float4 w;
            w.x = __expf(lrelu(s1r.x + s2r.x) - Mv.x);
            w.y = __expf(lrelu(s1r.y + s2r.y) - Mv.y);
            w.z = __expf(lrelu(s1r.z + s2r.z) - Mv.z);
            w.w = __expf(lrelu(s1r.w + s2r.w) - Mv.w);
            swp[e] = w;
        }
        if (tid < 8) { soff[n + tid] = 0u; swp[n + tid] = make_float4(0.f, 0.f, 0.f, 0.f); }
        __syncthreads();

        int t = 4 * par;
        if (t < n) {
            float w0 = reinterpret_cast<const float*>(&swp[t])[h];
            float w1 = reinterpret_cast<const float*>(&swp[t + 1])[h];
            float w2 = reinterpret_cast<const float*>(&swp[t + 2])[h];
            float w3 = reinterpret_cast<const float*>(&swp[t + 3])[h];
            uint2 p0 = *reinterpret_cast<const uint2*>(Wb + soff[t]     + lof);
            uint2 p1 = *reinterpret_cast<const uint2*>(Wb + soff[t + 1] + lof);
            uint2 p2 = *reinterpret_cast<const uint2*>(Wb + soff[t + 2] + lof);
            uint2 p3 = *reinterpret_cast<const uint2*>(Wb + soff[t + 3] + lof);
            while (true) {
                uint2 c0 = p0, c1 = p1, c2 = p2, c3 = p3;
                float cw0 = w0, cw1 = w1, cw2 = w2, cw3 = w3;
                t += 8;
                if (t < n) {
                    w0 = reinterpret_cast<const float*>(&swp[t])[h];
                    w1 = reinterpret_cast<const float*>(&swp[t + 1])[h];
                    w2 = reinterpret_cast<const float*>(&swp[t + 2])[h];
                    w3 = reinterpret_cast<const float*>(&swp[t + 3])[h];
                    p0 = *reinterpret_cast<const uint2*>(Wb + soff[t]     + lof);
                    p1 = *reinterpret_cast<const uint2*>(Wb + soff[t + 1] + lof);
                    p2 = *reinterpret_cast<const uint2*>(Wb + soff[t + 2] + lof);
                    p3 = *reinterpret_cast<const uint2*>(Wb + soff[t + 3] + lof);
                }
                z += cw0 + cw1 + cw2 + cw3;
                __half2 wh0 = __float2half2_rn(cw0);
                __half2 wh1 = __float2half2_rn(cw1);
                __half2 wh2 = __float2half2_rn(cw2);
                __half2 wh3 = __float2half2_rn(cw3);
                HF4(A0, wh0, c0) HF4(A1, wh1, c1) HF4(A2, wh2, c2) HF4(A3, wh3, c3)
                if (t >= n) break;
            }
        }
    }
#undef HF4
#undef CVT8
#pragma unroll
    for (int k = 0; k < 4; k++) {
        A0[k] = __hadd2(A0[k], A1[k]);
        A2[k] = __hadd2(A2[k], A3[k]);
        A0[k] = __hadd2(A0[k], A2[k]);
    }

    for (int o = 16; o; o >>= 1) z += __shfl_xor_sync(0xFFFFFFFFu, z, o);
    if (lane == 0) szw[warp] = z;

    {
        float2 f0 = __half22float2(A0[0]);
        float2 f1 = __half22float2(A0[1]);
        float2 f2 = __half22float2(A0[2]);
        float2 f3 = __half22float2(A0[3]);
        *reinterpret_cast<float4*>(&sacc[warp][lane * 8]) =
            make_float4(f0.x, f0.y, f1.x, f1.y);
        *reinterpret_cast<float4*>(&sacc[warp][lane * 8 + 4]) =
            make_float4(f2.x, f2.y, f3.x, f3.y);
    }
    __syncthreads();

    if (warp < 4) {
        int hh = warp;
        float Z = szw[2 * hh] + szw[2 * hh + 1];
        float inv = 1.0f / Z;
        float o[8];
#pragma unroll
        for (int k = 0; k < 8; k++) {
            float t = (sacc[2 * hh][lane * 8 + k] + sacc[2 * hh + 1][lane * 8 + k]) * inv;
            o[k] = t > 0.f ? t : expm1f(t);   // elu
        }
        uint4 w;
        __nv_bfloat162 p;
        p = __float22bfloat162_rn(make_float2(o[0], o[1])); w.x = *(unsigned int*)&p;
        p = __float22bfloat162_rn(make_float2(o[2], o[3])); w.y = *(unsigned int*)&p;
        p = __float22bfloat162_rn(make_float2(o[4], o[5])); w.z = *(unsigned int*)&p;
        p = __float22bfloat162_rn(make_float2(o[6], o[7])); w.w = *(unsigned int*)&p;
        *reinterpret_cast<uint4*>(outBase + (long)hh * headStride +
                                  (long)row * ostride + lane * 8) = w;
    }
}

// fp32 aggregation (FOUT=64, out layer 0, no elu)
__global__ void k_agg64(const float* __restrict__ Wh, const float* __restrict__ s1,
                        const float* __restrict__ s2, const float* __restrict__ Mp,
                        const int* __restrict__ rp, const int* __restrict__ ci,
                        float* __restrict__ out) {
    constexpr int TX = 16, TY = 16;
    int row = blockIdx.x;
    int tid = threadIdx.x;
    int tx = tid % TX, ty = tid / TX;
    __shared__ float sw[256];
    __shared__ int sj[256];
    __shared__ float4 sacc[256];
    __shared__ float sz[256];
    float s1i = s1[row];
    float M = Mp[0];
    int rs = rp[row], re = rp[row + 1];
    float4 acc = make_float4(0.f, 0.f, 0.f, 0.f);
    float z = 0.f;
    for (int base = rs; base < re; base += 256) {
        int n = min(256, re - base);
        __syncthreads();
        for (int t = tid; t < n; t += 256) {
            int j = ci[base + t];
            sj[t] = j;
            float w = __expf(lrelu(s1i + s2[j]) - M);
            sw[t] = w;
            z += w;
        }
        __syncthreads();
        for (int t = ty; t < n; t += TY) {
            float w = sw[t];
            float4 v = reinterpret_cast<const float4*>(Wh + (long)sj[t] * 64)[tx];
            acc.x += w * v.x; acc.y += w * v.y; acc.z += w * v.z; acc.w += w * v.w;
        }
    }
    sacc[tid] = acc; sz[tid] = z; __syncthreads();
    for (int s = 128; s; s >>= 1) { if (tid < s) sz[tid] += sz[tid + s]; __syncthreads(); }
    if (ty == 0) {
        float4 a = sacc[tx];
#pragma unroll
        for (int yy = 1; yy < TY; yy++) {
            float4 b = sacc[yy * TX + tx];
            a.x += b.x; a.y += b.y; a.z += b.z; a.w += b.w;
        }
        float inv = 1.0f / sz[0];
        *reinterpret_cast<float4*>(out + (long)row * 64 + tx * 4) =
            make_float4(a.x * inv, a.y * inv, a.z * inv, a.w * inv);
    }
}

// FOUT == 1 aggregation
__global__ void k_agg1(const float* __restrict__ whc, const float* __restrict__ s1,
                       const float* __restrict__ s2, const float* __restrict__ Mp,
                       const int* __restrict__ rp, const int* __restrict__ ci,
                       float* __restrict__ out) {
    int row = blockIdx.x, tid = threadIdx.x;
    __shared__ float sa[256], szz[256];
    float s1i = s1[row], M = Mp[0];
    int rs = rp[row], re = rp[row + 1];
    float acc = 0.f, z = 0.f;
    for (int e = rs + tid; e < re; e += 256) {
        int j = ci[e];
        float w = __expf(lrelu(s1i + s2[j]) - M);
        z += w;
        acc += w * whc[j];
    }
    sa[tid] = acc; szz[tid] = z; __syncthreads();
    for (int s = 128; s; s >>= 1) {
        if (tid < s) { sa[tid] += sa[tid + s]; szz[tid] += szz[tid + s]; }
        __syncthreads();
    }
    if (tid == 0) out[row] = sa[0] / szz[0];
}

__global__ void k_out1s(const float* __restrict__ h, const float* __restrict__ Wo1,
                        const float* __restrict__ ao1, float* __restrict__ whc,
                        float* __restrict__ s1, float* __restrict__ s2) {
    int gw = (blockIdx.x * blockDim.x + threadIdx.x) >> 5;
    int lane = threadIdx.x & 31;
    if (gw >= NN) return;
    float d = 0.f;
    for (int f = lane; f < 64; f += 32) d += h[(long)gw * 64 + f] * Wo1[f];
    for (int o = 16; o; o >>= 1) d += __shfl_xor_sync(0xFFFFFFFFu, d, o);
    if (lane == 0) { whc[gw] = d; s1[gw] = d * ao1[0]; s2[gw] = d * ao1[1]; }
}

// ---------------- bf16 tensor-core GEMM, double-buffered smem ----------------
__device__ __forceinline__ void ldsm4(unsigned& r0, unsigned& r1, unsigned& r2, unsigned& r3,
                                      unsigned addr) {
    asm volatile("ldmatrix.sync.aligned.m8n8.x4.shared.b16 {%0,%1,%2,%3}, [%4];"
                 : "=r"(r0), "=r"(r1), "=r"(r2), "=r"(r3) : "r"(addr));
}
__device__ __forceinline__ void ldsm4t(unsigned& r0, unsigned& r1, unsigned& r2, unsigned& r3,
                                       unsigned addr) {
    asm volatile("ldmatrix.sync.aligned.m8n8.x4.trans.shared.b16 {%0,%1,%2,%3}, [%4];"
                 : "=r"(r0), "=r"(r1), "=r"(r2), "=r"(r3) : "r"(addr));
}
__device__ __forceinline__ void mma16816(float* c, unsigned a0, unsigned a1, unsigned a2,
                                         unsigned a3, unsigned b0, unsigned b1) {
    asm volatile(
        "mma.sync.aligned.m16n8k16.row.col.f32.bf16.bf16.f32 "
        "{%0,%1,%2,%3},{%4,%5,%6,%7},{%8,%9},{%0,%1,%2,%3};"
        : "+f"(c[0]), "+f"(c[1]), "+f"(c[2]), "+f"(c[3])
        : "r"(a0), "r"(a1), "r"(a2), "r"(a3), "r"(b0), "r"(b1));
}

#define GA_ROWB 80
#define GB_ROWB 272
#define GA_BYTES (128 * GA_ROWB)
#define GB_BYTES (32 * GB_ROWB)
#define SBUF (GA_BYTES + GB_BYTES)

__global__ void __launch_bounds__(256, 2) k_bgemm(
    const __nv_bfloat16* __restrict__ A, const __nv_bfloat16* __restrict__ B,
    float* __restrict__ C, unsigned short* __restrict__ C8,
    int M, int N, int K, int lda,
    long sA, long sB, long sC, long sC8) {
    __shared__ __align__(16) unsigned char sm[2 * SBUF];
    A += (long)blockIdx.z * sA;
    B += (long)blockIdx.z * sB;
    if (C) C += (long)blockIdx.z * sC;
    if (C8) C8 += (long)blockIdx.z * sC8;

    int tid = threadIdx.x;
    int warp = tid >> 5, lane = tid & 31;
    int wm = warp & 3, wn = warp >> 2;
    int m0 = blockIdx.y * 128, n0 = blockIdx.x * 128;

    int ar = tid >> 2;
    int ac = tid & 3;
    int br = tid >> 4;
    int bc = tid & 15;
    bool bok = (n0 + bc * 8) < N;

    unsigned s_base = (unsigned)__cvta_generic_to_shared(sm);
    int sub = lane >> 3, r = lane & 7;

    float acc[2][8][4] = {};
    int KT = K / 32;
    uint4 av0, av1, bv0, bv1;
    const uint4 zero4 = make_uint4(0, 0, 0, 0);

    av0 = reinterpret_cast<const uint4*>(A + (long)(m0 + ar) * lda)[ac];
    av1 = reinterpret_cast<const uint4*>(A + (long)(m0 + ar + 64) * lda)[ac];
    bv0 = bok ? *reinterpret_cast<const uint4*>(B + (long)br * N + n0 + bc * 8) : zero4;
    bv1 = bok ? *reinterpret_cast<const uint4*>(B + (long)(br + 16) * N + n0 + bc * 8) : zero4;
    {
        uint4* As4 = reinterpret_cast<uint4*>(sm);
        uint4* Bs4 = reinterpret_cast<uint4*>(sm + GA_BYTES);
        As4[ar * 5 + ac] = av0;
        As4[(ar + 64) * 5 + ac] = av1;
        Bs4[br * 17 + bc] = bv0;
        Bs4[(br + 16) * 17 + bc] = bv1;
    }

    int p = 0;
    for (int it = 0; it < KT; it++) {
        __syncthreads();
        bool more = (it + 1 < KT);
        if (more) {
            int kof = (it + 1) * 32;
            av0 = reinterpret_cast<const uint4*>(A + (long)(m0 + ar) * lda + kof)[ac];
            av1 = reinterpret_cast<const uint4*>(A + (long)(m0 + ar + 64) * lda + kof)[ac];
            bv0 = bok ? *reinterpret_cast<const uint4*>(B + (long)(kof + br) * N + n0 + bc * 8) : zero4;
            bv1 = bok ? *reinterpret_cast<const uint4*>(B + (long)(kof + br + 16) * N + n0 + bc * 8) : zero4;
        }

        unsigned sA_base = s_base + p * SBUF;
        unsigned sB_base = sA_base + GA_BYTES;
#pragma unroll
        for (int ks = 0; ks < 2; ks++) {
            unsigned a[2][4];
#pragma unroll
            for (int i = 0; i < 2; i++) {
                unsigned addr = sA_base
                    + (unsigned)((wm * 32 + i * 16 + (sub & 1) * 8 + r) * GA_ROWB
                                 + ks * 32 + (sub >> 1) * 16);
                ldsm4(a[i][0], a[i][1], a[i][2], a[i][3], addr);
            }
            unsigned b[4][4];
#pragma unroll
            for (int j = 0; j < 4; j++) {
                unsigned addr = sB_base
                    + (unsigned)((ks * 16 + (sub & 1) * 8 + r) * GB_ROWB
                                 + (wn * 64 + j * 16 + (sub >> 1) * 8) * 2);
                ldsm4t(b[j][0], b[j][1], b[j][2], b[j][3], addr);
            }
#pragma unroll
            for (int i = 0; i < 2; i++) {
#pragma unroll
                for (int j = 0; j < 4; j++) {
                    mma16816(acc[i][2 * j],     a[i][0], a[i][1], a[i][2], a[i][3],
                             b[j][0], b[j][1]);
                    mma16816(acc[i][2 * j + 1], a[i][0], a[i][1], a[i][2], a[i][3],
                             b[j][2], b[j][3]);
                }
            }
        }
        if (more) {
            uint4* As4 = reinterpret_cast<uint4*>(sm + (p ^ 1) * SBUF);
            uint4* Bs4 = reinterpret_cast<uint4*>(sm + (p ^ 1) * SBUF + GA_BYTES);
            As4[ar * 5 + ac] = av0;
            As4[(ar + 64) * 5 + ac] = av1;
            Bs4[br * 17 + bc] = bv0;
            Bs4[(br + 16) * 17 + bc] = bv1;
        }
        p ^= 1;
    }

    int g = lane >> 2, ti = lane & 3;
#pragma unroll
    for (int i = 0; i < 2; i++) {
#pragma unroll
        for (int jj = 0; jj < 8; jj++) {
            int row = m0 + wm * 32 + i * 16 + g;
            int col = n0 + wn * 64 + jj * 8 + ti * 2;
            if (col < N) {
                float* c = acc[i][jj];
                if (C) {
                    *reinterpret_cast<float2*>(C + (long)row * N + col) = make_float2(c[0], c[1]);
                    *reinterpret_cast<float2*>(C + (long)(row + 8) * N + col) = make_float2(c[2], c[3]);
                }
                if (C8) {
                    C8[((long)row * N + col) >> 1] =
                        __nv_cvt_float2_to_fp8x2(make_float2(c[0], c[1]), __NV_SATFINITE, __NV_E4M3);
                    C8[((long)(row + 8) * N + col) >> 1] =
                        __nv_cvt_float2_to_fp8x2(make_float2(c[2], c[3]), __NV_SATFINITE, __NV_E4M3);
                }
            }
        }
    }
}

// ---------------- final degree MLP ----------------
__global__ void k_mlp(const float* __restrict__ hout, const float* __restrict__ dv,
                      const float* __restrict__ dW, const float* __restrict__ dW0,
                      const float* __restrict__ dW1, const float* __restrict__ dW01,
                      const float* __restrict__ dW2, const float* __restrict__ dW02,
                      const float* __restrict__ dV, const float* __restrict__ dV0,
                      float* __restrict__ out) {
    int i = blockIdx.x * blockDim.x + threadIdx.x;
    if (i >= NN) return;
    float hv = hout[i];
    float x0 = hv > 0.f ? hv : expm1f(hv);
    float x1 = dv[i];
    float h0[10];
#pragma unroll
    for (int k = 0; k < 10; k++)
        h0[k] = lrelu(x0 * dW[k] + x1 * dW[10 + k] + dW0[k]);
    float h1[20];
#pragma unroll
    for (int k = 0; k < 20; k++) {
        float t = dW01[k];
#pragma unroll
        for (int j = 0; j < 10; j++) t += h0[j] * dW1[j * 20 + k];
        h1[k] = lrelu(t);
    }
    float h2[10];
#pragma unroll
    for (int k = 0; k < 10; k++) {
        float t = dW02[k];
#pragma unroll
        for (int j = 0; j < 20; j++) t += h1[j] * dW2[j * 10 + k];
        h2[k] = lrelu(t);
    }
    float o = dV0[0];
#pragma unroll
    for (int j = 0; j < 10; j++) o += h2[j] * dV[j];
    out[i] = lrelu(o);
}

// ---------------- launch ----------------
extern "C" void kernel_launch(void* const* d_in, const int* in_sizes, int n_in,
                              void* d_out, int out_size) {
    const float* x     = (const float*)d_in[0];
    const float* adj   = (const float*)d_in[1];
    const int*   obs   = (const int*)d_in[2];
    const float* s_mat = (const float*)d_in[3];
    const float* theta = (const float*)d_in[4];
    const float* Wh0   = (const float*)d_in[5];
    const float* ah0   = (const float*)d_in[6];
    const float* Wh1   = (const float*)d_in[7];
    const float* ah1   = (const float*)d_in[8];
    const float* Wo0   = (const float*)d_in[9];
    const float* ao0   = (const float*)d_in[10];
    const float* Wo1   = (const float*)d_in[11];
    const float* ao1   = (const float*)d_in[12];
    const float* dW    = (const float*)d_in[13];
    const float* dW0   = (const float*)d_in[14];
    const float* dW1   = (const float*)d_in[15];
    const float* dW01  = (const float*)d_in[16];
    const float* dW2   = (const float*)d_in[17];
    const float* dW02  = (const float*)d_in[18];
    const float* dV    = (const float*)d_in[19];
    const float* dV0   = (const float*)d_in[20];
    float* out = (float*)d_out;

    float* fa = nullptr;
    int*   ia = nullptr;
    cudaGetSymbolAddress((void**)&fa, g_farena);
    cudaGetSymbolAddress((void**)&ia, g_iarena);

    float* P0   = fa + OFF_P0;
    float* P1   = fa + OFF_P1;
    float* oWh  = fa + OFF_OWH;
    float* ho0  = fa + OFF_HO0;
    float* whc  = fa + OFF_WHC;
    float* hout = fa + OFF_HOUT;
    float* s1v  = fa + OFF_S1V;
    float* s2v  = fa + OFF_S2V;
    float* Mp   = fa + OFF_M;
    float* dv   = fa + OFF_DV;
    float* s1o  = fa + OFF_S1O;
    float* s2o  = fa + OFF_S2O;
    float* part = fa + OFF_PART;
    unsigned char* Whb8  = (unsigned char*)(fa + OFF_WHB);
    __nv_bfloat16* hinb  = (__nv_bfloat16*)(fa + OFF_HINB);
    __nv_bfloat16* h1bb  = (__nv_bfloat16*)(fa + OFF_H1B);
    __nv_bfloat16* hcatb = (__nv_bfloat16*)(fa + OFF_HCATB);
    __nv_bfloat16* W0b   = (__nv_bfloat16*)(fa + OFF_W0B);
    __nv_bfloat16* W1b   = (__nv_bfloat16*)(fa + OFF_W1B);
    __nv_bfloat16* Wo0b  = (__nv_bfloat16*)(fa + OFF_WO0B);
    int* cnt = ia + OFF_CNT;
    int* rp  = ia + OFF_RP;
    unsigned* msk = (unsigned*)(ia + OFF_MSK);
    int* ci  = ia + OFF_CI;

    const long NM = (long)NN * 256;

    // prep (launches 1-3)
    k_mergeb<<<2048, 256>>>((const float4*)x, obs, (const float4*)theta, (uint2*)hinb);
    k_cvt3<<<(131072 + 65536 + 16384 + 255) / 256, 256>>>(
        (const float4*)Wh0, (uint2*)W0b, 131072,
        (const float4*)Wh1, (uint2*)W1b, 65536,
        (const float4*)Wo0, (uint2*)Wo0b, 16384);
    k_count<<<NN, 256>>>(adj, msk, cnt);

    // launch 4: head-layer-0 GEMM  ← ncu capture slot
    k_bgemm<<<dim3(2, 32, 4), 256>>>(hinb, W0b, nullptr, (unsigned short*)Whb8,
                                     NN, 256, 512, 512, 0L, 512L * 256, 0L, (long)NN * 128);

    // CSR finish + remaining prep
    k_scan<<<1, 1024>>>(cnt, rp);
    k_fill<<<NN, 128>>>(msk, rp, ci);
    k_wa<<<dim3(128, 4), 256>>>(Wh0, ah0, P0, 512);
    k_wa<<<dim3(64, 4), 256>>>(Wh1, ah1, P1, 256);
    k_rowsum<<<NN, 256>>>(s_mat, dv);
    k_sb<<<2048, 256>>>(hinb, 0L, P0, 512, s1v, s2v);
    k_max4<<<4, 512>>>(s1v, s2v, Mp, 4);

    // ---- head layer 0 aggregation ----
    k_agg4<<<NN, 256>>>(Whb8, (const float4*)s1v, (const float4*)s2v, Mp,
                        rp, ci, h1bb, NM, 256);

    // ---- head layer 1 ----
    k_bgemm<<<dim3(2, 32, 4), 256>>>(h1bb, W1b, nullptr, (unsigned short*)Whb8,
                                     NN, 256, 256, 256, NM, 256L * 256, 0L, (long)NN * 128);
    k_sb<<<2048, 256>>>(h1bb, NM, P1, 256, s1v, s2v);
    k_max4<<<4, 512>>>(s1v, s2v, Mp, 4);
    k_agg4<<<NN, 256>>>(Whb8, (const float4*)s1v, (const float4*)s2v, Mp,
                        rp, ci, hcatb, 256L, 1024);

    // ---- output layer 0: split-K=4 GEMM + fused reduce/projection ----
    k_bgemm<<<dim3(1, 32, 4), 256>>>(hcatb, Wo0b, part, nullptr,
                                     NN, 64, 256, 1024, 256L, 256L * 64, 262144L, 0L);
    k_red4s<<<512, 256>>>((const float2*)part, (float2*)oWh, ao0, s1o, s2o);
    k_max4<<<1, 512>>>(s1o, s2o, Mp, 1);
    k_agg64<<<NN, 256>>>(oWh, s1o, s2o, Mp, rp, ci, ho0);

    // ---- output layer 1 ----
    k_out1s<<<512, 256>>>(ho0, Wo1, ao1, whc, s1o, s2o);
    k_max4<<<1, 512>>>(s1o, s2o, Mp, 1);
    k_agg1<<<NN, 256>>>(whc, s1o, s2o, Mp, rp, ci, hout);

    // ---- elu + degree MLP ----
    k_mlp<<<16, 256>>>(hout, dv, dW, dW0, dW1, dW01, dW2, dW02, dV, dV0, out);
}

// round 11
// speedup vs baseline: 1.4469x; 1.0119x over previous
#include <cuda_runtime.h>
#include <cuda_bf16.h>
#include <cuda_fp8.h>
#include <math.h>

#define NN 4096
#define ALPHA 0.2f

__device__ __forceinline__ float lrelu(float v){ return v >= 0.f ? v : ALPHA * v; }

// ---------------- scratch arenas (device globals; no allocation) -------------
#define OFF_P0    0L
#define OFF_P1    4096L
#define OFF_OWH   8192L       // bf16 4096*64 -> 131072 floats used
#define OFF_HO0   270336L
#define OFF_WHC   532480L
#define OFF_HOUT  536576L
#define OFF_S1V   540672L     // [NN][4] interleaved
#define OFF_S2V   557056L
#define OFF_M     573440L
#define OFF_DV    573456L
#define OFF_S1O   577552L
#define OFF_S2O   581648L
#define OFF_WHB   585744L     // fp8 4*4096*256 bytes
#define OFF_HINB  1634320L    // bf16 4096*512
#define OFF_H1B   2682896L    // bf16 4*4096*256
#define OFF_HCATB 4780048L    // bf16 4096*1024
#define OFF_W0B   6877200L
#define OFF_W1B   7139344L
#define OFF_WO0B  7270416L
#define OFF_PART  7303184L    // split-K partials 4*4096*64
#define FARENA_SZ 8400000L

#define OFF_CNT   0
#define OFF_RP    4096
#define OFF_MSK   8208
#define OFF_CI    532496
#define IARENA_SZ 2200000

__device__ float g_farena[FARENA_SZ];
__device__ int   g_iarena[IARENA_SZ];

// ---------------- fused count (adj bitmask) + rowsum (s_mat degree) ----------
__global__ void k_cnt_rs(const float* __restrict__ adj, unsigned* __restrict__ msk,
                         int* __restrict__ cnt,
                         const float* __restrict__ smat, float* __restrict__ dv) {
    int row = blockIdx.x, tid = threadIdx.x;
    int lane = tid & 31, wid = tid >> 5;
    const float4* p = reinterpret_cast<const float4*>(adj + (long)row * NN);
    unsigned* mrow = msk + (long)row * 128;
    int c = 0;
    for (int seg = wid; seg < 32; seg += 8) {
        float4 v = p[seg * 32 + lane];
        unsigned b0 = __ballot_sync(0xFFFFFFFFu, v.x > 0.f);
        unsigned b1 = __ballot_sync(0xFFFFFFFFu, v.y > 0.f);
        unsigned b2 = __ballot_sync(0xFFFFFFFFu, v.z > 0.f);
        unsigned b3 = __ballot_sync(0xFFFFFFFFu, v.w > 0.f);
        c += (v.x > 0.f) + (v.y > 0.f) + (v.z > 0.f) + (v.w > 0.f);
        if (lane == 0) {
            mrow[seg * 4 + 0] = b0; mrow[seg * 4 + 1] = b1;
            mrow[seg * 4 + 2] = b2; mrow[seg * 4 + 3] = b3;
        }
    }
    const float4* q = reinterpret_cast<const float4*>(smat + (long)row * NN);
    float a = 0.f;
    for (int i = tid; i < NN / 4; i += 256) { float4 v = q[i]; a += v.x + v.y + v.z + v.w; }
    for (int o = 16; o; o >>= 1) {
        c += __shfl_xor_sync(0xFFFFFFFFu, c, o);
        a += __shfl_xor_sync(0xFFFFFFFFu, a, o);
    }
    __shared__ int ws[8];
    __shared__ float fs[8];
    if (lane == 0) { ws[wid] = c; fs[wid] = a; }
    __syncthreads();
    if (tid == 0)
        cnt[row] = ws[0] + ws[1] + ws[2] + ws[3] + ws[4] + ws[5] + ws[6] + ws[7];
    if (tid == 32)
        dv[row] = fs[0] + fs[1] + fs[2] + fs[3] + fs[4] + fs[5] + fs[6] + fs[7];
}

__global__ void k_scan(const int* __restrict__ cnt, int* __restrict__ rp) {
    __shared__ int s[1024];
    int t = threadIdx.x;
    int v[4]; int loc = 0;
#pragma unroll
    for (int k = 0; k < 4; k++) { v[k] = cnt[t * 4 + k]; loc += v[k]; }
    s[t] = loc; __syncthreads();
    for (int off = 1; off < 1024; off <<= 1) {
        int add = (t >= off) ? s[t - off] : 0;
        __syncthreads();
        s[t] += add;
        __syncthreads();
    }
    int run = (t == 0) ? 0 : s[t - 1];
#pragma unroll
    for (int k = 0; k < 4; k++) { rp[t * 4 + k] = run; run += v[k]; }
    if (t == 1023) rp[NN] = run;
}

__global__ void k_fill(const unsigned* __restrict__ msk, const int* __restrict__ rp,
                       int* __restrict__ ci) {
    int row = blockIdx.x, tid = threadIdx.x;
    int lane = tid & 31, wid = tid >> 5;
    unsigned m = msk[(long)row * 128 + tid];
    int c = __popc(m);
    int pre = c;
    for (int o = 1; o < 32; o <<= 1) {
        int v = __shfl_up_sync(0xFFFFFFFFu, pre, o);
        if (lane >= o) pre += v;
    }
    __shared__ int wt[4];
    if (lane == 31) wt[wid] = pre;
    __syncthreads();
    int woff = 0;
    for (int i = 0; i < wid; i++) woff += wt[i];
    int pos = rp[row] + woff + pre - c;
    int base = (tid >> 2) * 128 + (tid & 3);
    while (m) {
        int b = __ffs(m) - 1;
        m &= m - 1;
        ci[pos++] = base + b * 4;
    }
}

// ---------------- fused prep: merge(x+seed*theta)->bf16 + 3 weight cvts ------
__device__ __forceinline__ uint2 pack_bf16x4(float4 v) {
    __nv_bfloat162 p0 = __float22bfloat162_rn(make_float2(v.x, v.y));
    __nv_bfloat162 p1 = __float22bfloat162_rn(make_float2(v.z, v.w));
    uint2 w;
    w.x = *reinterpret_cast<unsigned int*>(&p0);
    w.y = *reinterpret_cast<unsigned int*>(&p1);
    return w;
}

__global__ void k_prep(const float4* __restrict__ x, const int* __restrict__ obs,
                       const float4* __restrict__ theta, uint2* __restrict__ hinb,
                       const float4* __restrict__ w0, uint2* __restrict__ o0,
                       const float4* __restrict__ w1, uint2* __restrict__ o1,
                       const float4* __restrict__ w2, uint2* __restrict__ o2) {
    long i = (long)blockIdx.x * 256 + threadIdx.x;
    if (i < 524288L) {
        int row = (int)(i >> 7);
        int f4 = (int)(i & 127);
        float4 v = x[i];
        if (obs[row] == 1) {
            float4 t = theta[f4];
            v.x += t.x; v.y += t.y; v.z += t.z; v.w += t.w;
        }
        hinb[i] = pack_bf16x4(v);
        return;
    }
    i -= 524288L;
    if (i < 131072) { o0[i] = pack_bf16x4(w0[i]); return; }
    i -= 131072;
    if (i < 65536) { o1[i] = pack_bf16x4(w1[i]); return; }
    i -= 65536;
    if (i < 16384) { o2[i] = pack_bf16x4(w2[i]); }
}

// ---------------- fused W@a for both layers ----------------
__global__ void k_wa2(const float* __restrict__ W0, const float* __restrict__ a0,
                      float* __restrict__ P0,
                      const float* __restrict__ W1, const float* __restrict__ a1,
                      float* __restrict__ P1) {
    int h = blockIdx.y;
    int bx = blockIdx.x;
    const float* W; const float* a; float* P; int Fin;
    if (bx < 128) { W = W0; a = a0; P = P0; Fin = 512; }
    else { W = W1; a = a1; P = P1; Fin = 256; bx -= 128; }
    int idx = bx * 8 + (threadIdx.x >> 5);
    int lane = threadIdx.x & 31;
    if (idx >= 2 * Fin) return;
    int c = idx / Fin, f = idx % Fin;
    const float* wrow = W + ((long)h * Fin + f) * 256;
    const float* av = a + h * 512 + c * 256;
    float d = 0.f;
    for (int k = lane; k < 256; k += 32) d = fmaf(wrow[k], av[k], d);
    for (int o = 16; o; o >>= 1) d += __shfl_xor_sync(0xFFFFFFFFu, d, o);
    if (lane == 0) P[(2 * h + c) * Fin + f] = d;
}

// s1/s2 from bf16 activations -> interleaved [row][head] layout (gw = row*4+h)
__global__ void __launch_bounds__(256) k_sb(
    const __nv_bfloat16* __restrict__ act, long headStride,
    const float* __restrict__ P, int K,
    float* __restrict__ s1, float* __restrict__ s2) {
    __shared__ float Ps[4096];
    int tid = threadIdx.x;
    for (int i = tid; i < 8 * K; i += 256) Ps[i] = P[i];
    __syncthreads();
    int gw = blockIdx.x * 8 + (tid >> 5);
    int lane = tid & 31;
    int row = gw >> 2, h = gw & 3;
    const __nv_bfloat16* a = act + (long)h * headStride + (long)row * K;
    const float* p1 = Ps + (2 * h) * K;
    const float* p2 = p1 + K;
    float d1 = 0.f, d2 = 0.f;
    for (int f = lane * 2; f < K; f += 64) {
        unsigned u = *reinterpret_cast<const unsigned*>(a + f);
        float x0 = __uint_as_float(u << 16);
        float x1 = __uint_as_float(u & 0xFFFF0000u);
        d1 = fmaf(x0, p1[f], fmaf(x1, p1[f + 1], d1));
        d2 = fmaf(x0, p2[f], fmaf(x1, p2[f + 1], d2));
    }
    for (int o = 16; o; o >>= 1) {
        d1 += __shfl_xor_sync(0xFFFFFFFFu, d1, o);
        d2 += __shfl_xor_sync(0xFFFFFFFFu, d2, o);
    }
    if (lane == 0) { s1[gw] = d1; s2[gw] = d2; }
}

// fused split-K reduce + bf16 oWh + s projection (out layer 0, fout=64)
__global__ void k_red4s(const float2* __restrict__ part,
                        __nv_bfloat162* __restrict__ oWhb,
                        const float* __restrict__ ao0,
                        float* __restrict__ s1, float* __restrict__ s2) {
    int gw = blockIdx.x * 8 + (threadIdx.x >> 5);
    int lane = threadIdx.x & 31;
    long idx = (long)gw * 32 + lane;
    float2 v0 = part[idx];
    float2 v1 = part[idx + 131072];
    float2 v2 = part[idx + 262144];
    float2 v3 = part[idx + 393216];
    float2 s;
    s.x = v0.x + v1.x + v2.x + v3.x;
    s.y = v0.y + v1.y + v2.y + v3.y;
    oWhb[idx] = __float22bfloat162_rn(s);
    float d1 = s.x * ao0[lane * 2] + s.y * ao0[lane * 2 + 1];
    float d2 = s.x * ao0[64 + lane * 2] + s.y * ao0[64 + lane * 2 + 1];
    for (int o = 16; o; o >>= 1) {
        d1 += __shfl_xor_sync(0xFFFFFFFFu, d1, o);
        d2 += __shfl_xor_sync(0xFFFFFFFFu, d2, o);
    }
    if (lane == 0) { s1[gw] = d1; s2[gw] = d2; }
}

// per-head M = leaky(max s1 + max s2); stride-indexed: s[i*stride + h]
__global__ void k_max4(const float* __restrict__ s1, const float* __restrict__ s2,
                       float* __restrict__ Mp, int stride) {
    int h = blockIdx.x;
    __shared__ float m1s[512], m2s[512];
    int t = threadIdx.x;
    float m1 = -1e30f, m2 = -1e30f;
    for (int i = t; i < NN; i += 512) {
        m1 = fmaxf(m1, s1[i * stride + h]);
        m2 = fmaxf(m2, s2[i * stride + h]);
    }
    m1s[t] = m1; m2s[t] = m2; __syncthreads();
    for (int s = 256; s; s >>= 1) {
        if (t < s) { m1s[t] = fmaxf(m1s[t], m1s[t + s]); m2s[t] = fmaxf(m2s[t], m2s[t + s]); }
        __syncthreads();
    }
    if (t == 0) Mp[h] = lrelu(m1s[0] + m2s[0]);
}

// ---------- fused 4-head FP8 aggregation: 1 block per row, 2 warps/head ------
__global__ void __launch_bounds__(256, 4) k_agg4(
    const unsigned char* __restrict__ Whb,
    const float4* __restrict__ s1v, const float4* __restrict__ s2v,
    const float* __restrict__ Mp,
    const int* __restrict__ rp, const int* __restrict__ ci,
    __nv_bfloat16* __restrict__ outBase, long headStride, int ostride) {
    int row = blockIdx.x;
    int tid = threadIdx.x;
    int lane = tid & 31, warp = tid >> 5;
    int h = warp >> 1, par = warp & 1;

    __shared__ float4   swp[392];
    __shared__ unsigned soff[392];
    __shared__ float    sacc[8][256];
    __shared__ float    szw[8];

    int rs = rp[row], re = rp[row + 1];
    float4 s1r = s1v[row];
    float4 Mv = *reinterpret_cast<const float4*>(Mp);

    const unsigned char* Wb = Whb + (long)h * (NN * 256);
    unsigned lof = lane * 8;

    __half2 zero2 = __float2half2_rn(0.f);
    __half2 A0[4] = {zero2, zero2, zero2, zero2};
    __half2 A1[4] = {zero2, zero2, zero2, zero2};
    __half2 A2[4] = {zero2, zero2, zero2, zero2};
    __half2 A3[4] = {zero2, zero2, zero2, zero2};
    float z = 0.f;

#define CVT8(us) (*reinterpret_cast<__half2*>(&(hrtmp = __nv_cvt_fp8x2_to_halfraw2((us), __NV_E4M3))))
    __half2_raw hrtmp;
#define HF4(A, wh, v) { \
    A[0] = __hfma2(wh, CVT8((unsigned short)((v).x & 0xFFFFu)), A[0]); \
    A[1] = __hfma2(wh, CVT8((unsigned short)((v).x >> 16)),     A[1]); \
    A[2] = __hfma2(wh, CVT8((unsigned short)((v).y & 0xFFFFu)), A[2]); \
    A[3] = __hfma2(wh, CVT8((unsigned short)((v).y >> 16)),     A[3]); }

    for (int base = rs; base < re; base += 384) {
        int n = min(384, re - base);
        __syncthreads();
        for (int e = tid; e < n; e += 256) {
            int j = ci[base + e];
            soff[e] = (unsigned)j << 8;
            float4 s2r = s2v[j];
            float4 w;
            w.x = __expf(lrelu(s1r.x + s2r.x) - Mv.x);
            w.y = __expf(lrelu(s1r.y + s2r.y) - Mv.y);
            w.z = __expf(lrelu(s1r.z + s2r.z) - Mv.z);
            w.w = __expf(lrelu(s1r.w + s2r.w) - Mv.w);
            swp[e] = w;
        }
        if (tid < 8) { soff[n + tid] = 0u; swp[n + tid] = make_float4(0.f, 0.f, 0.f, 0.f); }
        __syncthreads();

        int t = 4 * par;
        if (t < n) {
            float w0 = reinterpret_cast<const float*>(&swp[t])[h];
            float w1 = reinterpret_cast<const float*>(&swp[t + 1])[h];
            float w2 = reinterpret_cast<const float*>(&swp[t + 2])[h];
            float w3 = reinterpret_cast<const float*>(&swp[t + 3])[h];
            uint2 p0 = *reinterpret_cast<const uint2*>(Wb + soff[t]     + lof);
            uint2 p1 = *reinterpret_cast<const uint2*>(Wb + soff[t + 1] + lof);
            uint2 p2 = *reinterpret_cast<const uint2*>(Wb + soff[t + 2] + lof);
            uint2 p3 = *reinterpret_cast<const uint2*>(Wb + soff[t + 3] + lof);
            while (true) {
                uint2 c0 = p0, c1 = p1, c2 = p2, c3 = p3;
                float cw0 = w0, cw1 = w1, cw2 = w2, cw3 = w3;
                t += 8;
                if (t < n) {
                    w0 = reinterpret_cast<const float*>(&swp[t])[h];
                    w1 = reinterpret_cast<const float*>(&swp[t + 1])[h];
                    w2 = reinterpret_cast<const float*>(&swp[t + 2])[h];
                    w3 = reinterpret_cast<const float*>(&swp[t + 3])[h];
                    p0 = *reinterpret_cast<const uint2*>(Wb + soff[t]     + lof);
                    p1 = *reinterpret_cast<const uint2*>(Wb + soff[t + 1] + lof);
                    p2 = *reinterpret_cast<const uint2*>(Wb + soff[t + 2] + lof);
                    p3 = *reinterpret_cast<const uint2*>(Wb + soff[t + 3] + lof);
                }
                z += cw0 + cw1 + cw2 + cw3;
                __half2 wh0 = __float2half2_rn(cw0);
                __half2 wh1 = __float2half2_rn(cw1);
                __half2 wh2 = __float2half2_rn(cw2);
                __half2 wh3 = __float2half2_rn(cw3);
                HF4(A0, wh0, c0) HF4(A1, wh1, c1) HF4(A2, wh2, c2) HF4(A3, wh3, c3)
                if (t >= n) break;
            }
        }
    }
#undef HF4
#undef CVT8
#pragma unroll
    for (int k = 0; k < 4; k++) {
        A0[k] = __hadd2(A0[k], A1[k]);
        A2[k] = __hadd2(A2[k], A3[k]);
        A0[k] = __hadd2(A0[k], A2[k]);
    }

    for (int o = 16; o; o >>= 1) z += __shfl_xor_sync(0xFFFFFFFFu, z, o);
    if (lane == 0) szw[warp] = z;

    {
        float2 f0 = __half22float2(A0[0]);
        float2 f1 = __half22float2(A0[1]);
        float2 f2 = __half22float2(A0[2]);
        float2 f3 = __half22float2(A0[3]);
        *reinterpret_cast<float4*>(&sacc[warp][lane * 8]) =
            make_float4(f0.x, f0.y, f1.x, f1.y);
        *reinterpret_cast<float4*>(&sacc[warp][lane * 8 + 4]) =
            make_float4(f2.x, f2.y, f3.x, f3.y);
    }
    __syncthreads();

    if (warp < 4) {
        int hh = warp;
        float Z = szw[2 * hh] + szw[2 * hh + 1];
        float inv = 1.0f / Z;
        float o[8];
#pragma unroll
        for (int k = 0; k < 8; k++) {
            float t = (sacc[2 * hh][lane * 8 + k] + sacc[2 * hh + 1][lane * 8 + k]) * inv;
            o[k] = t > 0.f ? t : expm1f(t);   // elu
        }
        uint4 w;
        __nv_bfloat162 p;
        p = __float22bfloat162_rn(make_float2(o[0], o[1])); w.x = *(unsigned int*)&p;
        p = __float22bfloat162_rn(make_float2(o[2], o[3])); w.y = *(unsigned int*)&p;
        p = __float22bfloat162_rn(make_float2(o[4], o[5])); w.z = *(unsigned int*)&p;
        p = __float22bfloat162_rn(make_float2(o[6], o[7])); w.w = *(unsigned int*)&p;
        *reinterpret_cast<uint4*>(outBase + (long)hh * headStride +
                                  (long)row * ostride + lane * 8) = w;
    }
}

// bf16 aggregation (FOUT=64, out layer 0, no elu, fp32 accumulate)
__global__ void k_agg64b(const __nv_bfloat16* __restrict__ Wh,
                         const float* __restrict__ s1, const float* __restrict__ s2,
                         const float* __restrict__ Mp,
                         const int* __restrict__ rp, const int* __restrict__ ci,
                         float* __restrict__ out) {
    int row = blockIdx.x, tid = threadIdx.x;
    int tx = tid & 7, ty = tid >> 3;   // 8 feat-groups x 32 neighbor lanes
    __shared__ float sw[258];
    __shared__ unsigned soff[258];
    __shared__ float sacc[2048];       // [32][64]
    __shared__ float szr[256];
    float s1i = s1[row], M = Mp[0];
    int rs = rp[row], re = rp[row + 1];
    float acc[8] = {0.f,0.f,0.f,0.f,0.f,0.f,0.f,0.f};
    float z = 0.f;
    unsigned lof = tx * 16;
    for (int base = rs; base < re; base += 256) {
        int n = min(256, re - base);
        __syncthreads();
        if (tid < n) {
            int j = ci[base + tid];
            soff[tid] = (unsigned)j << 7;   // 128 B per bf16 row
            float w = __expf(lrelu(s1i + s2[j]) - M);
            sw[tid] = w;
            z += w;
        }
        __syncthreads();
        for (int t = ty; t < n; t += 32) {
            float w = sw[t];
            uint4 v = *reinterpret_cast<const uint4*>(
                reinterpret_cast<const char*>(Wh) + soff[t] + lof);
#define UNP(u, k0) \
            acc[k0]   = fmaf(w, __uint_as_float((u) << 16),         acc[k0]); \
            acc[k0+1] = fmaf(w, __uint_as_float((u) & 0xFFFF0000u), acc[k0+1]);
            UNP(v.x, 0) UNP(v.y, 2) UNP(v.z, 4) UNP(v.w, 6)
#undef UNP
        }
    }
    szr[tid] = z; __syncthreads();
    for (int s = 128; s; s >>= 1) { if (tid < s) szr[tid] += szr[tid + s]; __syncthreads(); }
    float Z = szr[0];
    *reinterpret_cast<float4*>(&sacc[ty * 64 + tx * 8]) =
        make_float4(acc[0], acc[1], acc[2], acc[3]);
    *reinterpret_cast<float4*>(&sacc[ty * 64 + tx * 8 + 4]) =
        make_float4(acc[4], acc[5], acc[6], acc[7]);
    __syncthreads();
#pragma unroll
    for (int s = 16; s; s >>= 1) {
        if (ty < s) {
            float4* d0 = reinterpret_cast<float4*>(&sacc[ty * 64 + tx * 8]);
            float4* o0 = reinterpret_cast<float4*>(&sacc[(ty + s) * 64 + tx * 8]);
            float4 a = d0[0], b = o0[0];
            a.x += b.x; a.y += b.y; a.z += b.z; a.w += b.w; d0[0] = a;
            float4 c = d0[1], e = o0[1];
            c.x += e.x; c.y += e.y; c.z += e.z; c.w += e.w; d0[1] = c;
        }
        __syncthreads();
    }
    if (ty == 0) {
        float inv = 1.0f / Z;
        float4 a = *reinterpret_cast<const float4*>(&sacc[tx * 8]);
        float4 b = *reinterpret_cast<const float4*>(&sacc[tx * 8 + 4]);
        *reinterpret_cast<float4*>(out + (long)row * 64 + tx * 8) =
            make_float4(a.x * inv, a.y * inv, a.z * inv, a.w * inv);
        *reinterpret_cast<float4*>(out + (long)row * 64 + tx * 8 + 4) =
            make_float4(b.x * inv, b.y * inv, b.z * inv, b.w * inv);
    }
}

// FOUT == 1 aggregation
__global__ void k_agg1(const float* __restrict__ whc, const float* __restrict__ s1,
                       const float* __restrict__ s2, const float* __restrict__ Mp,
                       const int* __restrict__ rp, const int* __restrict__ ci,
                       float* __restrict__ out) {
    int row = blockIdx.x, tid = threadIdx.x;
    __shared__ float sa[256], szz[256];
    float s1i = s1[row], M = Mp[0];
    int rs = rp[row], re = rp[row + 1];
    float acc = 0.f, z = 0.f;
    for (int e = rs + tid; e < re; e += 256) {
        int j = ci[e];
        float w = __expf(lrelu(s1i + s2[j]) - M);
        z += w;
        acc += w * whc[j];
    }
    sa[tid] = acc; szz[tid] = z; __syncthreads();
    for (int s = 128; s; s >>= 1) {
        if (tid < s) { sa[tid] += sa[tid + s]; szz[tid] += szz[tid + s]; }
        __syncthreads();
    }
    if (tid == 0) out[row] = sa[0] / szz[0];
}

__global__ void k_out1s(const float* __restrict__ h, const float* __restrict__ Wo1,
                        const float* __restrict__ ao1, float* __restrict__ whc,
                        float* __restrict__ s1, float* __restrict__ s2) {
    int gw = (blockIdx.x * blockDim.x + threadIdx.x) >> 5;
    int lane = threadIdx.x & 31;
    if (gw >= NN) return;
    float d = 0.f;
    for (int f = lane; f < 64; f += 32) d += h[(long)gw * 64 + f] * Wo1[f];
    for (int o = 16; o; o >>= 1) d += __shfl_xor_sync(0xFFFFFFFFu, d, o);
    if (lane == 0) { whc[gw] = d; s1[gw] = d * ao1[0]; s2[gw] = d * ao1[1]; }
}

// ---------------- bf16 tensor-core GEMM, cp.async double-buffered ------------
__device__ __forceinline__ void ldsm4(unsigned& r0, unsigned& r1, unsigned& r2, unsigned& r3,
                                      unsigned addr) {
    asm volatile("ldmatrix.sync.aligned.m8n8.x4.shared.b16 {%0,%1,%2,%3}, [%4];"
                 : "=r"(r0), "=r"(r1), "=r"(r2), "=r"(r3) : "r"(addr));
}
__device__ __forceinline__ void ldsm4t(unsigned& r0, unsigned& r1, unsigned& r2, unsigned& r3,
                                       unsigned addr) {
    asm volatile("ldmatrix.sync.aligned.m8n8.x4.trans.shared.b16 {%0,%1,%2,%3}, [%4];"
                 : "=r"(r0), "=r"(r1), "=r"(r2), "=r"(r3) : "r"(addr));
}
__device__ __forceinline__ void mma16816(float* c, unsigned a0, unsigned a1, unsigned a2,
                                         unsigned a3, unsigned b0, unsigned b1) {
    asm volatile(
        "mma.sync.aligned.m16n8k16.row.col.f32.bf16.bf16.f32 "
        "{%0,%1,%2,%3},{%4,%5,%6,%7},{%8,%9},{%0,%1,%2,%3};"
        : "+f"(c[0]), "+f"(c[1]), "+f"(c[2]), "+f"(c[3])
        : "r"(a0), "r"(a1), "r"(a2), "r"(a3), "r"(b0), "r"(b1));
}
__device__ __forceinline__ void cpa16(unsigned d, const void* s, int sz) {
    asm volatile("cp.async.cg.shared.global [%0], [%1], 16, %2;"
                 :: "r"(d), "l"(s), "r"(sz));
}

#define GA_ROWB 80
#define GB_ROWB 272
#define GA_BYTES (128 * GA_ROWB)
#define GB_BYTES (32 * GB_ROWB)
#define SBUF (GA_BYTES + GB_BYTES)

__global__ void __launch_bounds__(256, 2) k_bgemm(
    const __nv_bfloat16* __restrict__ A, const __nv_bfloat16* __restrict__ B,
    float* __restrict__ C, unsigned short* __restrict__ C8,
    int M, int N, int K, int lda,
    long sA, long sB, long sC, long sC8) {
    __shared__ __align__(16) unsigned char sm[2 * SBUF];
    A += (long)blockIdx.z * sA;
    B += (long)blockIdx.z * sB;
    if (C) C += (long)blockIdx.z * sC;
    if (C8) C8 += (long)blockIdx.z * sC8;

    int tid = threadIdx.x;
    int warp = tid >> 5, lane = tid & 31;
    int wm = warp & 3, wn = warp >> 2;
    int m0 = blockIdx.y * 128, n0 = blockIdx.x * 128;

    int ar = tid >> 2;
    int ac = tid & 3;
    int br = tid >> 4;
    int bc = tid & 15;
    int bsz = ((n0 + bc * 8) < N) ? 16 : 0;

    unsigned s_base = (unsigned)__cvta_generic_to_shared(sm);
    int sub = lane >> 3, r = lane & 7;

    float acc[2][8][4] = {};
    int KT = K / 32;

    // async load of k-tile `it` into buffer `buf`
    auto issue = [&](int it, int buf) {
        int kof = it * 32;
        unsigned sa = s_base + buf * SBUF;
        unsigned sb = sa + GA_BYTES;
        cpa16(sa + (unsigned)(ar * 5 + ac) * 16,
              A + (long)(m0 + ar) * lda + kof + ac * 8, 16);
        cpa16(sa + (unsigned)((ar + 64) * 5 + ac) * 16,
              A + (long)(m0 + ar + 64) * lda + kof + ac * 8, 16);
        cpa16(sb + (unsigned)(br * 17 + bc) * 16,
              B + (long)(kof + br) * N + n0 + bc * 8, bsz);
        cpa16(sb + (unsigned)((br + 16) * 17 + bc) * 16,
              B + (long)(kof + br + 16) * N + n0 + bc * 8, bsz);
        asm volatile("cp.async.commit_group;");
    };

    issue(0, 0);
    int p = 0;
    for (int it = 0; it < KT; it++) {
        asm volatile("cp.async.wait_group 0;" ::: "memory");
        __syncthreads();
        if (it + 1 < KT) issue(it + 1, p ^ 1);

        unsigned sA_base = s_base + p * SBUF;
        unsigned sB_base = sA_base + GA_BYTES;
#pragma unroll
        for (int ks = 0; ks < 2; ks++) {
            unsigned a[2][4];
#pragma unroll
            for (int i = 0; i < 2; i++) {
                unsigned addr = sA_base
                    + (unsigned)((wm * 32 + i * 16 + (sub & 1) * 8 + r) * GA_ROWB
                                 + ks * 32 + (sub >> 1) * 16);
                ldsm4(a[i][0], a[i][1], a[i][2], a[i][3], addr);
            }
            unsigned b[4][4];
#pragma unroll
            for (int j = 0; j < 4; j++) {
                unsigned addr = sB_base
                    + (unsigned)((ks * 16 + (sub & 1) * 8 + r) * GB_ROWB
                                 + (wn * 64 + j * 16 + (sub >> 1) * 8) * 2);
                ldsm4t(b[j][0], b[j][1], b[j][2], b[j][3], addr);
            }
#pragma unroll
            for (int i = 0; i < 2; i++) {
#pragma unroll
                for (int j = 0; j < 4; j++) {
                    mma16816(acc[i][2 * j],     a[i][0], a[i][1], a[i][2], a[i][3],
                             b[j][0], b[j][1]);
                    mma16816(acc[i][2 * j + 1], a[i][0], a[i][1], a[i][2], a[i][3],
                             b[j][2], b[j][3]);
                }
            }
        }
        p ^= 1;
    }

    int g = lane >> 2, ti = lane & 3;
#pragma unroll
    for (int i = 0; i < 2; i++) {
#pragma unroll
        for (int jj = 0; jj < 8; jj++) {
            int row = m0 + wm * 32 + i * 16 + g;
            int col = n0 + wn * 64 + jj * 8 + ti * 2;
            if (col < N) {
                float* c = acc[i][jj];
                if (C) {
                    *reinterpret_cast<float2*>(C + (long)row * N + col) = make_float2(c[0], c[1]);
                    *reinterpret_cast<float2*>(C + (long)(row + 8) * N + col) = make_float2(c[2], c[3]);
                }
                if (C8) {
                    C8[((long)row * N + col) >> 1] =
                        __nv_cvt_float2_to_fp8x2(make_float2(c[0], c[1]), __NV_SATFINITE, __NV_E4M3);
                    C8[((long)(row + 8) * N + col) >> 1] =
                        __nv_cvt_float2_to_fp8x2(make_float2(c[2], c[3]), __NV_SATFINITE, __NV_E4M3);
                }
            }
        }
    }
}

// ---------------- final degree MLP ----------------
__global__ void k_mlp(const float* __restrict__ hout, const float* __restrict__ dv,
                      const float* __restrict__ dW, const float* __restrict__ dW0,
                      const float* __restrict__ dW1, const float* __restrict__ dW01,
                      const float* __restrict__ dW2, const float* __restrict__ dW02,
                      const float* __restrict__ dV, const float* __restrict__ dV0,
                      float* __restrict__ out) {
    int i = blockIdx.x * blockDim.x + threadIdx.x;
    if (i >= NN) return;
    float hv = hout[i];
    float x0 = hv > 0.f ? hv : expm1f(hv);
    float x1 = dv[i];
    float h0[10];
#pragma unroll
    for (int k = 0; k < 10; k++)
        h0[k] = lrelu(x0 * dW[k] + x1 * dW[10 + k] + dW0[k]);
    float h1[20];
#pragma unroll
    for (int k = 0; k < 20; k++) {
        float t = dW01[k];
#pragma unroll
        for (int j = 0; j < 10; j++) t += h0[j] * dW1[j * 20 + k];
        h1[k] = lrelu(t);
    }
    float h2[10];
#pragma unroll
    for (int k = 0; k < 10; k++) {
        float t = dW02[k];
#pragma unroll
        for (int j = 0; j < 20; j++) t += h1[j] * dW2[j * 10 + k];
        h2[k] = lrelu(t);
    }
    float o = dV0[0];
#pragma unroll
    for (int j = 0; j < 10; j++) o += h2[j] * dV[j];
    out[i] = lrelu(o);
}

// ---------------- launch ----------------
extern "C" void kernel_launch(void* const* d_in, const int* in_sizes, int n_in,
                              void* d_out, int out_size) {
    const float* x     = (const float*)d_in[0];
    const float* adj   = (const float*)d_in[1];
    const int*   obs   = (const int*)d_in[2];
    const float* s_mat = (const float*)d_in[3];
    const float* theta = (const float*)d_in[4];
    const float* Wh0   = (const float*)d_in[5];
    const float* ah0   = (const float*)d_in[6];
    const float* Wh1   = (const float*)d_in[7];
    const float* ah1   = (const float*)d_in[8];
    const float* Wo0   = (const float*)d_in[9];
    const float* ao0   = (const float*)d_in[10];
    const float* Wo1   = (const float*)d_in[11];
    const float* ao1   = (const float*)d_in[12];
    const float* dW    = (const float*)d_in[13];
    const float* dW0   = (const float*)d_in[14];
    const float* dW1   = (const float*)d_in[15];
    const float* dW01  = (const float*)d_in[16];
    const float* dW2   = (const float*)d_in[17];
    const float* dW02  = (const float*)d_in[18];
    const float* dV    = (const float*)d_in[19];
    const float* dV0   = (const float*)d_in[20];
    float* out = (float*)d_out;

    float* fa = nullptr;
    int*   ia = nullptr;
    cudaGetSymbolAddress((void**)&fa, g_farena);
    cudaGetSymbolAddress((void**)&ia, g_iarena);

    float* P0   = fa + OFF_P0;
    float* P1   = fa + OFF_P1;
    __nv_bfloat16* oWhb = (__nv_bfloat16*)(fa + OFF_OWH);
    float* ho0  = fa + OFF_HO0;
    float* whc  = fa + OFF_WHC;
    float* hout = fa + OFF_HOUT;
    float* s1v  = fa + OFF_S1V;
    float* s2v  = fa + OFF_S2V;
    float* Mp   = fa + OFF_M;
    float* dv   = fa + OFF_DV;
    float* s1o  = fa + OFF_S1O;
    float* s2o  = fa + OFF_S2O;
    float* part = fa + OFF_PART;
    unsigned char* Whb8  = (unsigned char*)(fa + OFF_WHB);
    __nv_bfloat16* hinb  = (__nv_bfloat16*)(fa + OFF_HINB);
    __nv_bfloat16* h1bb  = (__nv_bfloat16*)(fa + OFF_H1B);
    __nv_bfloat16* hcatb = (__nv_bfloat16*)(fa + OFF_HCATB);
    __nv_bfloat16* W0b   = (__nv_bfloat16*)(fa + OFF_W0B);
    __nv_bfloat16* W1b   = (__nv_bfloat16*)(fa + OFF_W1B);
    __nv_bfloat16* Wo0b  = (__nv_bfloat16*)(fa + OFF_WO0B);
    int* cnt = ia + OFF_CNT;
    int* rp  = ia + OFF_RP;
    unsigned* msk = (unsigned*)(ia + OFF_MSK);
    int* ci  = ia + OFF_CI;

    const long NM = (long)NN * 256;

    // launches 1-3: fused prep, fused count+rowsum, fused W@a
    k_prep<<<2880, 256>>>((const float4*)x, obs, (const float4*)theta, (uint2*)hinb,
                          (const float4*)Wh0, (uint2*)W0b,
                          (const float4*)Wh1, (uint2*)W1b,
                          (const float4*)Wo0, (uint2*)Wo0b);
    k_cnt_rs<<<NN, 256>>>(adj, msk, cnt, s_mat, dv);
    k_wa2<<<dim3(192, 4), 256>>>(Wh0, ah0, P0, Wh1, ah1, P1);

    // launch 4: head-layer-0 GEMM  ← ncu capture slot (cp.async version)
    k_bgemm<<<dim3(2, 32, 4), 256>>>(hinb, W0b, nullptr, (unsigned short*)Whb8,
                                     NN, 256, 512, 512, 0L, 512L * 256, 0L, (long)NN * 128);

    // CSR finish + s-path
    k_scan<<<1, 1024>>>(cnt, rp);
    k_fill<<<NN, 128>>>(msk, rp, ci);
    k_sb<<<2048, 256>>>(hinb, 0L, P0, 512, s1v, s2v);
    k_max4<<<4, 512>>>(s1v, s2v, Mp, 4);

    // ---- head layer 0 aggregation ----
    k_agg4<<<NN, 256>>>(Whb8, (const float4*)s1v, (const float4*)s2v, Mp,
                        rp, ci, h1bb, NM, 256);

    // ---- head layer 1 ----
    k_bgemm<<<dim3(2, 32, 4), 256>>>(h1bb, W1b, nullptr, (unsigned short*)Whb8,
                                     NN, 256, 256, 256, NM, 256L * 256, 0L, (long)NN * 128);
    k_sb<<<2048, 256>>>(h1bb, NM, P1, 256, s1v, s2v);
    k_max4<<<4, 512>>>(s1v, s2v, Mp, 4);
    k_agg4<<<NN, 256>>>(Whb8, (const float4*)s1v, (const float4*)s2v, Mp,
                        rp, ci, hcatb, 256L, 1024);

    // ---- output layer 0: split-K=4 GEMM + fused reduce/bf16/projection ----
    k_bgemm<<<dim3(1, 32, 4), 256>>>(hcatb, Wo0b, part, nullptr,
                                     NN, 64, 256, 1024, 256L, 256L * 64, 262144L, 0L);
    k_red4s<<<512, 256>>>((const float2*)part, (__nv_bfloat162*)oWhb, ao0, s1o, s2o);
    k_max4<<<1, 512>>>(s1o, s2o, Mp, 1);
    k_agg64b<<<NN, 256>>>(oWhb, s1o, s2o, Mp, rp, ci, ho0);

    // ---- output layer 1 ----
    k_out1s<<<512, 256>>>(ho0, Wo1, ao1, whc, s1o, s2o);
    k_max4<<<1, 512>>>(s1o, s2o, Mp, 1);
    k_agg1<<<NN, 256>>>(whc, s1o, s2o, Mp, rp, ci, hout);

    // ---- elu + degree MLP ----
    k_mlp<<<16, 256>>>(hout, dv, dW, dW0, dW1, dW01, dW2, dW02, dV, dV0, out);
}

// round 12
// speedup vs baseline: 1.5140x; 1.0464x over previous
#include <cuda_runtime.h>
#include <cuda_bf16.h>
#include <cuda_fp8.h>
#include <math.h>

#define NN 4096
#define ALPHA 0.2f

__device__ __forceinline__ float lrelu(float v){ return v >= 0.f ? v : ALPHA * v; }

// ---------------- scratch arenas (device globals; no allocation) -------------
#define OFF_P0    0L
#define OFF_P1    4096L
#define OFF_OWH   8192L
#define OFF_HO0   270336L
#define OFF_WHC   532480L
#define OFF_HOUT  536576L
#define OFF_S1V   540672L
#define OFF_S2V   557056L
#define OFF_M     573440L
#define OFF_DV    573456L
#define OFF_S1O   577552L
#define OFF_S2O   581648L
#define OFF_WHB   585744L     // fp8 4*4096*256 bytes
#define OFF_HINB  1634320L    // bf16 4096*512
#define OFF_H1B   2682896L    // bf16 4*4096*256
#define OFF_HCATB 4780048L    // bf16 4096*1024
#define OFF_W0B   6877200L
#define OFF_W1B   7139344L
#define OFF_WO0B  7270416L
#define OFF_PART  7303184L
#define FARENA_SZ 8400000L

#define OFF_CNT   0
#define OFF_RP    4096
#define OFF_MSK   8208
#define OFF_CI    532496
#define IARENA_SZ 2200000

__device__ float g_farena[FARENA_SZ];
__device__ int   g_iarena[IARENA_SZ];

// ---------------- fused count (adj bitmask) + rowsum (s_mat degree) ----------
__global__ void k_cnt_rs(const float* __restrict__ adj, unsigned* __restrict__ msk,
                         int* __restrict__ cnt,
                         const float* __restrict__ smat, float* __restrict__ dv) {
    int row = blockIdx.x, tid = threadIdx.x;
    int lane = tid & 31, wid = tid >> 5;
    const float4* p = reinterpret_cast<const float4*>(adj + (long)row * NN);
    unsigned* mrow = msk + (long)row * 128;
    int c = 0;
    for (int seg = wid; seg < 32; seg += 8) {
        float4 v = p[seg * 32 + lane];
        unsigned b0 = __ballot_sync(0xFFFFFFFFu, v.x > 0.f);
        unsigned b1 = __ballot_sync(0xFFFFFFFFu, v.y > 0.f);
        unsigned b2 = __ballot_sync(0xFFFFFFFFu, v.z > 0.f);
        unsigned b3 = __ballot_sync(0xFFFFFFFFu, v.w > 0.f);
        c += (v.x > 0.f) + (v.y > 0.f) + (v.z > 0.f) + (v.w > 0.f);
        if (lane == 0) {
            mrow[seg * 4 + 0] = b0; mrow[seg * 4 + 1] = b1;
            mrow[seg * 4 + 2] = b2; mrow[seg * 4 + 3] = b3;
        }
    }
    const float4* q = reinterpret_cast<const float4*>(smat + (long)row * NN);
    float a = 0.f;
    for (int i = tid; i < NN / 4; i += 256) { float4 v = q[i]; a += v.x + v.y + v.z + v.w; }
    for (int o = 16; o; o >>= 1) {
        c += __shfl_xor_sync(0xFFFFFFFFu, c, o);
        a += __shfl_xor_sync(0xFFFFFFFFu, a, o);
    }
    __shared__ int ws[8];
    __shared__ float fs[8];
    if (lane == 0) { ws[wid] = c; fs[wid] = a; }
    __syncthreads();
    if (tid == 0)
        cnt[row] = ws[0] + ws[1] + ws[2] + ws[3] + ws[4] + ws[5] + ws[6] + ws[7];
    if (tid == 32)
        dv[row] = fs[0] + fs[1] + fs[2] + fs[3] + fs[4] + fs[5] + fs[6] + fs[7];
}

__global__ void k_scan(const int* __restrict__ cnt, int* __restrict__ rp) {
    __shared__ int s[1024];
    int t = threadIdx.x;
    int v[4]; int loc = 0;
#pragma unroll
    for (int k = 0; k < 4; k++) { v[k] = cnt[t * 4 + k]; loc += v[k]; }
    s[t] = loc; __syncthreads();
    for (int off = 1; off < 1024; off <<= 1) {
        int add = (t >= off) ? s[t - off] : 0;
        __syncthreads();
        s[t] += add;
        __syncthreads();
    }
    int run = (t == 0) ? 0 : s[t - 1];
#pragma unroll
    for (int k = 0; k < 4; k++) { rp[t * 4 + k] = run; run += v[k]; }
    if (t == 1023) rp[NN] = run;
}

__global__ void k_fill(const unsigned* __restrict__ msk, const int* __restrict__ rp,
                       int* __restrict__ ci) {
    int row = blockIdx.x, tid = threadIdx.x;
    int lane = tid & 31, wid = tid >> 5;
    unsigned m = msk[(long)row * 128 + tid];
    int c = __popc(m);
    int pre = c;
    for (int o = 1; o < 32; o <<= 1) {
        int v = __shfl_up_sync(0xFFFFFFFFu, pre, o);
        if (lane >= o) pre += v;
    }
    __shared__ int wt[4];
    if (lane == 31) wt[wid] = pre;
    __syncthreads();
    int woff = 0;
    for (int i = 0; i < wid; i++) woff += wt[i];
    int pos = rp[row] + woff + pre - c;
    int base = (tid >> 2) * 128 + (tid & 3);
    while (m) {
        int b = __ffs(m) - 1;
        m &= m - 1;
        ci[pos++] = base + b * 4;
    }
}

// ---------------- fused prep: merge(x+seed*theta)->bf16 + 3 weight cvts ------
__device__ __forceinline__ uint2 pack_bf16x4(float4 v) {
    __nv_bfloat162 p0 = __float22bfloat162_rn(make_float2(v.x, v.y));
    __nv_bfloat162 p1 = __float22bfloat162_rn(make_float2(v.z, v.w));
    uint2 w;
    w.x = *reinterpret_cast<unsigned int*>(&p0);
    w.y = *reinterpret_cast<unsigned int*>(&p1);
    return w;
}

__global__ void k_prep(const float4* __restrict__ x, const int* __restrict__ obs,
                       const float4* __restrict__ theta, uint2* __restrict__ hinb,
                       const float4* __restrict__ w0, uint2* __restrict__ o0,
                       const float4* __restrict__ w1, uint2* __restrict__ o1,
                       const float4* __restrict__ w2, uint2* __restrict__ o2) {
    long i = (long)blockIdx.x * 256 + threadIdx.x;
    if (i < 524288L) {
        int row = (int)(i >> 7);
        int f4 = (int)(i & 127);
        float4 v = x[i];
        if (obs[row] == 1) {
            float4 t = theta[f4];
            v.x += t.x; v.y += t.y; v.z += t.z; v.w += t.w;
        }
        hinb[i] = pack_bf16x4(v);
        return;
    }
    i -= 524288L;
    if (i < 131072) { o0[i] = pack_bf16x4(w0[i]); return; }
    i -= 131072;
    if (i < 65536) { o1[i] = pack_bf16x4(w1[i]); return; }
    i -= 65536;
    if (i < 16384) { o2[i] = pack_bf16x4(w2[i]); }
}

// ---------------- fused W@a for both layers ----------------
__global__ void k_wa2(const float* __restrict__ W0, const float* __restrict__ a0,
                      float* __restrict__ P0,
                      const float* __restrict__ W1, const float* __restrict__ a1,
                      float* __restrict__ P1) {
    int h = blockIdx.y;
    int bx = blockIdx.x;
    const float* W; const float* a; float* P; int Fin;
    if (bx < 128) { W = W0; a = a0; P = P0; Fin = 512; }
    else { W = W1; a = a1; P = P1; Fin = 256; bx -= 128; }
    int idx = bx * 8 + (threadIdx.x >> 5);
    int lane = threadIdx.x & 31;
    if (idx >= 2 * Fin) return;
    int c = idx / Fin, f = idx % Fin;
    const float* wrow = W + ((long)h * Fin + f) * 256;
    const float* av = a + h * 512 + c * 256;
    float d = 0.f;
    for (int k = lane; k < 256; k += 32) d = fmaf(wrow[k], av[k], d);
    for (int o = 16; o; o >>= 1) d += __shfl_xor_sync(0xFFFFFFFFu, d, o);
    if (lane == 0) P[(2 * h + c) * Fin + f] = d;
}

// s1/s2 from bf16 activations -> interleaved [row][head] layout (gw = row*4+h)
__global__ void __launch_bounds__(256) k_sb(
    const __nv_bfloat16* __restrict__ act, long headStride,
    const float* __restrict__ P, int K,
    float* __restrict__ s1, float* __restrict__ s2) {
    __shared__ float Ps[4096];
    int tid = threadIdx.x;
    for (int i = tid; i < 8 * K; i += 256) Ps[i] = P[i];
    __syncthreads();
    int gw = blockIdx.x * 8 + (tid >> 5);
    int lane = tid & 31;
    int row = gw >> 2, h = gw & 3;
    const __nv_bfloat16* a = act + (long)h * headStride + (long)row * K;
    const float* p1 = Ps + (2 * h) * K;
    const float* p2 = p1 + K;
    float d1 = 0.f, d2 = 0.f;
    for (int f = lane * 2; f < K; f += 64) {
        unsigned u = *reinterpret_cast<const unsigned*>(a + f);
        float x0 = __uint_as_float(u << 16);
        float x1 = __uint_as_float(u & 0xFFFF0000u);
        d1 = fmaf(x0, p1[f], fmaf(x1, p1[f + 1], d1));
        d2 = fmaf(x0, p2[f], fmaf(x1, p2[f + 1], d2));
    }
    for (int o = 16; o; o >>= 1) {
        d1 += __shfl_xor_sync(0xFFFFFFFFu, d1, o);
        d2 += __shfl_xor_sync(0xFFFFFFFFu, d2, o);
    }
    if (lane == 0) { s1[gw] = d1; s2[gw] = d2; }
}

// fused split-K reduce + bf16 oWh + s projection (out layer 0, fout=64)
__global__ void k_red4s(const float2* __restrict__ part,
                        __nv_bfloat162* __restrict__ oWhb,
                        const float* __restrict__ ao0,
                        float* __restrict__ s1, float* __restrict__ s2) {
    int gw = blockIdx.x * 8 + (threadIdx.x >> 5);
    int lane = threadIdx.x & 31;
    long idx = (long)gw * 32 + lane;
    float2 v0 = part[idx];
    float2 v1 = part[idx + 131072];
    float2 v2 = part[idx + 262144];
    float2 v3 = part[idx + 393216];
    float2 s;
    s.x = v0.x + v1.x + v2.x + v3.x;
    s.y = v0.y + v1.y + v2.y + v3.y;
    oWhb[idx] = __float22bfloat162_rn(s);
    float d1 = s.x * ao0[lane * 2] + s.y * ao0[lane * 2 + 1];
    float d2 = s.x * ao0[64 + lane * 2] + s.y * ao0[64 + lane * 2 + 1];
    for (int o = 16; o; o >>= 1) {
        d1 += __shfl_xor_sync(0xFFFFFFFFu, d1, o);
        d2 += __shfl_xor_sync(0xFFFFFFFFu, d2, o);
    }
    if (lane == 0) { s1[gw] = d1; s2[gw] = d2; }
}

// per-head M = leaky(max s1 + max s2); stride-indexed: s[i*stride + h]
__global__ void k_max4(const float* __restrict__ s1, const float* __restrict__ s2,
                       float* __restrict__ Mp, int stride) {
    int h = blockIdx.x;
    __shared__ float m1s[512], m2s[512];
    int t = threadIdx.x;
    float m1 = -1e30f, m2 = -1e30f;
    for (int i = t; i < NN; i += 512) {
        m1 = fmaxf(m1, s1[i * stride + h]);
        m2 = fmaxf(m2, s2[i * stride + h]);
    }
    m1s[t] = m1; m2s[t] = m2; __syncthreads();
    for (int s = 256; s; s >>= 1) {
        if (t < s) { m1s[t] = fmaxf(m1s[t], m1s[t + s]); m2s[t] = fmaxf(m2s[t], m2s[t + s]); }
        __syncthreads();
    }
    if (t == 0) Mp[h] = lrelu(m1s[0] + m2s[0]);
}

// ---------- fused 4-head FP8 aggregation: 1 block per row, 2 warps/head ------
__global__ void __launch_bounds__(256, 4) k_agg4(
    const unsigned char* __restrict__ Whb,
    const float4* __restrict__ s1v, const float4* __restrict__ s2v,
    const float* __restrict__ Mp,
    const int* __restrict__ rp, const int* __restrict__ ci,
    __nv_bfloat16* __restrict__ outBase, long headStride, int ostride) {
    int row = blockIdx.x;
    int tid = threadIdx.x;
    int lane = tid & 31, warp = tid >> 5;
    int h = warp >> 1, par = warp & 1;

    __shared__ float4   swp[392];
    __shared__ unsigned soff[392];
    __shared__ float    sacc[8][256];
    __shared__ float    szw[8];

    int rs = rp[row], re = rp[row + 1];
    float4 s1r = s1v[row];
    float4 Mv = *reinterpret_cast<const float4*>(Mp);

    const unsigned char* Wb = Whb + (long)h * (NN * 256);
    unsigned lof = lane * 8;

    __half2 zero2 = __float2half2_rn(0.f);
    __half2 A0[4] = {zero2, zero2, zero2, zero2};
    __half2 A1[4] = {zero2, zero2, zero2, zero2};
    __half2 A2[4] = {zero2, zero2, zero2, zero2};
    __half2 A3[4] = {zero2, zero2, zero2, zero2};
    float z = 0.f;

#define CVT8(us) (*reinterpret_cast<__half2*>(&(hrtmp = __nv_cvt_fp8x2_to_halfraw2((us), __NV_E4M3))))
    __half2_raw hrtmp;
#define HF4(A, wh, v) { \
    A[0] = __hfma2(wh, CVT8((unsigned short)((v).x & 0xFFFFu)), A[0]); \
    A[1] = __hfma2(wh, CVT8((unsigned short)((v).x >> 16)),     A[1]); \
    A[2] = __hfma2(wh, CVT8((unsigned short)((v).y & 0xFFFFu)), A[2]); \
    A[3] = __hfma2(wh, CVT8((unsigned short)((v).y >> 16)),     A[3]); }

    for (int base = rs; base < re; base += 384) {
        int n = min(384, re - base);
        __syncthreads();
        for (int e = tid; e < n; e += 256) {
            int j = ci[base + e];
            soff[e] = (unsigned)j << 8;
            float4 s2r = s2v[j];
            float4 w;
            w.x = __expf(lrelu(s1r.x + s2r.x) - Mv.x);
            w.y = __expf(lrelu(s1r.y + s2r.y) - Mv.y);
            w.z = __expf(lrelu(s1r.z + s2r.z) - Mv.z);
            w.w = __expf(lrelu(s1r.w + s2r.w) - Mv.w);
            swp[e] = w;
        }
        if (tid < 8) { soff[n + tid] = 0u; swp[n + tid] = make_float4(0.f, 0.f, 0.f, 0.f); }
        __syncthreads();

        int t = 4 * par;
        if (t < n) {
            float w0 = reinterpret_cast<const float*>(&swp[t])[h];
            float w1 = reinterpret_cast<const float*>(&swp[t + 1])[h];
            float w2 = reinterpret_cast<const float*>(&swp[t + 2])[h];
            float w3 = reinterpret_cast<const float*>(&swp[t + 3])[h];
            uint2 p0 = *reinterpret_cast<const uint2*>(Wb + soff[t]     + lof);
            uint2 p1 = *reinterpret_cast<const uint2*>(Wb + soff[t + 1] + lof);
            uint2 p2 = *reinterpret_cast<const uint2*>(Wb + soff[t + 2] + lof);
            uint2 p3 = *reinterpret_cast<const uint2*>(Wb + soff[t + 3] + lof);
            while (true) {
                uint2 c0 = p0, c1 = p1, c2 = p2, c3 = p3;
                float cw0 = w0, cw1 = w1, cw2 = w2, cw3 = w3;
                t += 8;
                if (t < n) {
                    w0 = reinterpret_cast<const float*>(&swp[t])[h];
                    w1 = reinterpret_cast<const float*>(&swp[t + 1])[h];
                    w2 = reinterpret_cast<const float*>(&swp[t + 2])[h];
                    w3 = reinterpret_cast<const float*>(&swp[t + 3])[h];
                    p0 = *reinterpret_cast<const uint2*>(Wb + soff[t]     + lof);
                    p1 = *reinterpret_cast<const uint2*>(Wb + soff[t + 1] + lof);
                    p2 = *reinterpret_cast<const uint2*>(Wb + soff[t + 2] + lof);
                    p3 = *reinterpret_cast<const uint2*>(Wb + soff[t + 3] + lof);
                }
                z += cw0 + cw1 + cw2 + cw3;
                __half2 wh0 = __float2half2_rn(cw0);
                __half2 wh1 = __float2half2_rn(cw1);
                __half2 wh2 = __float2half2_rn(cw2);
                __half2 wh3 = __float2half2_rn(cw3);
                HF4(A0, wh0, c0) HF4(A1, wh1, c1) HF4(A2, wh2, c2) HF4(A3, wh3, c3)
                if (t >= n) break;
            }
        }
    }
#undef HF4
#undef CVT8
#pragma unroll
    for (int k = 0; k < 4; k++) {
        A0[k] = __hadd2(A0[k], A1[k]);
        A2[k] = __hadd2(A2[k], A3[k]);
        A0[k] = __hadd2(A0[k], A2[k]);
    }

    for (int o = 16; o; o >>= 1) z += __shfl_xor_sync(0xFFFFFFFFu, z, o);
    if (lane == 0) szw[warp] = z;

    {
        float2 f0 = __half22float2(A0[0]);
        float2 f1 = __half22float2(A0[1]);
        float2 f2 = __half22float2(A0[2]);
        float2 f3 = __half22float2(A0[3]);
        *reinterpret_cast<float4*>(&sacc[warp][lane * 8]) =
            make_float4(f0.x, f0.y, f1.x, f1.y);
        *reinterpret_cast<float4*>(&sacc[warp][lane * 8 + 4]) =
            make_float4(f2.x, f2.y, f3.x, f3.y);
    }
    __syncthreads();

    if (warp < 4) {
        int hh = warp;
        float Z = szw[2 * hh] + szw[2 * hh + 1];
        float inv = 1.0f / Z;
        float o[8];
#pragma unroll
        for (int k = 0; k < 8; k++) {
            float t = (sacc[2 * hh][lane * 8 + k] + sacc[2 * hh + 1][lane * 8 + k]) * inv;
            o[k] = t > 0.f ? t : expm1f(t);
        }
        uint4 w;
        __nv_bfloat162 p;
        p = __float22bfloat162_rn(make_float2(o[0], o[1])); w.x = *(unsigned int*)&p;
        p = __float22bfloat162_rn(make_float2(o[2], o[3])); w.y = *(unsigned int*)&p;
        p = __float22bfloat162_rn(make_float2(o[4], o[5])); w.z = *(unsigned int*)&p;
        p = __float22bfloat162_rn(make_float2(o[6], o[7])); w.w = *(unsigned int*)&p;
        *reinterpret_cast<uint4*>(outBase + (long)hh * headStride +
                                  (long)row * ostride + lane * 8) = w;
    }
}

// bf16 aggregation (FOUT=64, out layer 0, no elu, fp32 accumulate)
__global__ void k_agg64b(const __nv_bfloat16* __restrict__ Wh,
                         const float* __restrict__ s1, const float* __restrict__ s2,
                         const float* __restrict__ Mp,
                         const int* __restrict__ rp, const int* __restrict__ ci,
                         float* __restrict__ out) {
    int row = blockIdx.x, tid = threadIdx.x;
    int tx = tid & 7, ty = tid >> 3;
    __shared__ float sw[258];
    __shared__ unsigned soff[258];
    __shared__ float sacc[2048];
    __shared__ float szr[256];
    float s1i = s1[row], M = Mp[0];
    int rs = rp[row], re = rp[row + 1];
    float acc[8] = {0.f,0.f,0.f,0.f,0.f,0.f,0.f,0.f};
    float z = 0.f;
    unsigned lof = tx * 16;
    for (int base = rs; base < re; base += 256) {
        int n = min(256, re - base);
        __syncthreads();
        if (tid < n) {
            int j = ci[base + tid];
            soff[tid] = (unsigned)j << 7;
            float w = __expf(lrelu(s1i + s2[j]) - M);
            sw[tid] = w;
            z += w;
        }
        __syncthreads();
        for (int t = ty; t < n; t += 32) {
            float w = sw[t];
            uint4 v = *reinterpret_cast<const uint4*>(
                reinterpret_cast<const char*>(Wh) + soff[t] + lof);
#define UNP(u, k0) \
            acc[k0]   = fmaf(w, __uint_as_float((u) << 16),         acc[k0]); \
            acc[k0+1] = fmaf(w, __uint_as_float((u) & 0xFFFF0000u), acc[k0+1]);
            UNP(v.x, 0) UNP(v.y, 2) UNP(v.z, 4) UNP(v.w, 6)
#undef UNP
        }
    }
    szr[tid] = z; __syncthreads();
    for (int s = 128; s; s >>= 1) { if (tid < s) szr[tid] += szr[tid + s]; __syncthreads(); }
    float Z = szr[0];
    *reinterpret_cast<float4*>(&sacc[ty * 64 + tx * 8]) =
        make_float4(acc[0], acc[1], acc[2], acc[3]);
    *reinterpret_cast<float4*>(&sacc[ty * 64 + tx * 8 + 4]) =
        make_float4(acc[4], acc[5], acc[6], acc[7]);
    __syncthreads();
#pragma unroll
    for (int s = 16; s; s >>= 1) {
        if (ty < s) {
            float4* d0 = reinterpret_cast<float4*>(&sacc[ty * 64 + tx * 8]);
            float4* o0 = reinterpret_cast<float4*>(&sacc[(ty + s) * 64 + tx * 8]);
            float4 a = d0[0], b = o0[0];
            a.x += b.x; a.y += b.y; a.z += b.z; a.w += b.w; d0[0] = a;
            float4 c = d0[1], e = o0[1];
            c.x += e.x; c.y += e.y; c.z += e.z; c.w += e.w; d0[1] = c;
        }
        __syncthreads();
    }
    if (ty == 0) {
        float inv = 1.0f / Z;
        float4 a = *reinterpret_cast<const float4*>(&sacc[tx * 8]);
        float4 b = *reinterpret_cast<const float4*>(&sacc[tx * 8 + 4]);
        *reinterpret_cast<float4*>(out + (long)row * 64 + tx * 8) =
            make_float4(a.x * inv, a.y * inv, a.z * inv, a.w * inv);
        *reinterpret_cast<float4*>(out + (long)row * 64 + tx * 8 + 4) =
            make_float4(b.x * inv, b.y * inv, b.z * inv, b.w * inv);
    }
}

// FOUT == 1 aggregation
__global__ void k_agg1(const float* __restrict__ whc, const float* __restrict__ s1,
                       const float* __restrict__ s2, const float* __restrict__ Mp,
                       const int* __restrict__ rp, const int* __restrict__ ci,
                       float* __restrict__ out) {
    int row = blockIdx.x, tid = threadIdx.x;
    __shared__ float sa[256], szz[256];
    float s1i = s1[row], M = Mp[0];
    int rs = rp[row], re = rp[row + 1];
    float acc = 0.f, z = 0.f;
    for (int e = rs + tid; e < re; e += 256) {
        int j = ci[e];
        float w = __expf(lrelu(s1i + s2[j]) - M);
        z += w;
        acc += w * whc[j];
    }
    sa[tid] = acc; szz[tid] = z; __syncthreads();
    for (int s = 128; s; s >>= 1) {
        if (tid < s) { sa[tid] += sa[tid + s]; szz[tid] += szz[tid + s]; }
        __syncthreads();
    }
    if (tid == 0) out[row] = sa[0] / szz[0];
}

__global__ void k_out1s(const float* __restrict__ h, const float* __restrict__ Wo1,
                        const float* __restrict__ ao1, float* __restrict__ whc,
                        float* __restrict__ s1, float* __restrict__ s2) {
    int gw = (blockIdx.x * blockDim.x + threadIdx.x) >> 5;
    int lane = threadIdx.x & 31;
    if (gw >= NN) return;
    float d = 0.f;
    for (int f = lane; f < 64; f += 32) d += h[(long)gw * 64 + f] * Wo1[f];
    for (int o = 16; o; o >>= 1) d += __shfl_xor_sync(0xFFFFFFFFu, d, o);
    if (lane == 0) { whc[gw] = d; s1[gw] = d * ao1[0]; s2[gw] = d * ao1[1]; }
}

// ---------------- bf16 tensor-core GEMM, register double-buffered ------------
__device__ __forceinline__ void ldsm4(unsigned& r0, unsigned& r1, unsigned& r2, unsigned& r3,
                                      unsigned addr) {
    asm volatile("ldmatrix.sync.aligned.m8n8.x4.shared.b16 {%0,%1,%2,%3}, [%4];"
                 : "=r"(r0), "=r"(r1), "=r"(r2), "=r"(r3) : "r"(addr));
}
__device__ __forceinline__ void ldsm4t(unsigned& r0, unsigned& r1, unsigned& r2, unsigned& r3,
                                       unsigned addr) {
    asm volatile("ldmatrix.sync.aligned.m8n8.x4.trans.shared.b16 {%0,%1,%2,%3}, [%4];"
                 : "=r"(r0), "=r"(r1), "=r"(r2), "=r"(r3) : "r"(addr));
}
__device__ __forceinline__ void mma16816(float* c, unsigned a0, unsigned a1, unsigned a2,
                                         unsigned a3, unsigned b0, unsigned b1) {
    asm volatile(
        "mma.sync.aligned.m16n8k16.row.col.f32.bf16.bf16.f32 "
        "{%0,%1,%2,%3},{%4,%5,%6,%7},{%8,%9},{%0,%1,%2,%3};"
        : "+f"(c[0]), "+f"(c[1]), "+f"(c[2]), "+f"(c[3])
        : "r"(a0), "r"(a1), "r"(a2), "r"(a3), "r"(b0), "r"(b1));
}

#define GA_ROWB 80
#define GB_ROWB 272
#define GA_BYTES (128 * GA_ROWB)
#define GB_BYTES (32 * GB_ROWB)
#define SBUF (GA_BYTES + GB_BYTES)

__global__ void __launch_bounds__(256, 2) k_bgemm(
    const __nv_bfloat16* __restrict__ A, const __nv_bfloat16* __restrict__ B,
    float* __restrict__ C, unsigned short* __restrict__ C8,
    int M, int N, int K, int lda,
    long sA, long sB, long sC, long sC8) {
    __shared__ __align__(16) unsigned char sm[2 * SBUF];
    A += (long)blockIdx.z * sA;
    B += (long)blockIdx.z * sB;
    if (C) C += (long)blockIdx.z * sC;
    if (C8) C8 += (long)blockIdx.z * sC8;

    int tid = threadIdx.x;
    int warp = tid >> 5, lane = tid & 31;
    int wm = warp & 3, wn = warp >> 2;
    int m0 = blockIdx.y * 128, n0 = blockIdx.x * 128;

    int ar = tid >> 2;
    int ac = tid & 3;
    int br = tid >> 4;
    int bc = tid & 15;
    bool bok = (n0 + bc * 8) < N;

    unsigned s_base = (unsigned)__cvta_generic_to_shared(sm);
    int sub = lane >> 3, r = lane & 7;

    float acc[2][8][4] = {};
    int KT = K / 32;
    uint4 av0, av1, bv0, bv1;
    const uint4 zero4 = make_uint4(0, 0, 0, 0);

    av0 = reinterpret_cast<const uint4*>(A + (long)(m0 + ar) * lda)[ac];
    av1 = reinterpret_cast<const uint4*>(A + (long)(m0 + ar + 64) * lda)[ac];
    bv0 = bok ? *reinterpret_cast<const uint4*>(B + (long)br * N + n0 + bc * 8) : zero4;
    bv1 = bok ? *reinterpret_cast<const uint4*>(B + (long)(br + 16) * N + n0 + bc * 8) : zero4;
    {
        uint4* As4 = reinterpret_cast<uint4*>(sm);
        uint4* Bs4 = reinterpret_cast<uint4*>(sm + GA_BYTES);
        As4[ar * 5 + ac] = av0;
        As4[(ar + 64) * 5 + ac] = av1;
        Bs4[br * 17 + bc] = bv0;
        Bs4[(br + 16) * 17 + bc] = bv1;
    }

    int p = 0;
    for (int it = 0; it < KT; it++) {
        __syncthreads();
        bool more = (it + 1 < KT);
        if (more) {
            int kof = (it + 1) * 32;
            av0 = reinterpret_cast<const uint4*>(A + (long)(m0 + ar) * lda + kof)[ac];
            av1 = reinterpret_cast<const uint4*>(A + (long)(m0 + ar + 64) * lda + kof)[ac];
            bv0 = bok ? *reinterpret_cast<const uint4*>(B + (long)(kof + br) * N + n0 + bc * 8) : zero4;
            bv1 = bok ? *reinterpret_cast<const uint4*>(B + (long)(kof + br + 16) * N + n0 + bc * 8) : zero4;
        }

        unsigned sA_base = s_base + p * SBUF;
        unsigned sB_base = sA_base + GA_BYTES;
#pragma unroll
        for (int ks = 0; ks < 2; ks++) {
            unsigned a[2][4];
#pragma unroll
            for (int i = 0; i < 2; i++) {
                unsigned addr = sA_base
                    + (unsigned)((wm * 32 + i * 16 + (sub & 1) * 8 + r) * GA_ROWB
                                 + ks * 32 + (sub >> 1) * 16);
                ldsm4(a[i][0], a[i][1], a[i][2], a[i][3], addr);
            }
            unsigned b[4][4];
#pragma unroll
            for (int j = 0; j < 4; j++) {
                unsigned addr = sB_base
                    + (unsigned)((ks * 16 + (sub & 1) * 8 + r) * GB_ROWB
                                 + (wn * 64 + j * 16 + (sub >> 1) * 8) * 2);
                ldsm4t(b[j][0], b[j][1], b[j][2], b[j][3], addr);
            }
#pragma unroll
            for (int i = 0; i < 2; i++) {
#pragma unroll
                for (int j = 0; j < 4; j++) {
                    mma16816(acc[i][2 * j],     a[i][0], a[i][1], a[i][2], a[i][3],
                             b[j][0], b[j][1]);
                    mma16816(acc[i][2 * j + 1], a[i][0], a[i][1], a[i][2], a[i][3],
                             b[j][2], b[j][3]);
                }
            }
        }
        if (more) {
            uint4* As4 = reinterpret_cast<uint4*>(sm + (p ^ 1) * SBUF);
            uint4* Bs4 = reinterpret_cast<uint4*>(sm + (p ^ 1) * SBUF + GA_BYTES);
            As4[ar * 5 + ac] = av0;
            As4[(ar + 64) * 5 + ac] = av1;
            Bs4[br * 17 + bc] = bv0;
            Bs4[(br + 16) * 17 + bc] = bv1;
        }
        p ^= 1;
    }

    int g = lane >> 2, ti = lane & 3;
#pragma unroll
    for (int i = 0; i < 2; i++) {
#pragma unroll
        for (int jj = 0; jj < 8; jj++) {
            int row = m0 + wm * 32 + i * 16 + g;
            int col = n0 + wn * 64 + jj * 8 + ti * 2;
            if (col < N) {
                float* c = acc[i][jj];
                if (C) {
                    *reinterpret_cast<float2*>(C + (long)row * N + col) = make_float2(c[0], c[1]);
                    *reinterpret_cast<float2*>(C + (long)(row + 8) * N + col) = make_float2(c[2], c[3]);
                }
                if (C8) {
                    C8[((long)row * N + col) >> 1] =
                        __nv_cvt_float2_to_fp8x2(make_float2(c[0], c[1]), __NV_SATFINITE, __NV_E4M3);
                    C8[((long)(row + 8) * N + col) >> 1] =
                        __nv_cvt_float2_to_fp8x2(make_float2(c[2], c[3]), __NV_SATFINITE, __NV_E4M3);
                }
            }
        }
    }
}

// ---------------- final degree MLP ----------------
__global__ void k_mlp(const float* __restrict__ hout, const float* __restrict__ dv,
                      const float* __restrict__ dW, const float* __restrict__ dW0,
                      const float* __restrict__ dW1, const float* __restrict__ dW01,
                      const float* __restrict__ dW2, const float* __restrict__ dW02,
                      const float* __restrict__ dV, const float* __restrict__ dV0,
                      float* __restrict__ out) {
    int i = blockIdx.x * blockDim.x + threadIdx.x;
    if (i >= NN) return;
    float hv = hout[i];
    float x0 = hv > 0.f ? hv : expm1f(hv);
    float x1 = dv[i];
    float h0[10];
#pragma unroll
    for (int k = 0; k < 10; k++)
        h0[k] = lrelu(x0 * dW[k] + x1 * dW[10 + k] + dW0[k]);
    float h1[20];
#pragma unroll
    for (int k = 0; k < 20; k++) {
        float t = dW01[k];
#pragma unroll
        for (int j = 0; j < 10; j++) t += h0[j] * dW1[j * 20 + k];
        h1[k] = lrelu(t);
    }
    float h2[10];
#pragma unroll
    for (int k = 0; k < 10; k++) {
        float t = dW02[k];
#pragma unroll
        for (int j = 0; j < 20; j++) t += h1[j] * dW2[j * 10 + k];
        h2[k] = lrelu(t);
    }
    float o = dV0[0];
#pragma unroll
    for (int j = 0; j < 10; j++) o += h2[j] * dV[j];
    out[i] = lrelu(o);
}

// ---------------- launch ----------------
extern "C" void kernel_launch(void* const* d_in, const int* in_sizes, int n_in,
                              void* d_out, int out_size) {
    const float* x     = (const float*)d_in[0];
    const float* adj   = (const float*)d_in[1];
    const int*   obs   = (const int*)d_in[2];
    const float* s_mat = (const float*)d_in[3];
    const float* theta = (const float*)d_in[4];
    const float* Wh0   = (const float*)d_in[5];
    const float* ah0   = (const float*)d_in[6];
    const float* Wh1   = (const float*)d_in[7];
    const float* ah1   = (const float*)d_in[8];
    const float* Wo0   = (const float*)d_in[9];
    const float* ao0   = (const float*)d_in[10];
    const float* Wo1   = (const float*)d_in[11];
    const float* ao1   = (const float*)d_in[12];
    const float* dW    = (const float*)d_in[13];
    const float* dW0   = (const float*)d_in[14];
    const float* dW1   = (const float*)d_in[15];
    const float* dW01  = (const float*)d_in[16];
    const float* dW2   = (const float*)d_in[17];
    const float* dW02  = (const float*)d_in[18];
    const float* dV    = (const float*)d_in[19];
    const float* dV0   = (const float*)d_in[20];
    float* out = (float*)d_out;

    float* fa = nullptr;
    int*   ia = nullptr;
    cudaGetSymbolAddress((void**)&fa, g_farena);
    cudaGetSymbolAddress((void**)&ia, g_iarena);

    float* P0   = fa + OFF_P0;
    float* P1   = fa + OFF_P1;
    __nv_bfloat16* oWhb = (__nv_bfloat16*)(fa + OFF_OWH);
    float* ho0  = fa + OFF_HO0;
    float* whc  = fa + OFF_WHC;
    float* hout = fa + OFF_HOUT;
    float* s1v  = fa + OFF_S1V;
    float* s2v  = fa + OFF_S2V;
    float* Mp   = fa + OFF_M;
    float* dv   = fa + OFF_DV;
    float* s1o  = fa + OFF_S1O;
    float* s2o  = fa + OFF_S2O;
    float* part = fa + OFF_PART;
    unsigned char* Whb8  = (unsigned char*)(fa + OFF_WHB);
    __nv_bfloat16* hinb  = (__nv_bfloat16*)(fa + OFF_HINB);
    __nv_bfloat16* h1bb  = (__nv_bfloat16*)(fa + OFF_H1B);
    __nv_bfloat16* hcatb = (__nv_bfloat16*)(fa + OFF_HCATB);
    __nv_bfloat16* W0b   = (__nv_bfloat16*)(fa + OFF_W0B);
    __nv_bfloat16* W1b   = (__nv_bfloat16*)(fa + OFF_W1B);
    __nv_bfloat16* Wo0b  = (__nv_bfloat16*)(fa + OFF_WO0B);
    int* cnt = ia + OFF_CNT;
    int* rp  = ia + OFF_RP;
    unsigned* msk = (unsigned*)(ia + OFF_MSK);
    int* ci  = ia + OFF_CI;

    const long NM = (long)NN * 256;

    // one-time stream/event creation (correctness run happens before capture)
    static cudaStream_t sAux = nullptr;
    static cudaEvent_t evFork = nullptr, evJoin = nullptr;
    if (sAux == nullptr) {
        cudaStreamCreateWithFlags(&sAux, cudaStreamNonBlocking);
        cudaEventCreateWithFlags(&evFork, cudaEventDisableTiming);
        cudaEventCreateWithFlags(&evJoin, cudaEventDisableTiming);
    }

    // fork: CSR chain + degree on side stream (independent of GEMM path)
    cudaEventRecord(evFork, 0);
    cudaStreamWaitEvent(sAux, evFork, 0);
    k_cnt_rs<<<NN, 256, 0, sAux>>>(adj, msk, cnt, s_mat, dv);
    k_scan<<<1, 1024, 0, sAux>>>(cnt, rp);
    k_fill<<<NN, 128, 0, sAux>>>(msk, rp, ci);
    cudaEventRecord(evJoin, sAux);

    // main stream: prep -> GEMM L0 -> s-path
    k_prep<<<2880, 256>>>((const float4*)x, obs, (const float4*)theta, (uint2*)hinb,
                          (const float4*)Wh0, (uint2*)W0b,
                          (const float4*)Wh1, (uint2*)W1b,
                          (const float4*)Wo0, (uint2*)Wo0b);
    k_wa2<<<dim3(192, 4), 256>>>(Wh0, ah0, P0, Wh1, ah1, P1);
    k_bgemm<<<dim3(2, 32, 4), 256>>>(hinb, W0b, nullptr, (unsigned short*)Whb8,
                                     NN, 256, 512, 512, 0L, 512L * 256, 0L, (long)NN * 128);
    k_sb<<<2048, 256>>>(hinb, 0L, P0, 512, s1v, s2v);
    k_max4<<<4, 512>>>(s1v, s2v, Mp, 4);

    // join: aggregation needs rp/ci
    cudaStreamWaitEvent(0, evJoin, 0);

    // ---- head layer 0 aggregation ----
    k_agg4<<<NN, 256>>>(Whb8, (const float4*)s1v, (const float4*)s2v, Mp,
                        rp, ci, h1bb, NM, 256);

    // ---- head layer 1 ----
    k_bgemm<<<dim3(2, 32, 4), 256>>>(h1bb, W1b, nullptr, (unsigned short*)Whb8,
                                     NN, 256, 256, 256, NM, 256L * 256, 0L, (long)NN * 128);
    k_sb<<<2048, 256>>>(h1bb, NM, P1, 256, s1v, s2v);
    k_max4<<<4, 512>>>(s1v, s2v, Mp, 4);
    k_agg4<<<NN, 256>>>(Whb8, (const float4*)s1v, (const float4*)s2v, Mp,
                        rp, ci, hcatb, 256L, 1024);

    // ---- output layer 0: split-K=4 GEMM + fused reduce/bf16/projection ----
    k_bgemm<<<dim3(1, 32, 4), 256>>>(hcatb, Wo0b, part, nullptr,
                                     NN, 64, 256, 1024, 256L, 256L * 64, 262144L, 0L);
    k_red4s<<<512, 256>>>((const float2*)part, (__nv_bfloat162*)oWhb, ao0, s1o, s2o);
    k_max4<<<1, 512>>>(s1o, s2o, Mp, 1);
    k_agg64b<<<NN, 256>>>(oWhb, s1o, s2o, Mp, rp, ci, ho0);

    // ---- output layer 1 ----
    k_out1s<<<512, 256>>>(ho0, Wo1, ao1, whc, s1o, s2o);
    k_max4<<<1, 512>>>(s1o, s2o, Mp, 1);
    k_agg1<<<NN, 256>>>(whc, s1o, s2o, Mp, rp, ci, hout);

    // ---- elu + degree MLP ----
    k_mlp<<<16, 256>>>(hout, dv, dW, dW0, dW1, dW01, dW2, dW02, dV, dV0, out);
}